// round 6
// baseline (speedup 1.0000x reference)
#include <cuda_runtime.h>
#include <cuda_bf16.h>
#include <cstdint>

// ---------------------------------------------------------------------------
// Problem constants
// ---------------------------------------------------------------------------
#define Bsz    2
#define Lseq   1024
#define VOC    32000
#define Dm     512
#define NLAY   2
#define INNER  1024
#define MLPD   2048
#define NSEG   8
#define SEGLEN 128
#define NROWS  (Bsz*Lseq)      // 2048
#define DEC_SK 8
#define DEC_KSLICE (VOC/DEC_SK)   // 4000

// ---------------------------------------------------------------------------
// Scratch (device globals)
// ---------------------------------------------------------------------------
__device__ float g_x      [NROWS * Dm];
__device__ float g_decpart[DEC_SK * NROWS * Dm];
__device__ float g_ug     [NROWS * 2 * INNER];
__device__ float g_xs     [NROWS * Dm];
__device__ float g_state  [NLAY * Bsz * NSEG * INNER];
__device__ float g_last   [Bsz * NSEG * Dm];
__device__ int   g_starts [Bsz * NSEG];
__device__ int   g_ends   [Bsz * NSEG];
// bf16 hi/lo operand buffers
__device__ __nv_bfloat16 g_decAh[NROWS * VOC];
__device__ __nv_bfloat16 g_decAl[NROWS * VOC];
__device__ __nv_bfloat16 g_xh   [NROWS * Dm];
__device__ __nv_bfloat16 g_xl   [NROWS * Dm];
__device__ __nv_bfloat16 g_ph   [NROWS * INNER];
__device__ __nv_bfloat16 g_pl   [NROWS * INNER];
__device__ __nv_bfloat16 g_mlph [NROWS * MLPD];
__device__ __nv_bfloat16 g_mlpl [NROWS * MLPD];
__device__ __nv_bfloat16 g_Eh   [VOC * Dm];
__device__ __nv_bfloat16 g_El   [VOC * Dm];
__device__ __nv_bfloat16 g_WinH [NLAY * Dm * 2 * INNER];
__device__ __nv_bfloat16 g_WinL [NLAY * Dm * 2 * INNER];
__device__ __nv_bfloat16 g_WoutH[NLAY * INNER * Dm];
__device__ __nv_bfloat16 g_WoutL[NLAY * INNER * Dm];
__device__ __nv_bfloat16 g_Wm1H [NLAY * Dm * MLPD];
__device__ __nv_bfloat16 g_Wm1L [NLAY * Dm * MLPD];
__device__ __nv_bfloat16 g_Wm2H [NLAY * MLPD * Dm];
__device__ __nv_bfloat16 g_Wm2L [NLAY * MLPD * Dm];

__device__ __forceinline__ float silu_f(float v) { return v * (1.f / (1.f + __expf(-v))); }

__device__ __forceinline__ void split2(float a, float b, uint32_t& hp, uint32_t& lp) {
    __nv_bfloat16 ah = __float2bfloat16(a), bh = __float2bfloat16(b);
    float ar = a - __bfloat162float(ah), br = b - __bfloat162float(bh);
    __nv_bfloat16 al = __float2bfloat16(ar), bl = __float2bfloat16(br);
    hp = (uint32_t)__bfloat16_as_ushort(ah) | ((uint32_t)__bfloat16_as_ushort(bh) << 16);
    lp = (uint32_t)__bfloat16_as_ushort(al) | ((uint32_t)__bfloat16_as_ushort(bl) << 16);
}

// ---------------------------------------------------------------------------
// mma.sync / ldmatrix / cp.async primitives
// ---------------------------------------------------------------------------
__device__ __forceinline__ uint32_t smem_u32(const void* p) {
    return (uint32_t)__cvta_generic_to_shared(p);
}

__device__ __forceinline__ void ldmA(uint32_t* r, uint32_t addr) {
    asm volatile("ldmatrix.sync.aligned.m8n8.x4.shared.b16 {%0,%1,%2,%3}, [%4];"
                 : "=r"(r[0]), "=r"(r[1]), "=r"(r[2]), "=r"(r[3]) : "r"(addr));
}

__device__ __forceinline__ void ldmT(uint32_t& r0, uint32_t& r1, uint32_t& r2, uint32_t& r3,
                                     uint32_t addr) {
    asm volatile("ldmatrix.sync.aligned.m8n8.x4.trans.shared.b16 {%0,%1,%2,%3}, [%4];"
                 : "=r"(r0), "=r"(r1), "=r"(r2), "=r"(r3) : "r"(addr));
}

__device__ __forceinline__ void mma16816(float* c, const uint32_t* a, const uint32_t* b) {
    asm volatile("mma.sync.aligned.m16n8k16.row.col.f32.bf16.bf16.f32 "
                 "{%0,%1,%2,%3}, {%4,%5,%6,%7}, {%8,%9}, {%0,%1,%2,%3};"
                 : "+f"(c[0]), "+f"(c[1]), "+f"(c[2]), "+f"(c[3])
                 : "r"(a[0]), "r"(a[1]), "r"(a[2]), "r"(a[3]), "r"(b[0]), "r"(b[1]));
}

__device__ __forceinline__ void cpa16(uint32_t s, const void* g) {
    asm volatile("cp.async.cg.shared.global [%0], [%1], 16;" :: "r"(s), "l"(g));
}
__device__ __forceinline__ void cpa_commit() { asm volatile("cp.async.commit_group;"); }
__device__ __forceinline__ void cpa_wait1()  { asm volatile("cp.async.wait_group 1;"); }
__device__ __forceinline__ void cpa_wait0()  { asm volatile("cp.async.wait_group 0;"); }

// ---------------------------------------------------------------------------
// 2-stage pipelined tensor-core GEMM (unchanged from round 5)
// ---------------------------------------------------------------------------
#define A_LD 40
#define B_LD 136

template<int MTILES, int EPI>
__global__ void __launch_bounds__(256, 2)
gemm_mma(const __nv_bfloat16* __restrict__ Ah, const __nv_bfloat16* __restrict__ Al,
         const __nv_bfloat16* __restrict__ Bh, const __nv_bfloat16* __restrict__ Bl,
         float* __restrict__ Cf, __nv_bfloat16* __restrict__ Ch, __nv_bfloat16* __restrict__ Cl,
         int lda, int ldb, int ldc, int kchunk, int cslice)
{
    constexpr int BM = MTILES * 32;
    constexpr int A_E = BM * A_LD;
    constexpr int B_E = 32 * B_LD;
    constexpr int STAGE_B = (2 * A_E + 2 * B_E) * 2;
    constexpr int OFS_AL = A_E * 2;
    constexpr int OFS_BH = 2 * A_E * 2;
    constexpr int OFS_BL = 2 * A_E * 2 + B_E * 2;

    extern __shared__ __align__(16) char smem[];
    const uint32_t sb = smem_u32(smem);

    const int tid  = threadIdx.x;
    const int lane = tid & 31;
    const int wid  = tid >> 5;
    const int wm = (wid & 1) * (MTILES * 16);
    const int wn = (wid >> 1) * 32;
    const int mbase = blockIdx.y * BM;
    const int nbase = blockIdx.x * 128;
    const int kbeg  = blockIdx.z * kchunk;
    const int niter = kchunk >> 5;

    float acc[MTILES][4][4];
#pragma unroll
    for (int i = 0; i < MTILES; i++)
#pragma unroll
        for (int j = 0; j < 4; j++)
#pragma unroll
            for (int f = 0; f < 4; f++) acc[i][j][f] = 0.f;

    auto issue = [&](int st, int k0) {
        const uint32_t s0 = sb + st * STAGE_B;
#pragma unroll
        for (int i = 0; i < BM / 64; i++) {
            const int q = tid + i * 256;
            const int row = q >> 2, c16 = q & 3;
            const size_t ga = (size_t)(mbase + row) * lda + k0 + c16 * 8;
            const uint32_t so = (uint32_t)(row * A_LD + c16 * 8) * 2;
            cpa16(s0 + so, Ah + ga);
            cpa16(s0 + OFS_AL + so, Al + ga);
        }
#pragma unroll
        for (int i = 0; i < 2; i++) {
            const int q = tid + i * 256;
            const int kr = q >> 4, c16 = q & 15;
            const size_t gb = (size_t)(k0 + kr) * ldb + nbase + c16 * 8;
            const uint32_t so = (uint32_t)(kr * B_LD + c16 * 8) * 2;
            cpa16(s0 + OFS_BH + so, Bh + gb);
            cpa16(s0 + OFS_BL + so, Bl + gb);
        }
    };

    issue(0, kbeg);
    cpa_commit();

    for (int c = 0; c < niter; ++c) {
        if (c + 1 < niter) {
            issue((c + 1) & 1, kbeg + (c + 1) * 32);
            cpa_commit();
            cpa_wait1();
        } else {
            cpa_wait0();
        }
        __syncthreads();

        const uint32_t s0 = sb + (c & 1) * STAGE_B;
#pragma unroll
        for (int ks = 0; ks < 32; ks += 16) {
            uint32_t Af[MTILES][4], Alf[MTILES][4];
#pragma unroll
            for (int mt = 0; mt < MTILES; mt++) {
                const uint32_t off = (uint32_t)((wm + mt * 16 + (lane & 15)) * A_LD
                                                + ks + (lane >> 4) * 8) * 2;
                ldmA(Af[mt],  s0 + off);
                ldmA(Alf[mt], s0 + OFS_AL + off);
            }
            uint32_t Bf[4][2], Blf[4][2];
#pragma unroll
            for (int g = 0; g < 2; g++) {
                const uint32_t off = (uint32_t)((ks + (lane & 15)) * B_LD
                                                + wn + g * 16 + (lane >> 4) * 8) * 2;
                ldmT(Bf[2*g][0], Bf[2*g][1], Bf[2*g+1][0], Bf[2*g+1][1], s0 + OFS_BH + off);
                ldmT(Blf[2*g][0], Blf[2*g][1], Blf[2*g+1][0], Blf[2*g+1][1], s0 + OFS_BL + off);
            }
#pragma unroll
            for (int mt = 0; mt < MTILES; mt++)
#pragma unroll
                for (int nt = 0; nt < 4; nt++) {
                    mma16816(acc[mt][nt], Af[mt],  Bf[nt]);
                    mma16816(acc[mt][nt], Alf[mt], Bf[nt]);
                    mma16816(acc[mt][nt], Af[mt],  Blf[nt]);
                }
        }
        __syncthreads();
    }

    float* Cb = (EPI == 0) ? (Cf + (size_t)blockIdx.z * cslice) : Cf;
    const int tr = lane >> 2, tc = (lane & 3) * 2;
#pragma unroll
    for (int mt = 0; mt < MTILES; mt++) {
#pragma unroll
        for (int nt = 0; nt < 4; nt++) {
#pragma unroll
            for (int half = 0; half < 2; half++) {
                const int row = mbase + wm + mt * 16 + tr + half * 8;
                const int col = nbase + wn + nt * 8 + tc;
                float2 v = make_float2(acc[mt][nt][half * 2], acc[mt][nt][half * 2 + 1]);
                if (EPI == 0) {
                    *(float2*)(Cb + (size_t)row * ldc + col) = v;
                } else if (EPI == 1) {
                    v.x = silu_f(v.x); v.y = silu_f(v.y);
                    uint32_t hp, lp;
                    split2(v.x, v.y, hp, lp);
                    *(uint32_t*)(Ch + (size_t)row * ldc + col) = hp;
                    *(uint32_t*)(Cl + (size_t)row * ldc + col) = lp;
                } else {
                    float* p = Cb + (size_t)row * ldc + col;
                    float2 o = *(float2*)p;
                    v.x += o.x; v.y += o.y;
                    *(float2*)p = v;
                    uint32_t hp, lp;
                    split2(v.x, v.y, hp, lp);
                    *(uint32_t*)(Ch + (size_t)row * ldc + col) = hp;
                    *(uint32_t*)(Cl + (size_t)row * ldc + col) = lp;
                }
            }
        }
    }
}

// ---------------------------------------------------------------------------
// fp32 -> bf16 hi/lo split
// ---------------------------------------------------------------------------
__global__ void split_k(const float* __restrict__ src,
                        __nv_bfloat16* __restrict__ hi, __nv_bfloat16* __restrict__ lo, int n4)
{
    const int i = blockIdx.x * blockDim.x + threadIdx.x;
    if (i >= n4) return;
    const float4 v = ((const float4*)src)[i];
    uint32_t h0, l0, h1, l1;
    split2(v.x, v.y, h0, l0);
    split2(v.z, v.w, h1, l1);
    ((uint2*)hi)[i] = make_uint2(h0, h1);
    ((uint2*)lo)[i] = make_uint2(l0, l1);
}

// ---------------------------------------------------------------------------
// Small kernels
// ---------------------------------------------------------------------------
__global__ void compute_starts_k(const int* __restrict__ seg, int* __restrict__ starts,
                                 int* __restrict__ ends)
{
    int b = threadIdx.x;
    if (b >= Bsz) return;
    int cnt = 0;
    for (int t = 0; t < Lseq && cnt < NSEG; t++)
        if (seg[b * Lseq + t] != 0) starts[b * NSEG + cnt++] = t;
    while (cnt < NSEG) { starts[b * NSEG + cnt] = 0; cnt++; }
    for (int i = 0; i < NSEG - 1; i++) ends[b * NSEG + i] = starts[b * NSEG + i + 1];
    ends[b * NSEG + NSEG - 1] = Lseq;
}

__global__ void gather_correct_k(const int* __restrict__ ids, const float* __restrict__ E,
                                 float* __restrict__ x,
                                 __nv_bfloat16* __restrict__ xh, __nv_bfloat16* __restrict__ xl)
{
    const int row = blockIdx.x;
    const int id = ids[row];
    const float4 v = ((const float4*)(E + (size_t)id * Dm))[threadIdx.x];
    ((float4*)(x + (size_t)row * Dm))[threadIdx.x] = v;
    uint32_t h0, l0, h1, l1;
    split2(v.x, v.y, h0, l0);
    split2(v.z, v.w, h1, l1);
    ((uint2*)(xh + (size_t)row * Dm))[threadIdx.x] = make_uint2(h0, h1);
    ((uint2*)(xl + (size_t)row * Dm))[threadIdx.x] = make_uint2(l0, l1);
}

// ---------------------------------------------------------------------------
// Recurrence, unroll-8 with register double-buffer prefetch.
// h_t = a*h_{t-1} + u_t ; p_t = silu(g_t)*h_t -> ph/pl (bf16 hi/lo).
// Optionally (stateOut != nullptr) writes h checkpoints at segment starts:
//   state[q, i] = h_{starts[q,i]-1}  (0 if starts[q,i]==0).  Replaces save_state.
// ---------------------------------------------------------------------------
__global__ void recurrence_k(const float* __restrict__ ug, const float* __restrict__ Avec,
                             __nv_bfloat16* __restrict__ ph, __nv_bfloat16* __restrict__ pl,
                             const float* __restrict__ init,
                             float* __restrict__ stateOut, const int* __restrict__ starts,
                             int seqlen)
{
    const int idx = blockIdx.x * blockDim.x + threadIdx.x;
    const int q = idx >> 10;
    const int c = idx & (INNER - 1);
    const float a = Avec[c];
    const float* up = ug + (size_t)q * seqlen * (2 * INNER) + c;
    const float* gp = up + INNER;
    __nv_bfloat16* php = ph + (size_t)q * seqlen * INNER + c;
    __nv_bfloat16* plp = pl + (size_t)q * seqlen * INNER + c;
    float hv = init ? init[idx] : 0.f;

    int si = 0, nextStart = 0x7fffffff;
    if (stateOut) {
        while (si < NSEG && starts[q * NSEG + si] <= 0) {
            stateOut[((size_t)q * NSEG + si) * INNER + c] = 0.f;   // start==0 -> zero state
            si++;
        }
        if (si < NSEG) nextStart = starts[q * NSEG + si];
    }

    float u0[8], g0[8], u1[8], g1[8];
#pragma unroll
    for (int j = 0; j < 8; j++) {
        u0[j] = up[(size_t)j * (2 * INNER)];
        g0[j] = gp[(size_t)j * (2 * INNER)];
    }
    for (int t0 = 0; t0 < seqlen; t0 += 8) {
        if (t0 + 8 < seqlen) {
#pragma unroll
            for (int j = 0; j < 8; j++) {
                u1[j] = up[(size_t)(t0 + 8 + j) * (2 * INNER)];
                g1[j] = gp[(size_t)(t0 + 8 + j) * (2 * INNER)];
            }
        }
#pragma unroll
        for (int j = 0; j < 8; j++) {
            const int t = t0 + j;
            hv = fmaf(a, hv, u0[j]);
            if (stateOut && (t + 1) == nextStart) {
                stateOut[((size_t)q * NSEG + si) * INNER + c] = hv;
                si++;
                nextStart = (si < NSEG) ? starts[q * NSEG + si] : 0x7fffffff;
            }
            const float p = silu_f(g0[j]) * hv;
            const __nv_bfloat16 hi = __float2bfloat16(p);
            const __nv_bfloat16 lo = __float2bfloat16(p - __bfloat162float(hi));
            php[(size_t)t * INNER] = hi;
            plp[(size_t)t * INNER] = lo;
        }
#pragma unroll
        for (int j = 0; j < 8; j++) { u0[j] = u1[j]; g0[j] = g1[j]; }
    }
}

__global__ void build_xs_k(const float* __restrict__ part, float* __restrict__ xs,
                           __nv_bfloat16* __restrict__ xsh, __nv_bfloat16* __restrict__ xsl,
                           const int* __restrict__ starts, const int* __restrict__ ends)
{
    const int r = blockIdx.x;
    const int q = r >> 7;
    const int t = r & (SEGLEN - 1);
    const int b = q >> 3;
    const int s = starts[q], e = ends[q];
    const int pos = s + t;
    float4 v = make_float4(0.f, 0.f, 0.f, 0.f);
    if (pos < e && pos < Lseq) {
        const size_t base = ((size_t)b * Lseq + pos) * Dm;
#pragma unroll
        for (int p = 0; p < DEC_SK; p++) {
            const float4 w = ((const float4*)(part + (size_t)p * NROWS * Dm + base))[threadIdx.x];
            v.x += w.x; v.y += w.y; v.z += w.z; v.w += w.w;
        }
    }
    ((float4*)(xs + (size_t)r * Dm))[threadIdx.x] = v;
    uint32_t h0, l0, h1, l1;
    split2(v.x, v.y, h0, l0);
    split2(v.z, v.w, h1, l1);
    ((uint2*)(xsh + (size_t)r * Dm))[threadIdx.x] = make_uint2(h0, h1);
    ((uint2*)(xsl + (size_t)r * Dm))[threadIdx.x] = make_uint2(l0, l1);
}

__global__ void extract_last_k(const float* __restrict__ xs, float* __restrict__ last,
                               const int* __restrict__ starts, const int* __restrict__ ends)
{
    const int q = blockIdx.x;
    int len = ends[q] - starts[q];
    if (len > SEGLEN) len = SEGLEN;
    if (len < 1) len = 1;
    const float4* s = (const float4*)(xs + ((size_t)q * SEGLEN + (len - 1)) * Dm);
    float4* d = (float4*)(last + (size_t)q * Dm);
    d[threadIdx.x] = s[threadIdx.x];
}

__global__ void head_k(const float* __restrict__ last,
                       const float* __restrict__ muW, const float* __restrict__ mub,
                       const float* __restrict__ lvW, const float* __restrict__ lvb,
                       float* __restrict__ out)
{
    const int o = blockIdx.x * blockDim.x + threadIdx.x;
    const int which = o >> 13;
    const int rem = o & 8191;
    const int r = rem >> 9, d = rem & 511;
    const float* W = which ? lvW : muW;
    const float* bias = which ? lvb : mub;
    const float* lr = last + (size_t)r * Dm;
    float acc = bias[d];
#pragma unroll 8
    for (int k = 0; k < Dm; k++) acc = fmaf(lr[k], W[(size_t)k * Dm + d], acc);
    out[o] = acc;
}

// ---------------------------------------------------------------------------
// Orchestration. Launch order matters: launch #5 (0-based) is the dec GEMM so
// the ncu capture (-s 5 -c 1) profiles it.
// ---------------------------------------------------------------------------
extern "C" void kernel_launch(void* const* d_in, const int* in_sizes, int n_in,
                              void* d_out, int out_size)
{
    const float* decoder_output = (const float*)d_in[0];
    const int*   input_ids      = (const int*)  d_in[1];
    const int*   seg_idx        = (const int*)  d_in[2];
    const float* E              = (const float*)d_in[3];
    const float* Aparam         = (const float*)d_in[4];
    const float* Win            = (const float*)d_in[5];
    const float* Wout           = (const float*)d_in[6];
    const float* Wm1            = (const float*)d_in[7];
    const float* Wm2            = (const float*)d_in[8];
    const float* muW            = (const float*)d_in[9];
    const float* mub            = (const float*)d_in[10];
    const float* lvW            = (const float*)d_in[11];
    const float* lvb            = (const float*)d_in[12];
    float* out = (float*)d_out;

    float *x, *decpart, *ug, *xs, *state, *last;
    int *starts, *ends;
    __nv_bfloat16 *decAh, *decAl, *xh, *xl, *ph, *pl, *mlph, *mlpl;
    __nv_bfloat16 *eh, *el, *winh, *winl, *wouth, *woutl, *wm1h, *wm1l, *wm2h, *wm2l;
    cudaGetSymbolAddress((void**)&x,       g_x);
    cudaGetSymbolAddress((void**)&decpart, g_decpart);
    cudaGetSymbolAddress((void**)&ug,      g_ug);
    cudaGetSymbolAddress((void**)&xs,      g_xs);
    cudaGetSymbolAddress((void**)&state,   g_state);
    cudaGetSymbolAddress((void**)&last,    g_last);
    cudaGetSymbolAddress((void**)&starts,  g_starts);
    cudaGetSymbolAddress((void**)&ends,    g_ends);
    cudaGetSymbolAddress((void**)&decAh,   g_decAh);
    cudaGetSymbolAddress((void**)&decAl,   g_decAl);
    cudaGetSymbolAddress((void**)&xh,      g_xh);
    cudaGetSymbolAddress((void**)&xl,      g_xl);
    cudaGetSymbolAddress((void**)&ph,      g_ph);
    cudaGetSymbolAddress((void**)&pl,      g_pl);
    cudaGetSymbolAddress((void**)&mlph,    g_mlph);
    cudaGetSymbolAddress((void**)&mlpl,    g_mlpl);
    cudaGetSymbolAddress((void**)&eh,      g_Eh);
    cudaGetSymbolAddress((void**)&el,      g_El);
    cudaGetSymbolAddress((void**)&winh,    g_WinH);
    cudaGetSymbolAddress((void**)&winl,    g_WinL);
    cudaGetSymbolAddress((void**)&wouth,   g_WoutH);
    cudaGetSymbolAddress((void**)&woutl,   g_WoutL);
    cudaGetSymbolAddress((void**)&wm1h,    g_Wm1H);
    cudaGetSymbolAddress((void**)&wm1l,    g_Wm1L);
    cudaGetSymbolAddress((void**)&wm2h,    g_Wm2H);
    cudaGetSymbolAddress((void**)&wm2l,    g_Wm2L);

    constexpr int SM4 = (2 * 128 * A_LD + 2 * 32 * B_LD) * 2 * 2;
    constexpr int SM2 = (2 * 64  * A_LD + 2 * 32 * B_LD) * 2 * 2;
    cudaFuncSetAttribute(gemm_mma<4, 0>, cudaFuncAttributeMaxDynamicSharedMemorySize, SM4);
    cudaFuncSetAttribute(gemm_mma<4, 1>, cudaFuncAttributeMaxDynamicSharedMemorySize, SM4);
    cudaFuncSetAttribute(gemm_mma<2, 2>, cudaFuncAttributeMaxDynamicSharedMemorySize, SM2);

    auto split = [&](const float* s, __nv_bfloat16* hh, __nv_bfloat16* ll, size_t n) {
        split_k<<<(int)((n / 4 + 255) / 256), 256>>>(s, hh, ll, (int)(n / 4));
    };

    // #0..#4
    compute_starts_k<<<1, 32>>>(seg_idx, starts, ends);
    gather_correct_k<<<NROWS, 128>>>(input_ids, E, x, xh, xl);
    split(E,    eh,    el,    (size_t)VOC * Dm);
    split(decoder_output, decAh, decAl, (size_t)NROWS * VOC);
    split(Win,  winh,  winl,  (size_t)NLAY * Dm * 2 * INNER);

    // #5: dec = decoder_output @ E  (the launch ncu profiles)
    gemm_mma<4, 0><<<dim3(Dm / 128, NROWS / 128, DEC_SK), 256, SM4>>>(
        decAh, decAl, eh, el, decpart, nullptr, nullptr,
        VOC, Dm, Dm, DEC_KSLICE, NROWS * Dm);

    // remaining weight splits
    split(Wout, wouth, woutl, (size_t)NLAY * INNER * Dm);
    split(Wm1,  wm1h,  wm1l,  (size_t)NLAY * Dm * MLPD);
    split(Wm2,  wm2h,  wm2l,  (size_t)NLAY * MLPD * Dm);

    // -------- Base pass --------
    for (int l = 0; l < NLAY; l++) {
        const size_t oWin  = (size_t)l * Dm * 2 * INNER;
        const size_t oWout = (size_t)l * INNER * Dm;
        const size_t oWm1  = (size_t)l * Dm * MLPD;
        const size_t oWm2  = (size_t)l * MLPD * Dm;
        const float* Al    = Aparam + (size_t)l * INNER;
        float* stl = state + (size_t)l * Bsz * NSEG * INNER;

        gemm_mma<4, 0><<<dim3((2 * INNER) / 128, NROWS / 128, 1), 256, SM4>>>(
            xh, xl, winh + oWin, winl + oWin, ug, nullptr, nullptr,
            Dm, 2 * INNER, 2 * INNER, Dm, 0);
        recurrence_k<<<(Bsz * INNER) / 256, 256>>>(ug, Al, ph, pl, nullptr, stl, starts, Lseq);
        gemm_mma<2, 2><<<dim3(Dm / 128, NROWS / 64, 1), 256, SM2>>>(
            ph, pl, wouth + oWout, woutl + oWout, x, xh, xl,
            INNER, Dm, Dm, INNER, 0);
        gemm_mma<4, 1><<<dim3(MLPD / 128, NROWS / 128, 1), 256, SM4>>>(
            xh, xl, wm1h + oWm1, wm1l + oWm1, nullptr, mlph, mlpl,
            Dm, MLPD, MLPD, Dm, 0);
        gemm_mma<2, 2><<<dim3(Dm / 128, NROWS / 64, 1), 256, SM2>>>(
            mlph, mlpl, wm2h + oWm2, wm2l + oWm2, x, xh, xl,
            MLPD, Dm, Dm, MLPD, 0);
    }

    // -------- Segment pass --------
    build_xs_k<<<NROWS, 128>>>(decpart, xs, xh, xl, starts, ends);
    for (int l = 0; l < NLAY; l++) {
        const size_t oWin  = (size_t)l * Dm * 2 * INNER;
        const size_t oWout = (size_t)l * INNER * Dm;
        const size_t oWm1  = (size_t)l * Dm * MLPD;
        const size_t oWm2  = (size_t)l * MLPD * Dm;
        const float* Al    = Aparam + (size_t)l * INNER;
        const float* stl = state + (size_t)l * Bsz * NSEG * INNER;

        gemm_mma<4, 0><<<dim3((2 * INNER) / 128, NROWS / 128, 1), 256, SM4>>>(
            xh, xl, winh + oWin, winl + oWin, ug, nullptr, nullptr,
            Dm, 2 * INNER, 2 * INNER, Dm, 0);
        recurrence_k<<<(Bsz * NSEG * INNER) / 256, 256>>>(ug, Al, ph, pl, stl,
                                                          nullptr, nullptr, SEGLEN);
        gemm_mma<2, 2><<<dim3(Dm / 128, NROWS / 64, 1), 256, SM2>>>(
            ph, pl, wouth + oWout, woutl + oWout, xs, xh, xl,
            INNER, Dm, Dm, INNER, 0);
        gemm_mma<4, 1><<<dim3(MLPD / 128, NROWS / 128, 1), 256, SM4>>>(
            xh, xl, wm1h + oWm1, wm1l + oWm1, nullptr, mlph, mlpl,
            Dm, MLPD, MLPD, Dm, 0);
        gemm_mma<2, 2><<<dim3(Dm / 128, NROWS / 64, 1), 256, SM2>>>(
            mlph, mlpl, wm2h + oWm2, wm2l + oWm2, xs, xh, xl,
            MLPD, Dm, Dm, MLPD, 0);
    }

    extract_last_k<<<Bsz * NSEG, 128>>>(xs, last, starts, ends);
    head_k<<<(2 * Bsz * NSEG * Dm) / 256, 256>>>(last, muW, mub, lvW, lvb, out);
}

// round 7
// speedup vs baseline: 1.5239x; 1.5239x over previous
#include <cuda_runtime.h>
#include <cuda_bf16.h>
#include <cstdint>

// ---------------------------------------------------------------------------
// Problem constants
// ---------------------------------------------------------------------------
#define Bsz    2
#define Lseq   1024
#define VOC    32000
#define Dm     512
#define NLAY   2
#define INNER  1024
#define MLPD   2048
#define NSEG   8
#define SEGLEN 128
#define NROWS  (Bsz*Lseq)      // 2048
#define DEC_SK 8
#define DEC_KSLICE (VOC/DEC_SK)   // 4000
#define NCH    8               // scan chunks per base sequence (1024/128)

// ---------------------------------------------------------------------------
// Scratch
// ---------------------------------------------------------------------------
__device__ float g_x      [NROWS * Dm];
__device__ float g_dec    [NROWS * Dm];
__device__ float g_decpart[DEC_SK * NROWS * Dm];
__device__ float g_ug     [NROWS * 2 * INNER];
__device__ float g_h      [NROWS * INNER];
__device__ float g_mlp    [NROWS * MLPD];
__device__ float g_xs     [NROWS * Dm];
__device__ float g_state  [NLAY * Bsz * NSEG * INNER];
__device__ float g_carry  [Bsz * NCH * INNER];
__device__ float g_sin    [Bsz * NCH * INNER];
__device__ float g_last   [Bsz * NSEG * Dm];
__device__ int   g_starts [Bsz * NSEG];
__device__ int   g_ends   [Bsz * NSEG];
__device__ __nv_bfloat16 g_Eh   [VOC * Dm];
__device__ __nv_bfloat16 g_El   [VOC * Dm];
__device__ __nv_bfloat16 g_WinH [NLAY * Dm * 2 * INNER];
__device__ __nv_bfloat16 g_WinL [NLAY * Dm * 2 * INNER];
__device__ __nv_bfloat16 g_WoutH[NLAY * INNER * Dm];
__device__ __nv_bfloat16 g_WoutL[NLAY * INNER * Dm];
__device__ __nv_bfloat16 g_Wm1H [NLAY * Dm * MLPD];
__device__ __nv_bfloat16 g_Wm1L [NLAY * Dm * MLPD];
__device__ __nv_bfloat16 g_Wm2H [NLAY * MLPD * Dm];
__device__ __nv_bfloat16 g_Wm2L [NLAY * MLPD * Dm];

__device__ __forceinline__ float silu_f(float v) { return v * (1.f / (1.f + __expf(-v))); }

__device__ __forceinline__ void split2(float a, float b, uint32_t& hp, uint32_t& lp) {
    __nv_bfloat16 ah = __float2bfloat16(a), bh = __float2bfloat16(b);
    float ar = a - __bfloat162float(ah), br = b - __bfloat162float(bh);
    __nv_bfloat16 al = __float2bfloat16(ar), bl = __float2bfloat16(br);
    hp = (uint32_t)__bfloat16_as_ushort(ah) | ((uint32_t)__bfloat16_as_ushort(bh) << 16);
    lp = (uint32_t)__bfloat16_as_ushort(al) | ((uint32_t)__bfloat16_as_ushort(bl) << 16);
}

// ---------------------------------------------------------------------------
// mma.sync / ldmatrix primitives
// ---------------------------------------------------------------------------
__device__ __forceinline__ uint32_t smem_u32(const void* p) {
    return (uint32_t)__cvta_generic_to_shared(p);
}

__device__ __forceinline__ void ldmA(uint32_t* r, uint32_t addr) {
    asm volatile("ldmatrix.sync.aligned.m8n8.x4.shared.b16 {%0,%1,%2,%3}, [%4];"
                 : "=r"(r[0]), "=r"(r[1]), "=r"(r[2]), "=r"(r[3]) : "r"(addr));
}

__device__ __forceinline__ void ldmT(uint32_t& r0, uint32_t& r1, uint32_t& r2, uint32_t& r3,
                                     uint32_t addr) {
    asm volatile("ldmatrix.sync.aligned.m8n8.x4.trans.shared.b16 {%0,%1,%2,%3}, [%4];"
                 : "=r"(r0), "=r"(r1), "=r"(r2), "=r"(r3) : "r"(addr));
}

__device__ __forceinline__ void mma16816(float* c, const uint32_t* a, const uint32_t* b) {
    asm volatile("mma.sync.aligned.m16n8k16.row.col.f32.bf16.bf16.f32 "
                 "{%0,%1,%2,%3}, {%4,%5,%6,%7}, {%8,%9}, {%0,%1,%2,%3};"
                 : "+f"(c[0]), "+f"(c[1]), "+f"(c[2]), "+f"(c[3])
                 : "r"(a[0]), "r"(a[1]), "r"(a[2]), "r"(a[3]), "r"(b[0]), "r"(b[1]));
}

// ---------------------------------------------------------------------------
// Round-3 GEMM, templated on MTILES (BM = 32*MTILES).
//   fp32 A split on the fly to bf16 hi/lo; B pre-split hi/lo.
//   3-term: AhBh + AlBh + AhBl.
//   AMODE 0: a = A[r,k] ; AMODE 1: a = silu(A[r,k]) * A2[r,k]
//   EPI 0: C = acc ; EPI 1: C = silu(acc) ; EPI 2: C += acc
// ---------------------------------------------------------------------------
#define A_LD 40
#define B_LD 136

template<int MTILES, int AMODE, int EPI>
__global__ void __launch_bounds__(256)
gemm_mma(const float* __restrict__ A, const float* __restrict__ A2,
         const __nv_bfloat16* __restrict__ Bh, const __nv_bfloat16* __restrict__ Bl,
         float* __restrict__ C,
         int lda, int lda2, int ldb, int ldc, int kchunk, int cslice)
{
    constexpr int BM = MTILES * 32;
    __shared__ __align__(16) __nv_bfloat16 sAh[BM * A_LD];
    __shared__ __align__(16) __nv_bfloat16 sAl[BM * A_LD];
    __shared__ __align__(16) __nv_bfloat16 sBh[32 * B_LD];
    __shared__ __align__(16) __nv_bfloat16 sBl[32 * B_LD];

    const int tid  = threadIdx.x;
    const int lane = tid & 31;
    const int wid  = tid >> 5;
    const int wm = (wid & 1) * (MTILES * 16);
    const int wn = (wid >> 1) * 32;
    const int mbase = blockIdx.y * BM;
    const int nbase = blockIdx.x * 128;
    const int kbeg  = blockIdx.z * kchunk;

    float acc[MTILES][4][4];
#pragma unroll
    for (int i = 0; i < MTILES; i++)
#pragma unroll
        for (int j = 0; j < 4; j++)
#pragma unroll
            for (int f = 0; f < 4; f++) acc[i][j][f] = 0.f;

    const int arow = tid >> 3, ac4 = tid & 7;      // 32 rows / slot
    const int brow = tid >> 4, bc8 = tid & 15;     // 16 k-rows / slot

    for (int k0 = kbeg; k0 < kbeg + kchunk; k0 += 32) {
        float4 a[MTILES], g2[MTILES];
        uint4 vbh[2], vbl[2];
#pragma unroll
        for (int i = 0; i < MTILES; i++) {
            const int r = arow + i * 32;
            a[i] = *(const float4*)(A + (size_t)(mbase + r) * lda + k0 + ac4 * 4);
            if (AMODE == 1)
                g2[i] = *(const float4*)(A2 + (size_t)(mbase + r) * lda2 + k0 + ac4 * 4);
        }
#pragma unroll
        for (int i = 0; i < 2; i++) {
            const int r = brow + i * 16;
            const size_t gb = (size_t)(k0 + r) * ldb + nbase + bc8 * 8;
            vbh[i] = *(const uint4*)(Bh + gb);
            vbl[i] = *(const uint4*)(Bl + gb);
        }

        __syncthreads();
#pragma unroll
        for (int i = 0; i < MTILES; i++) {
            const int r = arow + i * 32;
            float4 v = a[i];
            if (AMODE == 1) {
                v.x = silu_f(v.x) * g2[i].x; v.y = silu_f(v.y) * g2[i].y;
                v.z = silu_f(v.z) * g2[i].z; v.w = silu_f(v.w) * g2[i].w;
            }
            uint32_t h0, l0, h1, l1;
            split2(v.x, v.y, h0, l0);
            split2(v.z, v.w, h1, l1);
            *(uint2*)(sAh + r * A_LD + ac4 * 4) = make_uint2(h0, h1);
            *(uint2*)(sAl + r * A_LD + ac4 * 4) = make_uint2(l0, l1);
        }
#pragma unroll
        for (int i = 0; i < 2; i++) {
            const int r = brow + i * 16;
            *(uint4*)(sBh + r * B_LD + bc8 * 8) = vbh[i];
            *(uint4*)(sBl + r * B_LD + bc8 * 8) = vbl[i];
        }
        __syncthreads();

#pragma unroll
        for (int ks = 0; ks < 32; ks += 16) {
            uint32_t Af[MTILES][4], Alf[MTILES][4];
#pragma unroll
            for (int mt = 0; mt < MTILES; mt++) {
                const int off = (wm + mt * 16 + (lane & 15)) * A_LD + ks + (lane >> 4) * 8;
                ldmA(Af[mt],  smem_u32(sAh + off));
                ldmA(Alf[mt], smem_u32(sAl + off));
            }
            uint32_t Bf[4][2], Blf[4][2];
#pragma unroll
            for (int g = 0; g < 2; g++) {
                const int off = (ks + (lane & 15)) * B_LD + wn + g * 16 + (lane >> 4) * 8;
                ldmT(Bf[2*g][0], Bf[2*g][1], Bf[2*g+1][0], Bf[2*g+1][1], smem_u32(sBh + off));
                ldmT(Blf[2*g][0], Blf[2*g][1], Blf[2*g+1][0], Blf[2*g+1][1], smem_u32(sBl + off));
            }
#pragma unroll
            for (int mt = 0; mt < MTILES; mt++)
#pragma unroll
                for (int nt = 0; nt < 4; nt++) {
                    mma16816(acc[mt][nt], Af[mt],  Bf[nt]);
                    mma16816(acc[mt][nt], Alf[mt], Bf[nt]);
                    mma16816(acc[mt][nt], Af[mt],  Blf[nt]);
                }
        }
    }

    float* Cb = C + (size_t)blockIdx.z * cslice;
    const int tr = lane >> 2, tc = (lane & 3) * 2;
#pragma unroll
    for (int mt = 0; mt < MTILES; mt++) {
#pragma unroll
        for (int nt = 0; nt < 4; nt++) {
            const int row = mbase + wm + mt * 16 + tr;
            const int col = nbase + wn + nt * 8 + tc;
            float2 v0 = make_float2(acc[mt][nt][0], acc[mt][nt][1]);
            float2 v1 = make_float2(acc[mt][nt][2], acc[mt][nt][3]);
            float* p0 = Cb + (size_t)row * ldc + col;
            float* p1 = Cb + (size_t)(row + 8) * ldc + col;
            if (EPI == 1) {
                v0.x = silu_f(v0.x); v0.y = silu_f(v0.y);
                v1.x = silu_f(v1.x); v1.y = silu_f(v1.y);
            }
            if (EPI == 2) {
                float2 o0 = *(float2*)p0, o1 = *(float2*)p1;
                v0.x += o0.x; v0.y += o0.y; v1.x += o1.x; v1.y += o1.y;
            }
            *(float2*)p0 = v0;
            *(float2*)p1 = v1;
        }
    }
}

// ---------------------------------------------------------------------------
// fp32 -> bf16 hi/lo split (weights + E)
// ---------------------------------------------------------------------------
__global__ void split_k(const float* __restrict__ src,
                        __nv_bfloat16* __restrict__ hi, __nv_bfloat16* __restrict__ lo, int n4)
{
    const int i = blockIdx.x * blockDim.x + threadIdx.x;
    if (i >= n4) return;
    const float4 v = ((const float4*)src)[i];
    uint32_t h0, l0, h1, l1;
    split2(v.x, v.y, h0, l0);
    split2(v.z, v.w, h1, l1);
    ((uint2*)hi)[i] = make_uint2(h0, h1);
    ((uint2*)lo)[i] = make_uint2(l0, l1);
}

// ---------------------------------------------------------------------------
// Chunked parallel linear scan:  h_t = a*h_{t-1} + u_t
// Phase 1: per-chunk carries.  Phase 2: combine.  Phase 3: final scan.
// Thread index decode: c = idx & 1023; chunk = (idx>>10) % nch; q = idx/(1024*nch)
// u = column c of ug rows (chunk-contiguous layout).
// ---------------------------------------------------------------------------
__global__ void scan_carry_k(const float* __restrict__ ug, const float* __restrict__ Avec,
                             float* __restrict__ carry, int nch)
{
    const int idx = blockIdx.x * blockDim.x + threadIdx.x;
    const int c = idx & (INNER - 1);
    const int gch = idx >> 10;              // q*nch + chunk
    const float a = Avec[c];
    const float* up = ug + (size_t)gch * SEGLEN * (2 * INNER) + c;
    float hv = 0.f;
#pragma unroll 8
    for (int t = 0; t < SEGLEN; t++)
        hv = fmaf(a, hv, up[(size_t)t * (2 * INNER)]);
    carry[idx] = hv;
}

__global__ void combine_k(const float* __restrict__ carry, const float* __restrict__ Avec,
                          float* __restrict__ sin_, int nch)
{
    const int idx = blockIdx.x * blockDim.x + threadIdx.x;   // q*INNER + c
    const int c = idx & (INNER - 1);
    const int q = idx >> 10;
    const float a = Avec[c];
    float a128 = a;
#pragma unroll
    for (int i = 0; i < 7; i++) a128 *= a128;    // a^128
    float s = 0.f;
    for (int k = 0; k < nch; k++) {
        const size_t o = (size_t)(q * nch + k) * INNER + c;
        sin_[o] = s;
        s = fmaf(a128, s, carry[o]);
    }
}

__global__ void scan_final_k(const float* __restrict__ ug, const float* __restrict__ Avec,
                             float* __restrict__ h, const float* __restrict__ sin_, int nch)
{
    const int idx = blockIdx.x * blockDim.x + threadIdx.x;
    const int c = idx & (INNER - 1);
    const int gch = idx >> 10;
    const float a = Avec[c];
    const float* up = ug + (size_t)gch * SEGLEN * (2 * INNER) + c;
    float* hp = h + (size_t)gch * SEGLEN * INNER + c;
    float hv = sin_[idx];
#pragma unroll 8
    for (int t = 0; t < SEGLEN; t++) {
        hv = fmaf(a, hv, up[(size_t)t * (2 * INNER)]);
        hp[(size_t)t * INNER] = hv;
    }
}

// ---------------------------------------------------------------------------
// Small kernels (round-3 versions)
// ---------------------------------------------------------------------------
__global__ void compute_starts_k(const int* __restrict__ seg, int* __restrict__ starts,
                                 int* __restrict__ ends)
{
    int b = threadIdx.x;
    if (b >= Bsz) return;
    int cnt = 0;
    for (int t = 0; t < Lseq && cnt < NSEG; t++)
        if (seg[b * Lseq + t] != 0) starts[b * NSEG + cnt++] = t;
    while (cnt < NSEG) { starts[b * NSEG + cnt] = 0; cnt++; }
    for (int i = 0; i < NSEG - 1; i++) ends[b * NSEG + i] = starts[b * NSEG + i + 1];
    ends[b * NSEG + NSEG - 1] = Lseq;
}

__global__ void gather_correct_k(const int* __restrict__ ids, const float* __restrict__ E,
                                 float* __restrict__ x)
{
    const int row = blockIdx.x;
    const int id = ids[row];
    const float4* s = (const float4*)(E + (size_t)id * Dm);
    float4* d = (float4*)(x + (size_t)row * Dm);
    d[threadIdx.x] = s[threadIdx.x];
}

__global__ void reduce_dec_k(const float* __restrict__ part, float* __restrict__ dec)
{
    const int i = blockIdx.x * blockDim.x + threadIdx.x;
    float s = 0.f;
#pragma unroll
    for (int p = 0; p < DEC_SK; p++) s += part[(size_t)p * NROWS * Dm + i];
    dec[i] = s;
}

__global__ void save_state_k(const float* __restrict__ h, float* __restrict__ st,
                             const int* __restrict__ starts)
{
    const int r = blockIdx.x;
    const int c = threadIdx.x;
    const int b = r >> 3;
    const int s = starts[r];
    st[(size_t)r * INNER + c] = (s > 0) ? h[((size_t)b * Lseq + (s - 1)) * INNER + c] : 0.f;
}

__global__ void build_xs_k(const float* __restrict__ dec, float* __restrict__ xs,
                           const int* __restrict__ starts, const int* __restrict__ ends)
{
    const int r = blockIdx.x;
    const int q = r >> 7;
    const int t = r & (SEGLEN - 1);
    const int b = q >> 3;
    const int s = starts[q], e = ends[q];
    const int pos = s + t;
    float4 v = make_float4(0.f, 0.f, 0.f, 0.f);
    if (pos < e && pos < Lseq)
        v = ((const float4*)(dec + ((size_t)b * Lseq + pos) * Dm))[threadIdx.x];
    ((float4*)(xs + (size_t)r * Dm))[threadIdx.x] = v;
}

__global__ void extract_last_k(const float* __restrict__ xs, float* __restrict__ last,
                               const int* __restrict__ starts, const int* __restrict__ ends)
{
    const int q = blockIdx.x;
    int len = ends[q] - starts[q];
    if (len > SEGLEN) len = SEGLEN;
    if (len < 1) len = 1;
    const float4* s = (const float4*)(xs + ((size_t)q * SEGLEN + (len - 1)) * Dm);
    float4* d = (float4*)(last + (size_t)q * Dm);
    d[threadIdx.x] = s[threadIdx.x];
}

__global__ void head_k(const float* __restrict__ last,
                       const float* __restrict__ muW, const float* __restrict__ mub,
                       const float* __restrict__ lvW, const float* __restrict__ lvb,
                       float* __restrict__ out)
{
    const int o = blockIdx.x * blockDim.x + threadIdx.x;
    const int which = o >> 13;
    const int rem = o & 8191;
    const int r = rem >> 9, d = rem & 511;
    const float* W = which ? lvW : muW;
    const float* bias = which ? lvb : mub;
    const float* lr = last + (size_t)r * Dm;
    float acc = bias[d];
#pragma unroll 8
    for (int k = 0; k < Dm; k++) acc = fmaf(lr[k], W[(size_t)k * Dm + d], acc);
    out[o] = acc;
}

// ---------------------------------------------------------------------------
// Orchestration (launch #3 = dec GEMM for the ncu capture window)
// ---------------------------------------------------------------------------
extern "C" void kernel_launch(void* const* d_in, const int* in_sizes, int n_in,
                              void* d_out, int out_size)
{
    const float* decoder_output = (const float*)d_in[0];
    const int*   input_ids      = (const int*)  d_in[1];
    const int*   seg_idx        = (const int*)  d_in[2];
    const float* E              = (const float*)d_in[3];
    const float* Aparam         = (const float*)d_in[4];
    const float* Win            = (const float*)d_in[5];
    const float* Wout           = (const float*)d_in[6];
    const float* Wm1            = (const float*)d_in[7];
    const float* Wm2            = (const float*)d_in[8];
    const float* muW            = (const float*)d_in[9];
    const float* mub            = (const float*)d_in[10];
    const float* lvW            = (const float*)d_in[11];
    const float* lvb            = (const float*)d_in[12];
    float* out = (float*)d_out;

    float *x, *dec, *decpart, *ug, *h, *mlp, *xs, *state, *carry, *sins, *last;
    int *starts, *ends;
    __nv_bfloat16 *eh, *el, *winh, *winl, *wouth, *woutl, *wm1h, *wm1l, *wm2h, *wm2l;
    cudaGetSymbolAddress((void**)&x,       g_x);
    cudaGetSymbolAddress((void**)&dec,     g_dec);
    cudaGetSymbolAddress((void**)&decpart, g_decpart);
    cudaGetSymbolAddress((void**)&ug,      g_ug);
    cudaGetSymbolAddress((void**)&h,       g_h);
    cudaGetSymbolAddress((void**)&mlp,     g_mlp);
    cudaGetSymbolAddress((void**)&xs,      g_xs);
    cudaGetSymbolAddress((void**)&state,   g_state);
    cudaGetSymbolAddress((void**)&carry,   g_carry);
    cudaGetSymbolAddress((void**)&sins,    g_sin);
    cudaGetSymbolAddress((void**)&last,    g_last);
    cudaGetSymbolAddress((void**)&starts,  g_starts);
    cudaGetSymbolAddress((void**)&ends,    g_ends);
    cudaGetSymbolAddress((void**)&eh,      g_Eh);
    cudaGetSymbolAddress((void**)&el,      g_El);
    cudaGetSymbolAddress((void**)&winh,    g_WinH);
    cudaGetSymbolAddress((void**)&winl,    g_WinL);
    cudaGetSymbolAddress((void**)&wouth,   g_WoutH);
    cudaGetSymbolAddress((void**)&woutl,   g_WoutL);
    cudaGetSymbolAddress((void**)&wm1h,    g_Wm1H);
    cudaGetSymbolAddress((void**)&wm1l,    g_Wm1L);
    cudaGetSymbolAddress((void**)&wm2h,    g_Wm2H);
    cudaGetSymbolAddress((void**)&wm2l,    g_Wm2L);

    auto split = [&](const float* s, __nv_bfloat16* hh, __nv_bfloat16* ll, size_t n) {
        split_k<<<(int)((n / 4 + 255) / 256), 256>>>(s, hh, ll, (int)(n / 4));
    };

    // #0..#2
    split(E, eh, el, (size_t)VOC * Dm);
    compute_starts_k<<<1, 32>>>(seg_idx, starts, ends);
    gather_correct_k<<<NROWS, 128>>>(input_ids, E, x);

    // #3: dec = decoder_output @ E  (split-K=8) — the launch ncu should capture
    gemm_mma<4, 0, 0><<<dim3(Dm / 128, NROWS / 128, DEC_SK), 256>>>(
        decoder_output, nullptr, eh, el, decpart, VOC, 0, Dm, Dm, DEC_KSLICE, NROWS * Dm);
    reduce_dec_k<<<(NROWS * Dm) / 256, 256>>>(decpart, dec);

    split(Win,  winh,  winl,  (size_t)NLAY * Dm * 2 * INNER);
    split(Wout, wouth, woutl, (size_t)NLAY * INNER * Dm);
    split(Wm1,  wm1h,  wm1l,  (size_t)NLAY * Dm * MLPD);
    split(Wm2,  wm2h,  wm2l,  (size_t)NLAY * MLPD * Dm);

    // -------- Base pass --------
    for (int l = 0; l < NLAY; l++) {
        const size_t oWin  = (size_t)l * Dm * 2 * INNER;
        const size_t oWout = (size_t)l * INNER * Dm;
        const size_t oWm1  = (size_t)l * Dm * MLPD;
        const size_t oWm2  = (size_t)l * MLPD * Dm;
        const float* Al    = Aparam + (size_t)l * INNER;
        float* stl = state + (size_t)l * Bsz * NSEG * INNER;

        gemm_mma<4, 0, 0><<<dim3((2 * INNER) / 128, NROWS / 128, 1), 256>>>(
            x, nullptr, winh + oWin, winl + oWin, ug, Dm, 0, 2 * INNER, 2 * INNER, Dm, 0);
        // parallel scan: carries -> combine -> final
        scan_carry_k<<<(Bsz * NCH * INNER) / 256, 256>>>(ug, Al, carry, NCH);
        combine_k<<<(Bsz * INNER) / 256, 256>>>(carry, Al, sins, NCH);
        scan_final_k<<<(Bsz * NCH * INNER) / 256, 256>>>(ug, Al, h, sins, NCH);
        save_state_k<<<Bsz * NSEG, INNER>>>(h, stl, starts);
        gemm_mma<2, 1, 2><<<dim3(Dm / 128, NROWS / 64, 1), 256>>>(
            ug + INNER, h, wouth + oWout, woutl + oWout, x, 2 * INNER, INNER, Dm, Dm, INNER, 0);
        gemm_mma<4, 0, 1><<<dim3(MLPD / 128, NROWS / 128, 1), 256>>>(
            x, nullptr, wm1h + oWm1, wm1l + oWm1, mlp, Dm, 0, MLPD, MLPD, Dm, 0);
        gemm_mma<2, 0, 2><<<dim3(Dm / 128, NROWS / 64, 1), 256>>>(
            mlp, nullptr, wm2h + oWm2, wm2l + oWm2, x, MLPD, 0, Dm, Dm, MLPD, 0);
    }

    // -------- Segment pass --------
    build_xs_k<<<NROWS, 128>>>(dec, xs, starts, ends);
    for (int l = 0; l < NLAY; l++) {
        const size_t oWin  = (size_t)l * Dm * 2 * INNER;
        const size_t oWout = (size_t)l * INNER * Dm;
        const size_t oWm1  = (size_t)l * Dm * MLPD;
        const size_t oWm2  = (size_t)l * MLPD * Dm;
        const float* Al    = Aparam + (size_t)l * INNER;
        const float* stl = state + (size_t)l * Bsz * NSEG * INNER;

        gemm_mma<4, 0, 0><<<dim3((2 * INNER) / 128, NROWS / 128, 1), 256>>>(
            xs, nullptr, winh + oWin, winl + oWin, ug, Dm, 0, 2 * INNER, 2 * INNER, Dm, 0);
        // 16 independent 128-token scans from saved states (nch=1, init = state)
        scan_final_k<<<(Bsz * NSEG * INNER) / 256, 256>>>(ug, Al, h, stl, 1);
        gemm_mma<2, 1, 2><<<dim3(Dm / 128, NROWS / 64, 1), 256>>>(
            ug + INNER, h, wouth + oWout, woutl + oWout, xs, 2 * INNER, INNER, Dm, Dm, INNER, 0);
        gemm_mma<4, 0, 1><<<dim3(MLPD / 128, NROWS / 128, 1), 256>>>(
            xs, nullptr, wm1h + oWm1, wm1l + oWm1, mlp, Dm, 0, MLPD, MLPD, Dm, 0);
        gemm_mma<2, 0, 2><<<dim3(Dm / 128, NROWS / 64, 1), 256>>>(
            mlp, nullptr, wm2h + oWm2, wm2l + oWm2, xs, MLPD, 0, Dm, Dm, MLPD, 0);
    }

    extract_last_k<<<Bsz * NSEG, 128>>>(xs, last, starts, ends);
    head_k<<<(2 * Bsz * NSEG * Dm) / 256, 256>>>(last, muW, mub, lvW, lvb, out);
}

// round 8
// speedup vs baseline: 1.5391x; 1.0099x over previous
#include <cuda_runtime.h>
#include <cuda_bf16.h>
#include <cstdint>

// ---------------------------------------------------------------------------
// Problem constants
// ---------------------------------------------------------------------------
#define Bsz    2
#define Lseq   1024
#define VOC    32000
#define Dm     512
#define NLAY   2
#define INNER  1024
#define MLPD   2048
#define NSEG   8
#define SEGLEN 128
#define NROWS  (Bsz*Lseq)      // 2048
#define DEC_SK 8
#define DEC_KSLICE (VOC/DEC_SK)   // 4000
#define NCH    8

// ---------------------------------------------------------------------------
// Scratch
// ---------------------------------------------------------------------------
__device__ float g_x      [NROWS * Dm];
__device__ float g_decpart[DEC_SK * NROWS * Dm];
__device__ float g_ug     [NROWS * 2 * INNER];
__device__ float g_h      [NROWS * INNER];
__device__ float g_xs     [NROWS * Dm];
__device__ float g_state  [NLAY * Bsz * NSEG * INNER];
__device__ float g_carry  [Bsz * NCH * INNER];
__device__ float g_sin    [Bsz * NCH * INNER];
__device__ float g_last   [Bsz * NSEG * Dm];
__device__ int   g_starts [Bsz * NSEG];
__device__ int   g_ends   [Bsz * NSEG];
// bf16 hi/lo operands
__device__ __nv_bfloat16 g_decAh[NROWS * VOC];
__device__ __nv_bfloat16 g_decAl[NROWS * VOC];
__device__ __nv_bfloat16 g_xh   [NROWS * Dm];
__device__ __nv_bfloat16 g_xl   [NROWS * Dm];
__device__ __nv_bfloat16 g_ph   [NROWS * INNER];
__device__ __nv_bfloat16 g_pl   [NROWS * INNER];
__device__ __nv_bfloat16 g_mlph [NROWS * MLPD];
__device__ __nv_bfloat16 g_mlpl [NROWS * MLPD];
__device__ __nv_bfloat16 g_Eh   [VOC * Dm];
__device__ __nv_bfloat16 g_El   [VOC * Dm];
__device__ __nv_bfloat16 g_WinH [NLAY * Dm * 2 * INNER];
__device__ __nv_bfloat16 g_WinL [NLAY * Dm * 2 * INNER];
__device__ __nv_bfloat16 g_WoutH[NLAY * INNER * Dm];
__device__ __nv_bfloat16 g_WoutL[NLAY * INNER * Dm];
__device__ __nv_bfloat16 g_Wm1H [NLAY * Dm * MLPD];
__device__ __nv_bfloat16 g_Wm1L [NLAY * Dm * MLPD];
__device__ __nv_bfloat16 g_Wm2H [NLAY * MLPD * Dm];
__device__ __nv_bfloat16 g_Wm2L [NLAY * MLPD * Dm];

__device__ __forceinline__ float silu_f(float v) { return v * (1.f / (1.f + __expf(-v))); }

__device__ __forceinline__ void split2(float a, float b, uint32_t& hp, uint32_t& lp) {
    __nv_bfloat16 ah = __float2bfloat16(a), bh = __float2bfloat16(b);
    float ar = a - __bfloat162float(ah), br = b - __bfloat162float(bh);
    __nv_bfloat16 al = __float2bfloat16(ar), bl = __float2bfloat16(br);
    hp = (uint32_t)__bfloat16_as_ushort(ah) | ((uint32_t)__bfloat16_as_ushort(bh) << 16);
    lp = (uint32_t)__bfloat16_as_ushort(al) | ((uint32_t)__bfloat16_as_ushort(bl) << 16);
}

// ---------------------------------------------------------------------------
// primitives
// ---------------------------------------------------------------------------
__device__ __forceinline__ uint32_t smem_u32(const void* p) {
    return (uint32_t)__cvta_generic_to_shared(p);
}
__device__ __forceinline__ void ldmA(uint32_t* r, uint32_t addr) {
    asm volatile("ldmatrix.sync.aligned.m8n8.x4.shared.b16 {%0,%1,%2,%3}, [%4];"
                 : "=r"(r[0]), "=r"(r[1]), "=r"(r[2]), "=r"(r[3]) : "r"(addr));
}
__device__ __forceinline__ void ldmT(uint32_t& r0, uint32_t& r1, uint32_t& r2, uint32_t& r3,
                                     uint32_t addr) {
    asm volatile("ldmatrix.sync.aligned.m8n8.x4.trans.shared.b16 {%0,%1,%2,%3}, [%4];"
                 : "=r"(r0), "=r"(r1), "=r"(r2), "=r"(r3) : "r"(addr));
}
__device__ __forceinline__ void mma16816(float* c, const uint32_t* a, const uint32_t* b) {
    asm volatile("mma.sync.aligned.m16n8k16.row.col.f32.bf16.bf16.f32 "
                 "{%0,%1,%2,%3}, {%4,%5,%6,%7}, {%8,%9}, {%0,%1,%2,%3};"
                 : "+f"(c[0]), "+f"(c[1]), "+f"(c[2]), "+f"(c[3])
                 : "r"(a[0]), "r"(a[1]), "r"(a[2]), "r"(a[3]), "r"(b[0]), "r"(b[1]));
}
__device__ __forceinline__ void cpa16(uint32_t s, const void* g) {
    asm volatile("cp.async.cg.shared.global [%0], [%1], 16;" :: "r"(s), "l"(g));
}
__device__ __forceinline__ void cpa_commit() { asm volatile("cp.async.commit_group;"); }
__device__ __forceinline__ void cpa_wait1()  { asm volatile("cp.async.wait_group 1;"); }
__device__ __forceinline__ void cpa_wait0()  { asm volatile("cp.async.wait_group 0;"); }

// ---------------------------------------------------------------------------
// GEMM v2: 512 threads, 16 warps (4 m x 4 n), warp tile 32x32, acc=32 regs.
// BM = MTILES*64 (MTILES=2 -> 128, MTILES=1 -> 64), BN=128, BK=32.
// All operands pre-split bf16 hi/lo in global; 2-stage cp.async pipeline.
// 3-term: AhBh + AlBh + AhBl.
//   EPI 0: Cf[bz slice] = acc
//   EPI 1: (Ch,Cl) = split(silu(acc))
//   EPI 2: Cf += acc ; (Ch,Cl) = split(Cf)
// ---------------------------------------------------------------------------
#define A_LD 40
#define B_LD 136

template<int MTILES, int EPI>
__global__ void __launch_bounds__(512, 2)
gemm2(const __nv_bfloat16* __restrict__ Ah, const __nv_bfloat16* __restrict__ Al,
      const __nv_bfloat16* __restrict__ Bh, const __nv_bfloat16* __restrict__ Bl,
      float* __restrict__ Cf, __nv_bfloat16* __restrict__ Ch, __nv_bfloat16* __restrict__ Cl,
      int lda, int ldb, int ldc, int kchunk, int cslice)
{
    constexpr int BM = MTILES * 64;
    constexpr int A_E = BM * A_LD;
    constexpr int B_E = 32 * B_LD;
    constexpr int STAGE_B = (2 * A_E + 2 * B_E) * 2;
    constexpr int OFS_AL = A_E * 2;
    constexpr int OFS_BH = 2 * A_E * 2;
    constexpr int OFS_BL = 2 * A_E * 2 + B_E * 2;

    extern __shared__ __align__(16) char smem[];
    const uint32_t sb = smem_u32(smem);

    const int tid  = threadIdx.x;
    const int lane = tid & 31;
    const int wid  = tid >> 5;
    const int wm = (wid >> 2) * (MTILES * 16);   // 4 warp-rows
    const int wn = (wid & 3) * 32;               // 4 warp-cols
    const int mbase = blockIdx.y * BM;
    const int nbase = blockIdx.x * 128;
    const int kbeg  = blockIdx.z * kchunk;
    const int niter = kchunk >> 5;

    float acc[MTILES][4][4];
#pragma unroll
    for (int i = 0; i < MTILES; i++)
#pragma unroll
        for (int j = 0; j < 4; j++)
#pragma unroll
            for (int f = 0; f < 4; f++) acc[i][j][f] = 0.f;

    auto issue = [&](int st, int k0) {
        const uint32_t s0 = sb + st * STAGE_B;
        if (tid < BM * 4) {                       // A: BM rows x 4 16B-chunks
            const int row = tid >> 2, c16 = tid & 3;
            const size_t ga = (size_t)(mbase + row) * lda + k0 + c16 * 8;
            const uint32_t so = (uint32_t)(row * A_LD + c16 * 8) * 2;
            cpa16(s0 + so, Ah + ga);
            cpa16(s0 + OFS_AL + so, Al + ga);
        }
        {                                         // B: 32 k-rows x 16 chunks
            const int kr = tid >> 4, c16 = tid & 15;
            const size_t gb = (size_t)(k0 + kr) * ldb + nbase + c16 * 8;
            const uint32_t so = (uint32_t)(kr * B_LD + c16 * 8) * 2;
            cpa16(s0 + OFS_BH + so, Bh + gb);
            cpa16(s0 + OFS_BL + so, Bl + gb);
        }
    };

    issue(0, kbeg);
    cpa_commit();

    for (int c = 0; c < niter; ++c) {
        if (c + 1 < niter) {
            issue((c + 1) & 1, kbeg + (c + 1) * 32);
            cpa_commit();
            cpa_wait1();
        } else {
            cpa_wait0();
        }
        __syncthreads();

        const uint32_t s0 = sb + (c & 1) * STAGE_B;
#pragma unroll
        for (int ks = 0; ks < 32; ks += 16) {
            uint32_t Bf[4][2], Blf[4][2];
#pragma unroll
            for (int g = 0; g < 2; g++) {
                const uint32_t off = (uint32_t)((ks + (lane & 15)) * B_LD
                                                + wn + g * 16 + (lane >> 4) * 8) * 2;
                ldmT(Bf[2*g][0], Bf[2*g][1], Bf[2*g+1][0], Bf[2*g+1][1], s0 + OFS_BH + off);
                ldmT(Blf[2*g][0], Blf[2*g][1], Blf[2*g+1][0], Blf[2*g+1][1], s0 + OFS_BL + off);
            }
#pragma unroll
            for (int mt = 0; mt < MTILES; mt++) {
                uint32_t Af[4], Alf[4];
                const uint32_t offA = (uint32_t)((wm + mt * 16 + (lane & 15)) * A_LD
                                                 + ks + (lane >> 4) * 8) * 2;
                ldmA(Af,  s0 + offA);
                ldmA(Alf, s0 + OFS_AL + offA);
#pragma unroll
                for (int nt = 0; nt < 4; nt++) {
                    mma16816(acc[mt][nt], Af,  Bf[nt]);
                    mma16816(acc[mt][nt], Alf, Bf[nt]);
                    mma16816(acc[mt][nt], Af,  Blf[nt]);
                }
            }
        }
        __syncthreads();
    }

    float* Cb = (EPI == 0) ? (Cf + (size_t)blockIdx.z * cslice) : Cf;
    const int tr = lane >> 2, tc = (lane & 3) * 2;
#pragma unroll
    for (int mt = 0; mt < MTILES; mt++) {
#pragma unroll
        for (int nt = 0; nt < 4; nt++) {
#pragma unroll
            for (int half = 0; half < 2; half++) {
                const int row = mbase + wm + mt * 16 + tr + half * 8;
                const int col = nbase + wn + nt * 8 + tc;
                float2 v = make_float2(acc[mt][nt][half * 2], acc[mt][nt][half * 2 + 1]);
                if (EPI == 0) {
                    *(float2*)(Cb + (size_t)row * ldc + col) = v;
                } else if (EPI == 1) {
                    v.x = silu_f(v.x); v.y = silu_f(v.y);
                    uint32_t hp, lp;
                    split2(v.x, v.y, hp, lp);
                    *(uint32_t*)(Ch + (size_t)row * ldc + col) = hp;
                    *(uint32_t*)(Cl + (size_t)row * ldc + col) = lp;
                } else {
                    float* p = Cb + (size_t)row * ldc + col;
                    float2 o = *(float2*)p;
                    v.x += o.x; v.y += o.y;
                    *(float2*)p = v;
                    uint32_t hp, lp;
                    split2(v.x, v.y, hp, lp);
                    *(uint32_t*)(Ch + (size_t)row * ldc + col) = hp;
                    *(uint32_t*)(Cl + (size_t)row * ldc + col) = lp;
                }
            }
        }
    }
}

// ---------------------------------------------------------------------------
// fp32 -> bf16 hi/lo split
// ---------------------------------------------------------------------------
__global__ void split_k(const float* __restrict__ src,
                        __nv_bfloat16* __restrict__ hi, __nv_bfloat16* __restrict__ lo, int n4)
{
    const int i = blockIdx.x * blockDim.x + threadIdx.x;
    if (i >= n4) return;
    const float4 v = ((const float4*)src)[i];
    uint32_t h0, l0, h1, l1;
    split2(v.x, v.y, h0, l0);
    split2(v.z, v.w, h1, l1);
    ((uint2*)hi)[i] = make_uint2(h0, h1);
    ((uint2*)lo)[i] = make_uint2(l0, l1);
}

// ---------------------------------------------------------------------------
// Scan kernels (r7 structure, + fused gate/split in the final phase)
// ---------------------------------------------------------------------------
__global__ void scan_carry_k(const float* __restrict__ ug, const float* __restrict__ Avec,
                             float* __restrict__ carry)
{
    const int idx = blockIdx.x * blockDim.x + threadIdx.x;
    const int c = idx & (INNER - 1);
    const int gch = idx >> 10;
    const float a = Avec[c];
    const float* up = ug + (size_t)gch * SEGLEN * (2 * INNER) + c;
    float hv = 0.f;
#pragma unroll 8
    for (int t = 0; t < SEGLEN; t++)
        hv = fmaf(a, hv, up[(size_t)t * (2 * INNER)]);
    carry[idx] = hv;
}

__global__ void combine_k(const float* __restrict__ carry, const float* __restrict__ Avec,
                          float* __restrict__ sin_)
{
    const int idx = blockIdx.x * blockDim.x + threadIdx.x;   // q*INNER + c
    const int c = idx & (INNER - 1);
    const int q = idx >> 10;
    const float a = Avec[c];
    float a128 = a;
#pragma unroll
    for (int i = 0; i < 7; i++) a128 *= a128;
    float s = 0.f;
    for (int k = 0; k < NCH; k++) {
        const size_t o = (size_t)(q * NCH + k) * INNER + c;
        sin_[o] = s;
        s = fmaf(a128, s, carry[o]);
    }
}

// Final scan + gate: h_t = a h_{t-1} + u_t ; p_t = silu(g_t) h_t -> ph/pl.
// hout optional (base pass: needed for checkpointing).
__global__ void scan_final_gate_k(const float* __restrict__ ug, const float* __restrict__ Avec,
                                  const float* __restrict__ sin_, float* __restrict__ hout,
                                  __nv_bfloat16* __restrict__ ph, __nv_bfloat16* __restrict__ pl)
{
    const int idx = blockIdx.x * blockDim.x + threadIdx.x;
    const int c = idx & (INNER - 1);
    const int gch = idx >> 10;
    const float a = Avec[c];
    const float* up = ug + (size_t)gch * SEGLEN * (2 * INNER) + c;
    const float* gp = up + INNER;
    __nv_bfloat16* php = ph + (size_t)gch * SEGLEN * INNER + c;
    __nv_bfloat16* plp = pl + (size_t)gch * SEGLEN * INNER + c;
    float* hp = hout ? hout + (size_t)gch * SEGLEN * INNER + c : nullptr;
    float hv = sin_[idx];
#pragma unroll 4
    for (int t = 0; t < SEGLEN; t++) {
        hv = fmaf(a, hv, up[(size_t)t * (2 * INNER)]);
        if (hp) hp[(size_t)t * INNER] = hv;
        const float p = silu_f(gp[(size_t)t * (2 * INNER)]) * hv;
        const __nv_bfloat16 hi = __float2bfloat16(p);
        const __nv_bfloat16 lo = __float2bfloat16(p - __bfloat162float(hi));
        php[(size_t)t * INNER] = hi;
        plp[(size_t)t * INNER] = lo;
    }
}

// ---------------------------------------------------------------------------
// Small kernels
// ---------------------------------------------------------------------------
__global__ void compute_starts_k(const int* __restrict__ seg, int* __restrict__ starts,
                                 int* __restrict__ ends)
{
    int b = threadIdx.x;
    if (b >= Bsz) return;
    int cnt = 0;
    for (int t = 0; t < Lseq && cnt < NSEG; t++)
        if (seg[b * Lseq + t] != 0) starts[b * NSEG + cnt++] = t;
    while (cnt < NSEG) { starts[b * NSEG + cnt] = 0; cnt++; }
    for (int i = 0; i < NSEG - 1; i++) ends[b * NSEG + i] = starts[b * NSEG + i + 1];
    ends[b * NSEG + NSEG - 1] = Lseq;
}

__global__ void gather_correct_k(const int* __restrict__ ids, const float* __restrict__ E,
                                 float* __restrict__ x,
                                 __nv_bfloat16* __restrict__ xh, __nv_bfloat16* __restrict__ xl)
{
    const int row = blockIdx.x;
    const int id = ids[row];
    const float4 v = ((const float4*)(E + (size_t)id * Dm))[threadIdx.x];
    ((float4*)(x + (size_t)row * Dm))[threadIdx.x] = v;
    uint32_t h0, l0, h1, l1;
    split2(v.x, v.y, h0, l0);
    split2(v.z, v.w, h1, l1);
    ((uint2*)(xh + (size_t)row * Dm))[threadIdx.x] = make_uint2(h0, h1);
    ((uint2*)(xl + (size_t)row * Dm))[threadIdx.x] = make_uint2(l0, l1);
}

__global__ void save_state_k(const float* __restrict__ h, float* __restrict__ st,
                             const int* __restrict__ starts)
{
    const int r = blockIdx.x;
    const int c = threadIdx.x;
    const int b = r >> 3;
    const int s = starts[r];
    st[(size_t)r * INNER + c] = (s > 0) ? h[((size_t)b * Lseq + (s - 1)) * INNER + c] : 0.f;
}

// xs from split-K partials (fused reduce), + hi/lo
__global__ void build_xs_k(const float* __restrict__ part, float* __restrict__ xs,
                           __nv_bfloat16* __restrict__ xsh, __nv_bfloat16* __restrict__ xsl,
                           const int* __restrict__ starts, const int* __restrict__ ends)
{
    const int r = blockIdx.x;
    const int q = r >> 7;
    const int t = r & (SEGLEN - 1);
    const int b = q >> 3;
    const int s = starts[q], e = ends[q];
    const int pos = s + t;
    float4 v = make_float4(0.f, 0.f, 0.f, 0.f);
    if (pos < e && pos < Lseq) {
        const size_t base = ((size_t)b * Lseq + pos) * Dm;
#pragma unroll
        for (int p = 0; p < DEC_SK; p++) {
            const float4 w = ((const float4*)(part + (size_t)p * NROWS * Dm + base))[threadIdx.x];
            v.x += w.x; v.y += w.y; v.z += w.z; v.w += w.w;
        }
    }
    ((float4*)(xs + (size_t)r * Dm))[threadIdx.x] = v;
    uint32_t h0, l0, h1, l1;
    split2(v.x, v.y, h0, l0);
    split2(v.z, v.w, h1, l1);
    ((uint2*)(xsh + (size_t)r * Dm))[threadIdx.x] = make_uint2(h0, h1);
    ((uint2*)(xsl + (size_t)r * Dm))[threadIdx.x] = make_uint2(l0, l1);
}

__global__ void extract_last_k(const float* __restrict__ xs, float* __restrict__ last,
                               const int* __restrict__ starts, const int* __restrict__ ends)
{
    const int q = blockIdx.x;
    int len = ends[q] - starts[q];
    if (len > SEGLEN) len = SEGLEN;
    if (len < 1) len = 1;
    const float4* s = (const float4*)(xs + ((size_t)q * SEGLEN + (len - 1)) * Dm);
    float4* d = (float4*)(last + (size_t)q * Dm);
    d[threadIdx.x] = s[threadIdx.x];
}

__global__ void head_k(const float* __restrict__ last,
                       const float* __restrict__ muW, const float* __restrict__ mub,
                       const float* __restrict__ lvW, const float* __restrict__ lvb,
                       float* __restrict__ out)
{
    const int o = blockIdx.x * blockDim.x + threadIdx.x;
    const int which = o >> 13;
    const int rem = o & 8191;
    const int r = rem >> 9, d = rem & 511;
    const float* W = which ? lvW : muW;
    const float* bias = which ? lvb : mub;
    const float* lr = last + (size_t)r * Dm;
    float acc = bias[d];
#pragma unroll 8
    for (int k = 0; k < Dm; k++) acc = fmaf(lr[k], W[(size_t)k * Dm + d], acc);
    out[o] = acc;
}

// ---------------------------------------------------------------------------
// Orchestration (my launch #3 = dec GEMM; ncu window has ~2-launch offset)
// ---------------------------------------------------------------------------
extern "C" void kernel_launch(void* const* d_in, const int* in_sizes, int n_in,
                              void* d_out, int out_size)
{
    const float* decoder_output = (const float*)d_in[0];
    const int*   input_ids      = (const int*)  d_in[1];
    const int*   seg_idx        = (const int*)  d_in[2];
    const float* E              = (const float*)d_in[3];
    const float* Aparam         = (const float*)d_in[4];
    const float* Win            = (const float*)d_in[5];
    const float* Wout           = (const float*)d_in[6];
    const float* Wm1            = (const float*)d_in[7];
    const float* Wm2            = (const float*)d_in[8];
    const float* muW            = (const float*)d_in[9];
    const float* mub            = (const float*)d_in[10];
    const float* lvW            = (const float*)d_in[11];
    const float* lvb            = (const float*)d_in[12];
    float* out = (float*)d_out;

    float *x, *decpart, *ug, *h, *xs, *state, *carry, *sins, *last;
    int *starts, *ends;
    __nv_bfloat16 *decAh, *decAl, *xh, *xl, *ph, *pl, *mlph, *mlpl;
    __nv_bfloat16 *eh, *el, *winh, *winl, *wouth, *woutl, *wm1h, *wm1l, *wm2h, *wm2l;
    cudaGetSymbolAddress((void**)&x,       g_x);
    cudaGetSymbolAddress((void**)&decpart, g_decpart);
    cudaGetSymbolAddress((void**)&ug,      g_ug);
    cudaGetSymbolAddress((void**)&h,       g_h);
    cudaGetSymbolAddress((void**)&xs,      g_xs);
    cudaGetSymbolAddress((void**)&state,   g_state);
    cudaGetSymbolAddress((void**)&carry,   g_carry);
    cudaGetSymbolAddress((void**)&sins,    g_sin);
    cudaGetSymbolAddress((void**)&last,    g_last);
    cudaGetSymbolAddress((void**)&starts,  g_starts);
    cudaGetSymbolAddress((void**)&ends,    g_ends);
    cudaGetSymbolAddress((void**)&decAh,   g_decAh);
    cudaGetSymbolAddress((void**)&decAl,   g_decAl);
    cudaGetSymbolAddress((void**)&xh,      g_xh);
    cudaGetSymbolAddress((void**)&xl,      g_xl);
    cudaGetSymbolAddress((void**)&ph,      g_ph);
    cudaGetSymbolAddress((void**)&pl,      g_pl);
    cudaGetSymbolAddress((void**)&mlph,    g_mlph);
    cudaGetSymbolAddress((void**)&mlpl,    g_mlpl);
    cudaGetSymbolAddress((void**)&eh,      g_Eh);
    cudaGetSymbolAddress((void**)&el,      g_El);
    cudaGetSymbolAddress((void**)&winh,    g_WinH);
    cudaGetSymbolAddress((void**)&winl,    g_WinL);
    cudaGetSymbolAddress((void**)&wouth,   g_WoutH);
    cudaGetSymbolAddress((void**)&woutl,   g_WoutL);
    cudaGetSymbolAddress((void**)&wm1h,    g_Wm1H);
    cudaGetSymbolAddress((void**)&wm1l,    g_Wm1L);
    cudaGetSymbolAddress((void**)&wm2h,    g_Wm2H);
    cudaGetSymbolAddress((void**)&wm2l,    g_Wm2L);

    constexpr int SMEM2 = (2 * 128 * A_LD + 2 * 32 * B_LD) * 2 * 2;  // 75,776 B
    constexpr int SMEM1 = (2 * 64  * A_LD + 2 * 32 * B_LD) * 2 * 2;  // 55,296 B
    cudaFuncSetAttribute(gemm2<2, 0>, cudaFuncAttributeMaxDynamicSharedMemorySize, SMEM2);
    cudaFuncSetAttribute(gemm2<2, 1>, cudaFuncAttributeMaxDynamicSharedMemorySize, SMEM2);
    cudaFuncSetAttribute(gemm2<1, 2>, cudaFuncAttributeMaxDynamicSharedMemorySize, SMEM1);

    auto split = [&](const float* s, __nv_bfloat16* hh, __nv_bfloat16* ll, size_t n) {
        split_k<<<(int)((n / 4 + 255) / 256), 256>>>(s, hh, ll, (int)(n / 4));
    };

    // #0..#2
    compute_starts_k<<<1, 32>>>(seg_idx, starts, ends);
    split(E, eh, el, (size_t)VOC * Dm);
    split(decoder_output, decAh, decAl, (size_t)NROWS * VOC);

    // #3: dec = decoder_output @ E  (split-K=8) — ncu capture target
    gemm2<2, 0><<<dim3(Dm / 128, NROWS / 128, DEC_SK), 512, SMEM2>>>(
        decAh, decAl, eh, el, decpart, nullptr, nullptr,
        VOC, Dm, Dm, DEC_KSLICE, NROWS * Dm);

    gather_correct_k<<<NROWS, 128>>>(input_ids, E, x, xh, xl);
    split(Win,  winh,  winl,  (size_t)NLAY * Dm * 2 * INNER);
    split(Wout, wouth, woutl, (size_t)NLAY * INNER * Dm);
    split(Wm1,  wm1h,  wm1l,  (size_t)NLAY * Dm * MLPD);
    split(Wm2,  wm2h,  wm2l,  (size_t)NLAY * MLPD * Dm);

    // -------- Base pass --------
    for (int l = 0; l < NLAY; l++) {
        const size_t oWin  = (size_t)l * Dm * 2 * INNER;
        const size_t oWout = (size_t)l * INNER * Dm;
        const size_t oWm1  = (size_t)l * Dm * MLPD;
        const size_t oWm2  = (size_t)l * MLPD * Dm;
        const float* Al    = Aparam + (size_t)l * INNER;
        float* stl = state + (size_t)l * Bsz * NSEG * INNER;

        gemm2<2, 0><<<dim3((2 * INNER) / 128, NROWS / 128, 1), 512, SMEM2>>>(
            xh, xl, winh + oWin, winl + oWin, ug, nullptr, nullptr,
            Dm, 2 * INNER, 2 * INNER, Dm, 0);
        scan_carry_k<<<(Bsz * NCH * INNER) / 256, 256>>>(ug, Al, carry);
        combine_k<<<(Bsz * INNER) / 256, 256>>>(carry, Al, sins);
        scan_final_gate_k<<<(Bsz * NCH * INNER) / 256, 256>>>(ug, Al, sins, h, ph, pl);
        save_state_k<<<Bsz * NSEG, INNER>>>(h, stl, starts);
        gemm2<1, 2><<<dim3(Dm / 128, NROWS / 64, 1), 512, SMEM1>>>(
            ph, pl, wouth + oWout, woutl + oWout, x, xh, xl,
            INNER, Dm, Dm, INNER, 0);
        gemm2<2, 1><<<dim3(MLPD / 128, NROWS / 128, 1), 512, SMEM2>>>(
            xh, xl, wm1h + oWm1, wm1l + oWm1, nullptr, mlph, mlpl,
            Dm, MLPD, MLPD, Dm, 0);
        gemm2<1, 2><<<dim3(Dm / 128, NROWS / 64, 1), 512, SMEM1>>>(
            mlph, mlpl, wm2h + oWm2, wm2l + oWm2, x, xh, xl,
            MLPD, Dm, Dm, MLPD, 0);
    }

    // -------- Segment pass --------
    build_xs_k<<<NROWS, 128>>>(decpart, xs, xh, xl, starts, ends);
    for (int l = 0; l < NLAY; l++) {
        const size_t oWin  = (size_t)l * Dm * 2 * INNER;
        const size_t oWout = (size_t)l * INNER * Dm;
        const size_t oWm1  = (size_t)l * Dm * MLPD;
        const size_t oWm2  = (size_t)l * MLPD * Dm;
        const float* Al    = Aparam + (size_t)l * INNER;
        const float* stl = state + (size_t)l * Bsz * NSEG * INNER;

        gemm2<2, 0><<<dim3((2 * INNER) / 128, NROWS / 128, 1), 512, SMEM2>>>(
            xh, xl, winh + oWin, winl + oWin, ug, nullptr, nullptr,
            Dm, 2 * INNER, 2 * INNER, Dm, 0);
        // 16 independent 128-token scans from saved states
        scan_final_gate_k<<<(Bsz * NSEG * INNER) / 256, 256>>>(ug, Al, stl, nullptr, ph, pl);
        gemm2<1, 2><<<dim3(Dm / 128, NROWS / 64, 1), 512, SMEM1>>>(
            ph, pl, wouth + oWout, woutl + oWout, xs, xh, xl,
            INNER, Dm, Dm, INNER, 0);
        gemm2<2, 1><<<dim3(MLPD / 128, NROWS / 128, 1), 512, SMEM2>>>(
            xh, xl, wm1h + oWm1, wm1l + oWm1, nullptr, mlph, mlpl,
            Dm, MLPD, MLPD, Dm, 0);
        gemm2<1, 2><<<dim3(Dm / 128, NROWS / 64, 1), 512, SMEM1>>>(
            mlph, mlpl, wm2h + oWm2, wm2l + oWm2, xs, xh, xl,
            MLPD, Dm, Dm, MLPD, 0);
    }

    extract_last_k<<<Bsz * NSEG, 128>>>(xs, last, starts, ends);
    head_k<<<(2 * Bsz * NSEG * Dm) / 256, 256>>>(last, muW, mub, lvW, lvb, out);
}

// round 9
// speedup vs baseline: 1.5591x; 1.0130x over previous
#include <cuda_runtime.h>
#include <cuda_bf16.h>
#include <cstdint>

// ---------------------------------------------------------------------------
// Problem constants
// ---------------------------------------------------------------------------
#define Bsz    2
#define Lseq   1024
#define VOC    32000
#define Dm     512
#define NLAY   2
#define INNER  1024
#define MLPD   2048
#define NSEG   8
#define SEGLEN 128
#define NROWS  (Bsz*Lseq)      // 2048
#define DEC_SK 8
#define DEC_KSLICE (VOC/DEC_SK)   // 4000
#define NCH    8

// ---------------------------------------------------------------------------
// Scratch
// ---------------------------------------------------------------------------
__device__ float g_x      [NROWS * Dm];
__device__ float g_decpart[DEC_SK * NROWS * Dm];
__device__ float g_ug     [NROWS * 2 * INNER];
__device__ float g_h      [NROWS * INNER];
__device__ float g_xs     [NROWS * Dm];
__device__ float g_state  [NLAY * Bsz * NSEG * INNER];
__device__ float g_carry  [Bsz * NCH * INNER];
__device__ float g_sin    [Bsz * NCH * INNER];
__device__ float g_last   [Bsz * NSEG * Dm];
__device__ int   g_starts [Bsz * NSEG];
__device__ int   g_ends   [Bsz * NSEG];
// bf16 hi/lo operands
__device__ __nv_bfloat16 g_decAh[NROWS * VOC];
__device__ __nv_bfloat16 g_decAl[NROWS * VOC];
__device__ __nv_bfloat16 g_xh   [NROWS * Dm];
__device__ __nv_bfloat16 g_xl   [NROWS * Dm];
__device__ __nv_bfloat16 g_ph   [NROWS * INNER];
__device__ __nv_bfloat16 g_pl   [NROWS * INNER];
__device__ __nv_bfloat16 g_mlph [NROWS * MLPD];
__device__ __nv_bfloat16 g_mlpl [NROWS * MLPD];
__device__ __nv_bfloat16 g_Eh   [VOC * Dm];
__device__ __nv_bfloat16 g_El   [VOC * Dm];
__device__ __nv_bfloat16 g_WinH [NLAY * Dm * 2 * INNER];
__device__ __nv_bfloat16 g_WinL [NLAY * Dm * 2 * INNER];
__device__ __nv_bfloat16 g_WoutH[NLAY * INNER * Dm];
__device__ __nv_bfloat16 g_WoutL[NLAY * INNER * Dm];
__device__ __nv_bfloat16 g_Wm1H [NLAY * Dm * MLPD];
__device__ __nv_bfloat16 g_Wm1L [NLAY * Dm * MLPD];
__device__ __nv_bfloat16 g_Wm2H [NLAY * MLPD * Dm];
__device__ __nv_bfloat16 g_Wm2L [NLAY * MLPD * Dm];

__device__ __forceinline__ float silu_f(float v) { return v * (1.f / (1.f + __expf(-v))); }

__device__ __forceinline__ void split2(float a, float b, uint32_t& hp, uint32_t& lp) {
    __nv_bfloat16 ah = __float2bfloat16(a), bh = __float2bfloat16(b);
    float ar = a - __bfloat162float(ah), br = b - __bfloat162float(bh);
    __nv_bfloat16 al = __float2bfloat16(ar), bl = __float2bfloat16(br);
    hp = (uint32_t)__bfloat16_as_ushort(ah) | ((uint32_t)__bfloat16_as_ushort(bh) << 16);
    lp = (uint32_t)__bfloat16_as_ushort(al) | ((uint32_t)__bfloat16_as_ushort(bl) << 16);
}

// ---------------------------------------------------------------------------
// primitives
// ---------------------------------------------------------------------------
__device__ __forceinline__ uint32_t smem_u32(const void* p) {
    return (uint32_t)__cvta_generic_to_shared(p);
}
__device__ __forceinline__ void ldmA(uint32_t* r, uint32_t addr) {
    asm volatile("ldmatrix.sync.aligned.m8n8.x4.shared.b16 {%0,%1,%2,%3}, [%4];"
                 : "=r"(r[0]), "=r"(r[1]), "=r"(r[2]), "=r"(r[3]) : "r"(addr));
}
__device__ __forceinline__ void ldmT(uint32_t& r0, uint32_t& r1, uint32_t& r2, uint32_t& r3,
                                     uint32_t addr) {
    asm volatile("ldmatrix.sync.aligned.m8n8.x4.trans.shared.b16 {%0,%1,%2,%3}, [%4];"
                 : "=r"(r0), "=r"(r1), "=r"(r2), "=r"(r3) : "r"(addr));
}
__device__ __forceinline__ void mma16816(float* c, const uint32_t* a, const uint32_t* b) {
    asm volatile("mma.sync.aligned.m16n8k16.row.col.f32.bf16.bf16.f32 "
                 "{%0,%1,%2,%3}, {%4,%5,%6,%7}, {%8,%9}, {%0,%1,%2,%3};"
                 : "+f"(c[0]), "+f"(c[1]), "+f"(c[2]), "+f"(c[3])
                 : "r"(a[0]), "r"(a[1]), "r"(a[2]), "r"(a[3]), "r"(b[0]), "r"(b[1]));
}
__device__ __forceinline__ void cpa16(uint32_t s, const void* g) {
    asm volatile("cp.async.cg.shared.global [%0], [%1], 16;" :: "r"(s), "l"(g));
}
__device__ __forceinline__ void cpa_commit() { asm volatile("cp.async.commit_group;"); }
__device__ __forceinline__ void cpa_wait1()  { asm volatile("cp.async.wait_group 1;"); }
__device__ __forceinline__ void cpa_wait0()  { asm volatile("cp.async.wait_group 0;"); }

#define A_LD 40
#define B_LD 136
#define B_LDW 264   // wide-B row (256 + 8 pad)

// ---------------------------------------------------------------------------
// gemm_big: dec-only GEMM. CTA 128x256x32, 256 threads, 8 warps (2m x 4n),
// warp tile 64x64 (acc=128 regs). Halves smem traffic per MAC vs gemm2.
// C[bz slice] = A[M,K] * B[K,N], operands pre-split bf16 hi/lo, 3-term.
// ---------------------------------------------------------------------------
__global__ void __launch_bounds__(256, 1)
gemm_big(const __nv_bfloat16* __restrict__ Ah, const __nv_bfloat16* __restrict__ Al,
         const __nv_bfloat16* __restrict__ Bh, const __nv_bfloat16* __restrict__ Bl,
         float* __restrict__ Cf, int lda, int ldb, int ldc, int kchunk, int cslice)
{
    constexpr int A_E = 128 * A_LD;      // 5120
    constexpr int B_E = 32 * B_LDW;      // 8448
    constexpr int STAGE_B = (2 * A_E + 2 * B_E) * 2;   // 54,272 B
    constexpr int OFS_AL = A_E * 2;
    constexpr int OFS_BH = 2 * A_E * 2;
    constexpr int OFS_BL = 2 * A_E * 2 + B_E * 2;

    extern __shared__ __align__(16) char smem[];
    const uint32_t sb = smem_u32(smem);

    const int tid  = threadIdx.x;
    const int lane = tid & 31;
    const int wid  = tid >> 5;
    const int wm = (wid & 1) * 64;
    const int wn = (wid >> 1) * 64;
    const int mbase = blockIdx.y * 128;
    const int nbase = blockIdx.x * 256;
    const int kbeg  = blockIdx.z * kchunk;
    const int niter = kchunk >> 5;

    float acc[4][8][4];
#pragma unroll
    for (int i = 0; i < 4; i++)
#pragma unroll
        for (int j = 0; j < 8; j++)
#pragma unroll
            for (int f = 0; f < 4; f++) acc[i][j][f] = 0.f;

    auto issue = [&](int st, int k0) {
        const uint32_t s0 = sb + st * STAGE_B;
#pragma unroll
        for (int i = 0; i < 2; i++) {              // A: 512 chunks / operand
            const int q = tid + i * 256;
            const int row = q >> 2, c16 = q & 3;
            const size_t ga = (size_t)(mbase + row) * lda + k0 + c16 * 8;
            const uint32_t so = (uint32_t)(row * A_LD + c16 * 8) * 2;
            cpa16(s0 + so, Ah + ga);
            cpa16(s0 + OFS_AL + so, Al + ga);
        }
#pragma unroll
        for (int i = 0; i < 4; i++) {              // B: 1024 chunks / operand
            const int q = tid + i * 256;
            const int kr = q >> 5, c16 = q & 31;
            const size_t gb = (size_t)(k0 + kr) * ldb + nbase + c16 * 8;
            const uint32_t so = (uint32_t)(kr * B_LDW + c16 * 8) * 2;
            cpa16(s0 + OFS_BH + so, Bh + gb);
            cpa16(s0 + OFS_BL + so, Bl + gb);
        }
    };

    issue(0, kbeg);
    cpa_commit();

    for (int c = 0; c < niter; ++c) {
        if (c + 1 < niter) {
            issue((c + 1) & 1, kbeg + (c + 1) * 32);
            cpa_commit();
            cpa_wait1();
        } else {
            cpa_wait0();
        }
        __syncthreads();

        const uint32_t s0 = sb + (c & 1) * STAGE_B;
#pragma unroll
        for (int ks = 0; ks < 32; ks += 16) {
            // B fragments: 64 cols hi + lo (kept in regs across mt loop)
            uint32_t Bf[8][2], Blf[8][2];
#pragma unroll
            for (int g = 0; g < 4; g++) {
                const uint32_t off = (uint32_t)((ks + (lane & 15)) * B_LDW
                                                + wn + g * 16 + (lane >> 4) * 8) * 2;
                ldmT(Bf[2*g][0], Bf[2*g][1], Bf[2*g+1][0], Bf[2*g+1][1], s0 + OFS_BH + off);
                ldmT(Blf[2*g][0], Blf[2*g][1], Blf[2*g+1][0], Blf[2*g+1][1], s0 + OFS_BL + off);
            }
#pragma unroll
            for (int mt = 0; mt < 4; mt++) {
                uint32_t Af[4], Alf[4];
                const uint32_t offA = (uint32_t)((wm + mt * 16 + (lane & 15)) * A_LD
                                                 + ks + (lane >> 4) * 8) * 2;
                ldmA(Af,  s0 + offA);
                ldmA(Alf, s0 + OFS_AL + offA);
#pragma unroll
                for (int nt = 0; nt < 8; nt++) {
                    mma16816(acc[mt][nt], Af,  Bf[nt]);
                    mma16816(acc[mt][nt], Alf, Bf[nt]);
                    mma16816(acc[mt][nt], Af,  Blf[nt]);
                }
            }
        }
        __syncthreads();
    }

    float* Cb = Cf + (size_t)blockIdx.z * cslice;
    const int tr = lane >> 2, tc = (lane & 3) * 2;
#pragma unroll
    for (int mt = 0; mt < 4; mt++) {
#pragma unroll
        for (int nt = 0; nt < 8; nt++) {
#pragma unroll
            for (int half = 0; half < 2; half++) {
                const int row = mbase + wm + mt * 16 + tr + half * 8;
                const int col = nbase + wn + nt * 8 + tc;
                float2 v = make_float2(acc[mt][nt][half * 2], acc[mt][nt][half * 2 + 1]);
                *(float2*)(Cb + (size_t)row * ldc + col) = v;
            }
        }
    }
}

// ---------------------------------------------------------------------------
// gemm2 (round-8): 512 threads, 16 warps (4m x 4n), warp 32x32 — mixer GEMMs
// ---------------------------------------------------------------------------
template<int MTILES, int EPI>
__global__ void __launch_bounds__(512, 2)
gemm2(const __nv_bfloat16* __restrict__ Ah, const __nv_bfloat16* __restrict__ Al,
      const __nv_bfloat16* __restrict__ Bh, const __nv_bfloat16* __restrict__ Bl,
      float* __restrict__ Cf, __nv_bfloat16* __restrict__ Ch, __nv_bfloat16* __restrict__ Cl,
      int lda, int ldb, int ldc, int kchunk, int cslice)
{
    constexpr int BM = MTILES * 64;
    constexpr int A_E = BM * A_LD;
    constexpr int B_E = 32 * B_LD;
    constexpr int STAGE_B = (2 * A_E + 2 * B_E) * 2;
    constexpr int OFS_AL = A_E * 2;
    constexpr int OFS_BH = 2 * A_E * 2;
    constexpr int OFS_BL = 2 * A_E * 2 + B_E * 2;

    extern __shared__ __align__(16) char smem[];
    const uint32_t sb = smem_u32(smem);

    const int tid  = threadIdx.x;
    const int lane = tid & 31;
    const int wid  = tid >> 5;
    const int wm = (wid >> 2) * (MTILES * 16);
    const int wn = (wid & 3) * 32;
    const int mbase = blockIdx.y * BM;
    const int nbase = blockIdx.x * 128;
    const int kbeg  = blockIdx.z * kchunk;
    const int niter = kchunk >> 5;

    float acc[MTILES][4][4];
#pragma unroll
    for (int i = 0; i < MTILES; i++)
#pragma unroll
        for (int j = 0; j < 4; j++)
#pragma unroll
            for (int f = 0; f < 4; f++) acc[i][j][f] = 0.f;

    auto issue = [&](int st, int k0) {
        const uint32_t s0 = sb + st * STAGE_B;
        if (tid < BM * 4) {
            const int row = tid >> 2, c16 = tid & 3;
            const size_t ga = (size_t)(mbase + row) * lda + k0 + c16 * 8;
            const uint32_t so = (uint32_t)(row * A_LD + c16 * 8) * 2;
            cpa16(s0 + so, Ah + ga);
            cpa16(s0 + OFS_AL + so, Al + ga);
        }
        {
            const int kr = tid >> 4, c16 = tid & 15;
            const size_t gb = (size_t)(k0 + kr) * ldb + nbase + c16 * 8;
            const uint32_t so = (uint32_t)(kr * B_LD + c16 * 8) * 2;
            cpa16(s0 + OFS_BH + so, Bh + gb);
            cpa16(s0 + OFS_BL + so, Bl + gb);
        }
    };

    issue(0, kbeg);
    cpa_commit();

    for (int c = 0; c < niter; ++c) {
        if (c + 1 < niter) {
            issue((c + 1) & 1, kbeg + (c + 1) * 32);
            cpa_commit();
            cpa_wait1();
        } else {
            cpa_wait0();
        }
        __syncthreads();

        const uint32_t s0 = sb + (c & 1) * STAGE_B;
#pragma unroll
        for (int ks = 0; ks < 32; ks += 16) {
            uint32_t Bf[4][2], Blf[4][2];
#pragma unroll
            for (int g = 0; g < 2; g++) {
                const uint32_t off = (uint32_t)((ks + (lane & 15)) * B_LD
                                                + wn + g * 16 + (lane >> 4) * 8) * 2;
                ldmT(Bf[2*g][0], Bf[2*g][1], Bf[2*g+1][0], Bf[2*g+1][1], s0 + OFS_BH + off);
                ldmT(Blf[2*g][0], Blf[2*g][1], Blf[2*g+1][0], Blf[2*g+1][1], s0 + OFS_BL + off);
            }
#pragma unroll
            for (int mt = 0; mt < MTILES; mt++) {
                uint32_t Af[4], Alf[4];
                const uint32_t offA = (uint32_t)((wm + mt * 16 + (lane & 15)) * A_LD
                                                 + ks + (lane >> 4) * 8) * 2;
                ldmA(Af,  s0 + offA);
                ldmA(Alf, s0 + OFS_AL + offA);
#pragma unroll
                for (int nt = 0; nt < 4; nt++) {
                    mma16816(acc[mt][nt], Af,  Bf[nt]);
                    mma16816(acc[mt][nt], Alf, Bf[nt]);
                    mma16816(acc[mt][nt], Af,  Blf[nt]);
                }
            }
        }
        __syncthreads();
    }

    float* Cb = (EPI == 0) ? (Cf + (size_t)blockIdx.z * cslice) : Cf;
    const int tr = lane >> 2, tc = (lane & 3) * 2;
#pragma unroll
    for (int mt = 0; mt < MTILES; mt++) {
#pragma unroll
        for (int nt = 0; nt < 4; nt++) {
#pragma unroll
            for (int half = 0; half < 2; half++) {
                const int row = mbase + wm + mt * 16 + tr + half * 8;
                const int col = nbase + wn + nt * 8 + tc;
                float2 v = make_float2(acc[mt][nt][half * 2], acc[mt][nt][half * 2 + 1]);
                if (EPI == 0) {
                    *(float2*)(Cb + (size_t)row * ldc + col) = v;
                } else if (EPI == 1) {
                    v.x = silu_f(v.x); v.y = silu_f(v.y);
                    uint32_t hp, lp;
                    split2(v.x, v.y, hp, lp);
                    *(uint32_t*)(Ch + (size_t)row * ldc + col) = hp;
                    *(uint32_t*)(Cl + (size_t)row * ldc + col) = lp;
                } else {
                    float* p = Cb + (size_t)row * ldc + col;
                    float2 o = *(float2*)p;
                    v.x += o.x; v.y += o.y;
                    *(float2*)p = v;
                    uint32_t hp, lp;
                    split2(v.x, v.y, hp, lp);
                    *(uint32_t*)(Ch + (size_t)row * ldc + col) = hp;
                    *(uint32_t*)(Cl + (size_t)row * ldc + col) = lp;
                }
            }
        }
    }
}

// ---------------------------------------------------------------------------
// fp32 -> bf16 hi/lo split
// ---------------------------------------------------------------------------
__global__ void split_k(const float* __restrict__ src,
                        __nv_bfloat16* __restrict__ hi, __nv_bfloat16* __restrict__ lo, int n4)
{
    const int i = blockIdx.x * blockDim.x + threadIdx.x;
    if (i >= n4) return;
    const float4 v = ((const float4*)src)[i];
    uint32_t h0, l0, h1, l1;
    split2(v.x, v.y, h0, l0);
    split2(v.z, v.w, h1, l1);
    ((uint2*)hi)[i] = make_uint2(h0, h1);
    ((uint2*)lo)[i] = make_uint2(l0, l1);
}

// ---------------------------------------------------------------------------
// Scan kernels
// ---------------------------------------------------------------------------
__global__ void scan_carry_k(const float* __restrict__ ug, const float* __restrict__ Avec,
                             float* __restrict__ carry)
{
    const int idx = blockIdx.x * blockDim.x + threadIdx.x;
    const int c = idx & (INNER - 1);
    const int gch = idx >> 10;
    const float a = Avec[c];
    const float* up = ug + (size_t)gch * SEGLEN * (2 * INNER) + c;
    float hv = 0.f;
#pragma unroll 8
    for (int t = 0; t < SEGLEN; t++)
        hv = fmaf(a, hv, up[(size_t)t * (2 * INNER)]);
    carry[idx] = hv;
}

__global__ void combine_k(const float* __restrict__ carry, const float* __restrict__ Avec,
                          float* __restrict__ sin_)
{
    const int idx = blockIdx.x * blockDim.x + threadIdx.x;
    const int c = idx & (INNER - 1);
    const int q = idx >> 10;
    const float a = Avec[c];
    float a128 = a;
#pragma unroll
    for (int i = 0; i < 7; i++) a128 *= a128;
    float s = 0.f;
    for (int k = 0; k < NCH; k++) {
        const size_t o = (size_t)(q * NCH + k) * INNER + c;
        sin_[o] = s;
        s = fmaf(a128, s, carry[o]);
    }
}

__global__ void scan_final_gate_k(const float* __restrict__ ug, const float* __restrict__ Avec,
                                  const float* __restrict__ sin_, float* __restrict__ hout,
                                  __nv_bfloat16* __restrict__ ph, __nv_bfloat16* __restrict__ pl)
{
    const int idx = blockIdx.x * blockDim.x + threadIdx.x;
    const int c = idx & (INNER - 1);
    const int gch = idx >> 10;
    const float a = Avec[c];
    const float* up = ug + (size_t)gch * SEGLEN * (2 * INNER) + c;
    const float* gp = up + INNER;
    __nv_bfloat16* php = ph + (size_t)gch * SEGLEN * INNER + c;
    __nv_bfloat16* plp = pl + (size_t)gch * SEGLEN * INNER + c;
    float* hp = hout ? hout + (size_t)gch * SEGLEN * INNER + c : nullptr;
    float hv = sin_[idx];
#pragma unroll 4
    for (int t = 0; t < SEGLEN; t++) {
        hv = fmaf(a, hv, up[(size_t)t * (2 * INNER)]);
        if (hp) hp[(size_t)t * INNER] = hv;
        const float p = silu_f(gp[(size_t)t * (2 * INNER)]) * hv;
        const __nv_bfloat16 hi = __float2bfloat16(p);
        const __nv_bfloat16 lo = __float2bfloat16(p - __bfloat162float(hi));
        php[(size_t)t * INNER] = hi;
        plp[(size_t)t * INNER] = lo;
    }
}

// ---------------------------------------------------------------------------
// Small kernels
// ---------------------------------------------------------------------------
__global__ void compute_starts_k(const int* __restrict__ seg, int* __restrict__ starts,
                                 int* __restrict__ ends)
{
    int b = threadIdx.x;
    if (b >= Bsz) return;
    int cnt = 0;
    for (int t = 0; t < Lseq && cnt < NSEG; t++)
        if (seg[b * Lseq + t] != 0) starts[b * NSEG + cnt++] = t;
    while (cnt < NSEG) { starts[b * NSEG + cnt] = 0; cnt++; }
    for (int i = 0; i < NSEG - 1; i++) ends[b * NSEG + i] = starts[b * NSEG + i + 1];
    ends[b * NSEG + NSEG - 1] = Lseq;
}

__global__ void gather_correct_k(const int* __restrict__ ids, const float* __restrict__ E,
                                 float* __restrict__ x,
                                 __nv_bfloat16* __restrict__ xh, __nv_bfloat16* __restrict__ xl)
{
    const int row = blockIdx.x;
    const int id = ids[row];
    const float4 v = ((const float4*)(E + (size_t)id * Dm))[threadIdx.x];
    ((float4*)(x + (size_t)row * Dm))[threadIdx.x] = v;
    uint32_t h0, l0, h1, l1;
    split2(v.x, v.y, h0, l0);
    split2(v.z, v.w, h1, l1);
    ((uint2*)(xh + (size_t)row * Dm))[threadIdx.x] = make_uint2(h0, h1);
    ((uint2*)(xl + (size_t)row * Dm))[threadIdx.x] = make_uint2(l0, l1);
}

__global__ void save_state_k(const float* __restrict__ h, float* __restrict__ st,
                             const int* __restrict__ starts)
{
    const int r = blockIdx.x;
    const int c = threadIdx.x;
    const int b = r >> 3;
    const int s = starts[r];
    st[(size_t)r * INNER + c] = (s > 0) ? h[((size_t)b * Lseq + (s - 1)) * INNER + c] : 0.f;
}

__global__ void build_xs_k(const float* __restrict__ part, float* __restrict__ xs,
                           __nv_bfloat16* __restrict__ xsh, __nv_bfloat16* __restrict__ xsl,
                           const int* __restrict__ starts, const int* __restrict__ ends)
{
    const int r = blockIdx.x;
    const int q = r >> 7;
    const int t = r & (SEGLEN - 1);
    const int b = q >> 3;
    const int s = starts[q], e = ends[q];
    const int pos = s + t;
    float4 v = make_float4(0.f, 0.f, 0.f, 0.f);
    if (pos < e && pos < Lseq) {
        const size_t base = ((size_t)b * Lseq + pos) * Dm;
#pragma unroll
        for (int p = 0; p < DEC_SK; p++) {
            const float4 w = ((const float4*)(part + (size_t)p * NROWS * Dm + base))[threadIdx.x];
            v.x += w.x; v.y += w.y; v.z += w.z; v.w += w.w;
        }
    }
    ((float4*)(xs + (size_t)r * Dm))[threadIdx.x] = v;
    uint32_t h0, l0, h1, l1;
    split2(v.x, v.y, h0, l0);
    split2(v.z, v.w, h1, l1);
    ((uint2*)(xsh + (size_t)r * Dm))[threadIdx.x] = make_uint2(h0, h1);
    ((uint2*)(xsl + (size_t)r * Dm))[threadIdx.x] = make_uint2(l0, l1);
}

__global__ void extract_last_k(const float* __restrict__ xs, float* __restrict__ last,
                               const int* __restrict__ starts, const int* __restrict__ ends)
{
    const int q = blockIdx.x;
    int len = ends[q] - starts[q];
    if (len > SEGLEN) len = SEGLEN;
    if (len < 1) len = 1;
    const float4* s = (const float4*)(xs + ((size_t)q * SEGLEN + (len - 1)) * Dm);
    float4* d = (float4*)(last + (size_t)q * Dm);
    d[threadIdx.x] = s[threadIdx.x];
}

__global__ void head_k(const float* __restrict__ last,
                       const float* __restrict__ muW, const float* __restrict__ mub,
                       const float* __restrict__ lvW, const float* __restrict__ lvb,
                       float* __restrict__ out)
{
    const int o = blockIdx.x * blockDim.x + threadIdx.x;
    const int which = o >> 13;
    const int rem = o & 8191;
    const int r = rem >> 9, d = rem & 511;
    const float* W = which ? lvW : muW;
    const float* bias = which ? lvb : mub;
    const float* lr = last + (size_t)r * Dm;
    float acc = bias[d];
#pragma unroll 8
    for (int k = 0; k < Dm; k++) acc = fmaf(lr[k], W[(size_t)k * Dm + d], acc);
    out[o] = acc;
}

// ---------------------------------------------------------------------------
// Orchestration (my launch #3 = dec GEMM; ncu window offset ~2)
// ---------------------------------------------------------------------------
extern "C" void kernel_launch(void* const* d_in, const int* in_sizes, int n_in,
                              void* d_out, int out_size)
{
    const float* decoder_output = (const float*)d_in[0];
    const int*   input_ids      = (const int*)  d_in[1];
    const int*   seg_idx        = (const int*)  d_in[2];
    const float* E              = (const float*)d_in[3];
    const float* Aparam         = (const float*)d_in[4];
    const float* Win            = (const float*)d_in[5];
    const float* Wout           = (const float*)d_in[6];
    const float* Wm1            = (const float*)d_in[7];
    const float* Wm2            = (const float*)d_in[8];
    const float* muW            = (const float*)d_in[9];
    const float* mub            = (const float*)d_in[10];
    const float* lvW            = (const float*)d_in[11];
    const float* lvb            = (const float*)d_in[12];
    float* out = (float*)d_out;

    float *x, *decpart, *ug, *h, *xs, *state, *carry, *sins, *last;
    int *starts, *ends;
    __nv_bfloat16 *decAh, *decAl, *xh, *xl, *ph, *pl, *mlph, *mlpl;
    __nv_bfloat16 *eh, *el, *winh, *winl, *wouth, *woutl, *wm1h, *wm1l, *wm2h, *wm2l;
    cudaGetSymbolAddress((void**)&x,       g_x);
    cudaGetSymbolAddress((void**)&decpart, g_decpart);
    cudaGetSymbolAddress((void**)&ug,      g_ug);
    cudaGetSymbolAddress((void**)&h,       g_h);
    cudaGetSymbolAddress((void**)&xs,      g_xs);
    cudaGetSymbolAddress((void**)&state,   g_state);
    cudaGetSymbolAddress((void**)&carry,   g_carry);
    cudaGetSymbolAddress((void**)&sins,    g_sin);
    cudaGetSymbolAddress((void**)&last,    g_last);
    cudaGetSymbolAddress((void**)&starts,  g_starts);
    cudaGetSymbolAddress((void**)&ends,    g_ends);
    cudaGetSymbolAddress((void**)&decAh,   g_decAh);
    cudaGetSymbolAddress((void**)&decAl,   g_decAl);
    cudaGetSymbolAddress((void**)&xh,      g_xh);
    cudaGetSymbolAddress((void**)&xl,      g_xl);
    cudaGetSymbolAddress((void**)&ph,      g_ph);
    cudaGetSymbolAddress((void**)&pl,      g_pl);
    cudaGetSymbolAddress((void**)&mlph,    g_mlph);
    cudaGetSymbolAddress((void**)&mlpl,    g_mlpl);
    cudaGetSymbolAddress((void**)&eh,      g_Eh);
    cudaGetSymbolAddress((void**)&el,      g_El);
    cudaGetSymbolAddress((void**)&winh,    g_WinH);
    cudaGetSymbolAddress((void**)&winl,    g_WinL);
    cudaGetSymbolAddress((void**)&wouth,   g_WoutH);
    cudaGetSymbolAddress((void**)&woutl,   g_WoutL);
    cudaGetSymbolAddress((void**)&wm1h,    g_Wm1H);
    cudaGetSymbolAddress((void**)&wm1l,    g_Wm1L);
    cudaGetSymbolAddress((void**)&wm2h,    g_Wm2H);
    cudaGetSymbolAddress((void**)&wm2l,    g_Wm2L);

    constexpr int SMEM_BIG = (2 * (128 * A_LD) + 2 * (32 * B_LDW)) * 2 * 2;  // 108,544 B
    constexpr int SMEM2 = (2 * 128 * A_LD + 2 * 32 * B_LD) * 2 * 2;
    constexpr int SMEM1 = (2 * 64  * A_LD + 2 * 32 * B_LD) * 2 * 2;
    cudaFuncSetAttribute(gemm_big, cudaFuncAttributeMaxDynamicSharedMemorySize, SMEM_BIG);
    cudaFuncSetAttribute(gemm2<2, 0>, cudaFuncAttributeMaxDynamicSharedMemorySize, SMEM2);
    cudaFuncSetAttribute(gemm2<2, 1>, cudaFuncAttributeMaxDynamicSharedMemorySize, SMEM2);
    cudaFuncSetAttribute(gemm2<1, 2>, cudaFuncAttributeMaxDynamicSharedMemorySize, SMEM1);

    auto split = [&](const float* s, __nv_bfloat16* hh, __nv_bfloat16* ll, size_t n) {
        split_k<<<(int)((n / 4 + 255) / 256), 256>>>(s, hh, ll, (int)(n / 4));
    };

    // #0..#2
    compute_starts_k<<<1, 32>>>(seg_idx, starts, ends);
    split(E, eh, el, (size_t)VOC * Dm);
    split(decoder_output, decAh, decAl, (size_t)NROWS * VOC);

    // #3: dec = decoder_output @ E  (split-K=8, big tiles) — ncu capture target
    gemm_big<<<dim3(Dm / 256, NROWS / 128, DEC_SK), 256, SMEM_BIG>>>(
        decAh, decAl, eh, el, decpart, VOC, Dm, Dm, DEC_KSLICE, NROWS * Dm);

    gather_correct_k<<<NROWS, 128>>>(input_ids, E, x, xh, xl);
    split(Win,  winh,  winl,  (size_t)NLAY * Dm * 2 * INNER);
    split(Wout, wouth, woutl, (size_t)NLAY * INNER * Dm);
    split(Wm1,  wm1h,  wm1l,  (size_t)NLAY * Dm * MLPD);
    split(Wm2,  wm2h,  wm2l,  (size_t)NLAY * MLPD * Dm);

    // -------- Base pass --------
    for (int l = 0; l < NLAY; l++) {
        const size_t oWin  = (size_t)l * Dm * 2 * INNER;
        const size_t oWout = (size_t)l * INNER * Dm;
        const size_t oWm1  = (size_t)l * Dm * MLPD;
        const size_t oWm2  = (size_t)l * MLPD * Dm;
        const float* Al    = Aparam + (size_t)l * INNER;
        float* stl = state + (size_t)l * Bsz * NSEG * INNER;

        gemm2<2, 0><<<dim3((2 * INNER) / 128, NROWS / 128, 1), 512, SMEM2>>>(
            xh, xl, winh + oWin, winl + oWin, ug, nullptr, nullptr,
            Dm, 2 * INNER, 2 * INNER, Dm, 0);
        scan_carry_k<<<(Bsz * NCH * INNER) / 256, 256>>>(ug, Al, carry);
        combine_k<<<(Bsz * INNER) / 256, 256>>>(carry, Al, sins);
        scan_final_gate_k<<<(Bsz * NCH * INNER) / 256, 256>>>(ug, Al, sins, h, ph, pl);
        save_state_k<<<Bsz * NSEG, INNER>>>(h, stl, starts);
        gemm2<1, 2><<<dim3(Dm / 128, NROWS / 64, 1), 512, SMEM1>>>(
            ph, pl, wouth + oWout, woutl + oWout, x, xh, xl,
            INNER, Dm, Dm, INNER, 0);
        gemm2<2, 1><<<dim3(MLPD / 128, NROWS / 128, 1), 512, SMEM2>>>(
            xh, xl, wm1h + oWm1, wm1l + oWm1, nullptr, mlph, mlpl,
            Dm, MLPD, MLPD, Dm, 0);
        gemm2<1, 2><<<dim3(Dm / 128, NROWS / 64, 1), 512, SMEM1>>>(
            mlph, mlpl, wm2h + oWm2, wm2l + oWm2, x, xh, xl,
            MLPD, Dm, Dm, MLPD, 0);
    }

    // -------- Segment pass --------
    build_xs_k<<<NROWS, 128>>>(decpart, xs, xh, xl, starts, ends);
    for (int l = 0; l < NLAY; l++) {
        const size_t oWin  = (size_t)l * Dm * 2 * INNER;
        const size_t oWout = (size_t)l * INNER * Dm;
        const size_t oWm1  = (size_t)l * Dm * MLPD;
        const size_t oWm2  = (size_t)l * MLPD * Dm;
        const float* Al    = Aparam + (size_t)l * INNER;
        const float* stl = state + (size_t)l * Bsz * NSEG * INNER;

        gemm2<2, 0><<<dim3((2 * INNER) / 128, NROWS / 128, 1), 512, SMEM2>>>(
            xh, xl, winh + oWin, winl + oWin, ug, nullptr, nullptr,
            Dm, 2 * INNER, 2 * INNER, Dm, 0);
        scan_final_gate_k<<<(Bsz * NSEG * INNER) / 256, 256>>>(ug, Al, stl, nullptr, ph, pl);
        gemm2<1, 2><<<dim3(Dm / 128, NROWS / 64, 1), 512, SMEM1>>>(
            ph, pl, wouth + oWout, woutl + oWout, xs, xh, xl,
            INNER, Dm, Dm, INNER, 0);
        gemm2<2, 1><<<dim3(MLPD / 128, NROWS / 128, 1), 512, SMEM2>>>(
            xh, xl, wm1h + oWm1, wm1l + oWm1, nullptr, mlph, mlpl,
            Dm, MLPD, MLPD, Dm, 0);
        gemm2<1, 2><<<dim3(Dm / 128, NROWS / 64, 1), 512, SMEM1>>>(
            mlph, mlpl, wm2h + oWm2, wm2l + oWm2, xs, xh, xl,
            MLPD, Dm, Dm, MLPD, 0);
    }

    extract_last_k<<<Bsz * NSEG, 128>>>(xs, last, starts, ends);
    head_k<<<(2 * Bsz * NSEG * Dm) / 256, 256>>>(last, muW, mub, lvW, lvb, out);
}

// round 10
// speedup vs baseline: 1.6181x; 1.0378x over previous
#include <cuda_runtime.h>
#include <cuda_bf16.h>
#include <cstdint>

// ---------------------------------------------------------------------------
// Problem constants
// ---------------------------------------------------------------------------
#define Bsz    2
#define Lseq   1024
#define VOC    32000
#define Dm     512
#define NLAY   2
#define INNER  1024
#define MLPD   2048
#define NSEG   8
#define SEGLEN 128
#define NROWS  (Bsz*Lseq)      // 2048 base rows
#define XROWS  (2*NROWS)       // 4096 = base + segment rows (merged passes)
#define DEC_SK 8
#define DEC_KSLICE (VOC/DEC_SK)   // 4000
#define NCH    8

// ---------------------------------------------------------------------------
// Scratch
// ---------------------------------------------------------------------------
__device__ float g_x      [XROWS * Dm];          // rows 0..2047 base, 2048.. segments
__device__ float g_decpart[DEC_SK * NROWS * Dm];
__device__ float g_ug     [XROWS * 2 * INNER];
__device__ float g_h      [NROWS * INNER];       // base h (for checkpoints)
__device__ float g_state  [NLAY * Bsz * NSEG * INNER];
__device__ float g_carry  [Bsz * NCH * INNER];
__device__ float g_sin    [Bsz * NCH * INNER];
__device__ float g_last   [Bsz * NSEG * Dm];
__device__ int   g_starts [Bsz * NSEG];
__device__ int   g_ends   [Bsz * NSEG];
// bf16 hi/lo operands
__device__ __nv_bfloat16 g_decAh[NROWS * VOC];
__device__ __nv_bfloat16 g_decAl[NROWS * VOC];
__device__ __nv_bfloat16 g_xh   [XROWS * Dm];
__device__ __nv_bfloat16 g_xl   [XROWS * Dm];
__device__ __nv_bfloat16 g_ph   [XROWS * INNER];
__device__ __nv_bfloat16 g_pl   [XROWS * INNER];
__device__ __nv_bfloat16 g_mlph [XROWS * MLPD];
__device__ __nv_bfloat16 g_mlpl [XROWS * MLPD];
__device__ __nv_bfloat16 g_Eh   [VOC * Dm];
__device__ __nv_bfloat16 g_El   [VOC * Dm];
__device__ __nv_bfloat16 g_WinH [NLAY * Dm * 2 * INNER];
__device__ __nv_bfloat16 g_WinL [NLAY * Dm * 2 * INNER];
__device__ __nv_bfloat16 g_WoutH[NLAY * INNER * Dm];
__device__ __nv_bfloat16 g_WoutL[NLAY * INNER * Dm];
__device__ __nv_bfloat16 g_Wm1H [NLAY * Dm * MLPD];
__device__ __nv_bfloat16 g_Wm1L [NLAY * Dm * MLPD];
__device__ __nv_bfloat16 g_Wm2H [NLAY * MLPD * Dm];
__device__ __nv_bfloat16 g_Wm2L [NLAY * MLPD * Dm];

__device__ __forceinline__ float silu_f(float v) { return v * (1.f / (1.f + __expf(-v))); }

__device__ __forceinline__ void split2(float a, float b, uint32_t& hp, uint32_t& lp) {
    __nv_bfloat16 ah = __float2bfloat16(a), bh = __float2bfloat16(b);
    float ar = a - __bfloat162float(ah), br = b - __bfloat162float(bh);
    __nv_bfloat16 al = __float2bfloat16(ar), bl = __float2bfloat16(br);
    hp = (uint32_t)__bfloat16_as_ushort(ah) | ((uint32_t)__bfloat16_as_ushort(bh) << 16);
    lp = (uint32_t)__bfloat16_as_ushort(al) | ((uint32_t)__bfloat16_as_ushort(bl) << 16);
}

// ---------------------------------------------------------------------------
// primitives
// ---------------------------------------------------------------------------
__device__ __forceinline__ uint32_t smem_u32(const void* p) {
    return (uint32_t)__cvta_generic_to_shared(p);
}
__device__ __forceinline__ void ldmA(uint32_t* r, uint32_t addr) {
    asm volatile("ldmatrix.sync.aligned.m8n8.x4.shared.b16 {%0,%1,%2,%3}, [%4];"
                 : "=r"(r[0]), "=r"(r[1]), "=r"(r[2]), "=r"(r[3]) : "r"(addr));
}
__device__ __forceinline__ void ldmT(uint32_t& r0, uint32_t& r1, uint32_t& r2, uint32_t& r3,
                                     uint32_t addr) {
    asm volatile("ldmatrix.sync.aligned.m8n8.x4.trans.shared.b16 {%0,%1,%2,%3}, [%4];"
                 : "=r"(r0), "=r"(r1), "=r"(r2), "=r"(r3) : "r"(addr));
}
__device__ __forceinline__ void mma16816(float* c, const uint32_t* a, const uint32_t* b) {
    asm volatile("mma.sync.aligned.m16n8k16.row.col.f32.bf16.bf16.f32 "
                 "{%0,%1,%2,%3}, {%4,%5,%6,%7}, {%8,%9}, {%0,%1,%2,%3};"
                 : "+f"(c[0]), "+f"(c[1]), "+f"(c[2]), "+f"(c[3])
                 : "r"(a[0]), "r"(a[1]), "r"(a[2]), "r"(a[3]), "r"(b[0]), "r"(b[1]));
}
__device__ __forceinline__ void cpa16(uint32_t s, const void* g) {
    asm volatile("cp.async.cg.shared.global [%0], [%1], 16;" :: "r"(s), "l"(g));
}
__device__ __forceinline__ void cpa_commit() { asm volatile("cp.async.commit_group;"); }
__device__ __forceinline__ void cpa_wait1()  { asm volatile("cp.async.wait_group 1;"); }
__device__ __forceinline__ void cpa_wait0()  { asm volatile("cp.async.wait_group 0;"); }

#define A_LD 40
#define B_LD 136
#define B_LDW 264

// ---------------------------------------------------------------------------
// gemm_big (dec): CTA 128x256x32, 8 warps (2m x 4n), warp 64x64.
// TERM-MAJOR mma ordering: all A/B frags hoisted, 32 independent mmas between
// same-accumulator reuses (breaks the HMMA RAW chain).
// ---------------------------------------------------------------------------
__global__ void __launch_bounds__(256, 1)
gemm_big(const __nv_bfloat16* __restrict__ Ah, const __nv_bfloat16* __restrict__ Al,
         const __nv_bfloat16* __restrict__ Bh, const __nv_bfloat16* __restrict__ Bl,
         float* __restrict__ Cf, int lda, int ldb, int ldc, int kchunk, int cslice)
{
    constexpr int A_E = 128 * A_LD;
    constexpr int B_E = 32 * B_LDW;
    constexpr int STAGE_B = (2 * A_E + 2 * B_E) * 2;
    constexpr int OFS_AL = A_E * 2;
    constexpr int OFS_BH = 2 * A_E * 2;
    constexpr int OFS_BL = 2 * A_E * 2 + B_E * 2;

    extern __shared__ __align__(16) char smem[];
    const uint32_t sb = smem_u32(smem);

    const int tid  = threadIdx.x;
    const int lane = tid & 31;
    const int wid  = tid >> 5;
    const int wm = (wid & 1) * 64;
    const int wn = (wid >> 1) * 64;
    const int mbase = blockIdx.y * 128;
    const int nbase = blockIdx.x * 256;
    const int kbeg  = blockIdx.z * kchunk;
    const int niter = kchunk >> 5;

    float acc[4][8][4];
#pragma unroll
    for (int i = 0; i < 4; i++)
#pragma unroll
        for (int j = 0; j < 8; j++)
#pragma unroll
            for (int f = 0; f < 4; f++) acc[i][j][f] = 0.f;

    auto issue = [&](int st, int k0) {
        const uint32_t s0 = sb + st * STAGE_B;
#pragma unroll
        for (int i = 0; i < 2; i++) {
            const int q = tid + i * 256;
            const int row = q >> 2, c16 = q & 3;
            const size_t ga = (size_t)(mbase + row) * lda + k0 + c16 * 8;
            const uint32_t so = (uint32_t)(row * A_LD + c16 * 8) * 2;
            cpa16(s0 + so, Ah + ga);
            cpa16(s0 + OFS_AL + so, Al + ga);
        }
#pragma unroll
        for (int i = 0; i < 4; i++) {
            const int q = tid + i * 256;
            const int kr = q >> 5, c16 = q & 31;
            const size_t gb = (size_t)(k0 + kr) * ldb + nbase + c16 * 8;
            const uint32_t so = (uint32_t)(kr * B_LDW + c16 * 8) * 2;
            cpa16(s0 + OFS_BH + so, Bh + gb);
            cpa16(s0 + OFS_BL + so, Bl + gb);
        }
    };

    issue(0, kbeg);
    cpa_commit();

    for (int c = 0; c < niter; ++c) {
        if (c + 1 < niter) {
            issue((c + 1) & 1, kbeg + (c + 1) * 32);
            cpa_commit();
            cpa_wait1();
        } else {
            cpa_wait0();
        }
        __syncthreads();

        const uint32_t s0 = sb + (c & 1) * STAGE_B;
#pragma unroll
        for (int ks = 0; ks < 32; ks += 16) {
            uint32_t Bf[8][2], Blf[8][2];
#pragma unroll
            for (int g = 0; g < 4; g++) {
                const uint32_t off = (uint32_t)((ks + (lane & 15)) * B_LDW
                                                + wn + g * 16 + (lane >> 4) * 8) * 2;
                ldmT(Bf[2*g][0], Bf[2*g][1], Bf[2*g+1][0], Bf[2*g+1][1], s0 + OFS_BH + off);
                ldmT(Blf[2*g][0], Blf[2*g][1], Blf[2*g+1][0], Blf[2*g+1][1], s0 + OFS_BL + off);
            }
            uint32_t Af[4][4], Alf[4][4];
#pragma unroll
            for (int mt = 0; mt < 4; mt++) {
                const uint32_t offA = (uint32_t)((wm + mt * 16 + (lane & 15)) * A_LD
                                                 + ks + (lane >> 4) * 8) * 2;
                ldmA(Af[mt],  s0 + offA);
                ldmA(Alf[mt], s0 + OFS_AL + offA);
            }
            // term-major: 32 independent mmas between same-acc reuses
#pragma unroll
            for (int mt = 0; mt < 4; mt++)
#pragma unroll
                for (int nt = 0; nt < 8; nt++)
                    mma16816(acc[mt][nt], Af[mt], Bf[nt]);
#pragma unroll
            for (int mt = 0; mt < 4; mt++)
#pragma unroll
                for (int nt = 0; nt < 8; nt++)
                    mma16816(acc[mt][nt], Alf[mt], Bf[nt]);
#pragma unroll
            for (int mt = 0; mt < 4; mt++)
#pragma unroll
                for (int nt = 0; nt < 8; nt++)
                    mma16816(acc[mt][nt], Af[mt], Blf[nt]);
        }
        __syncthreads();
    }

    float* Cb = Cf + (size_t)blockIdx.z * cslice;
    const int tr = lane >> 2, tc = (lane & 3) * 2;
#pragma unroll
    for (int mt = 0; mt < 4; mt++) {
#pragma unroll
        for (int nt = 0; nt < 8; nt++) {
#pragma unroll
            for (int half = 0; half < 2; half++) {
                const int row = mbase + wm + mt * 16 + tr + half * 8;
                const int col = nbase + wn + nt * 8 + tc;
                float2 v = make_float2(acc[mt][nt][half * 2], acc[mt][nt][half * 2 + 1]);
                *(float2*)(Cb + (size_t)row * ldc + col) = v;
            }
        }
    }
}

// ---------------------------------------------------------------------------
// gemm2 (mixer): 512 threads, 16 warps (4m x 4n), warp 32x32.
// Term-major within each mt (same-acc distance 4).
// ---------------------------------------------------------------------------
template<int MTILES, int EPI>
__global__ void __launch_bounds__(512, 2)
gemm2(const __nv_bfloat16* __restrict__ Ah, const __nv_bfloat16* __restrict__ Al,
      const __nv_bfloat16* __restrict__ Bh, const __nv_bfloat16* __restrict__ Bl,
      float* __restrict__ Cf, __nv_bfloat16* __restrict__ Ch, __nv_bfloat16* __restrict__ Cl,
      int lda, int ldb, int ldc, int kchunk, int cslice)
{
    constexpr int BM = MTILES * 64;
    constexpr int A_E = BM * A_LD;
    constexpr int B_E = 32 * B_LD;
    constexpr int STAGE_B = (2 * A_E + 2 * B_E) * 2;
    constexpr int OFS_AL = A_E * 2;
    constexpr int OFS_BH = 2 * A_E * 2;
    constexpr int OFS_BL = 2 * A_E * 2 + B_E * 2;

    extern __shared__ __align__(16) char smem[];
    const uint32_t sb = smem_u32(smem);

    const int tid  = threadIdx.x;
    const int lane = tid & 31;
    const int wid  = tid >> 5;
    const int wm = (wid >> 2) * (MTILES * 16);
    const int wn = (wid & 3) * 32;
    const int mbase = blockIdx.y * BM;
    const int nbase = blockIdx.x * 128;
    const int kbeg  = blockIdx.z * kchunk;
    const int niter = kchunk >> 5;

    float acc[MTILES][4][4];
#pragma unroll
    for (int i = 0; i < MTILES; i++)
#pragma unroll
        for (int j = 0; j < 4; j++)
#pragma unroll
            for (int f = 0; f < 4; f++) acc[i][j][f] = 0.f;

    auto issue = [&](int st, int k0) {
        const uint32_t s0 = sb + st * STAGE_B;
        if (tid < BM * 4) {
            const int row = tid >> 2, c16 = tid & 3;
            const size_t ga = (size_t)(mbase + row) * lda + k0 + c16 * 8;
            const uint32_t so = (uint32_t)(row * A_LD + c16 * 8) * 2;
            cpa16(s0 + so, Ah + ga);
            cpa16(s0 + OFS_AL + so, Al + ga);
        }
        {
            const int kr = tid >> 4, c16 = tid & 15;
            const size_t gb = (size_t)(k0 + kr) * ldb + nbase + c16 * 8;
            const uint32_t so = (uint32_t)(kr * B_LD + c16 * 8) * 2;
            cpa16(s0 + OFS_BH + so, Bh + gb);
            cpa16(s0 + OFS_BL + so, Bl + gb);
        }
    };

    issue(0, kbeg);
    cpa_commit();

    for (int c = 0; c < niter; ++c) {
        if (c + 1 < niter) {
            issue((c + 1) & 1, kbeg + (c + 1) * 32);
            cpa_commit();
            cpa_wait1();
        } else {
            cpa_wait0();
        }
        __syncthreads();

        const uint32_t s0 = sb + (c & 1) * STAGE_B;
#pragma unroll
        for (int ks = 0; ks < 32; ks += 16) {
            uint32_t Bf[4][2], Blf[4][2];
#pragma unroll
            for (int g = 0; g < 2; g++) {
                const uint32_t off = (uint32_t)((ks + (lane & 15)) * B_LD
                                                + wn + g * 16 + (lane >> 4) * 8) * 2;
                ldmT(Bf[2*g][0], Bf[2*g][1], Bf[2*g+1][0], Bf[2*g+1][1], s0 + OFS_BH + off);
                ldmT(Blf[2*g][0], Blf[2*g][1], Blf[2*g+1][0], Blf[2*g+1][1], s0 + OFS_BL + off);
            }
#pragma unroll
            for (int mt = 0; mt < MTILES; mt++) {
                uint32_t Af[4], Alf[4];
                const uint32_t offA = (uint32_t)((wm + mt * 16 + (lane & 15)) * A_LD
                                                 + ks + (lane >> 4) * 8) * 2;
                ldmA(Af,  s0 + offA);
                ldmA(Alf, s0 + OFS_AL + offA);
                // term-major: same-acc distance 4
#pragma unroll
                for (int nt = 0; nt < 4; nt++) mma16816(acc[mt][nt], Af,  Bf[nt]);
#pragma unroll
                for (int nt = 0; nt < 4; nt++) mma16816(acc[mt][nt], Alf, Bf[nt]);
#pragma unroll
                for (int nt = 0; nt < 4; nt++) mma16816(acc[mt][nt], Af,  Blf[nt]);
            }
        }
        __syncthreads();
    }

    float* Cb = (EPI == 0) ? (Cf + (size_t)blockIdx.z * cslice) : Cf;
    const int tr = lane >> 2, tc = (lane & 3) * 2;
#pragma unroll
    for (int mt = 0; mt < MTILES; mt++) {
#pragma unroll
        for (int nt = 0; nt < 4; nt++) {
#pragma unroll
            for (int half = 0; half < 2; half++) {
                const int row = mbase + wm + mt * 16 + tr + half * 8;
                const int col = nbase + wn + nt * 8 + tc;
                float2 v = make_float2(acc[mt][nt][half * 2], acc[mt][nt][half * 2 + 1]);
                if (EPI == 0) {
                    *(float2*)(Cb + (size_t)row * ldc + col) = v;
                } else if (EPI == 1) {
                    v.x = silu_f(v.x); v.y = silu_f(v.y);
                    uint32_t hp, lp;
                    split2(v.x, v.y, hp, lp);
                    *(uint32_t*)(Ch + (size_t)row * ldc + col) = hp;
                    *(uint32_t*)(Cl + (size_t)row * ldc + col) = lp;
                } else {
                    float* p = Cb + (size_t)row * ldc + col;
                    float2 o = *(float2*)p;
                    v.x += o.x; v.y += o.y;
                    *(float2*)p = v;
                    uint32_t hp, lp;
                    split2(v.x, v.y, hp, lp);
                    *(uint32_t*)(Ch + (size_t)row * ldc + col) = hp;
                    *(uint32_t*)(Cl + (size_t)row * ldc + col) = lp;
                }
            }
        }
    }
}

// ---------------------------------------------------------------------------
// fp32 -> bf16 hi/lo split
// ---------------------------------------------------------------------------
__global__ void split_k(const float* __restrict__ src,
                        __nv_bfloat16* __restrict__ hi, __nv_bfloat16* __restrict__ lo, int n4)
{
    const int i = blockIdx.x * blockDim.x + threadIdx.x;
    if (i >= n4) return;
    const float4 v = ((const float4*)src)[i];
    uint32_t h0, l0, h1, l1;
    split2(v.x, v.y, h0, l0);
    split2(v.z, v.w, h1, l1);
    ((uint2*)hi)[i] = make_uint2(h0, h1);
    ((uint2*)lo)[i] = make_uint2(l0, l1);
}

// ---------------------------------------------------------------------------
// Scan kernels
// ---------------------------------------------------------------------------
__global__ void scan_carry_k(const float* __restrict__ ug, const float* __restrict__ Avec,
                             float* __restrict__ carry)
{
    const int idx = blockIdx.x * blockDim.x + threadIdx.x;
    const int c = idx & (INNER - 1);
    const int gch = idx >> 10;
    const float a = Avec[c];
    const float* up = ug + (size_t)gch * SEGLEN * (2 * INNER) + c;
    float hv = 0.f;
#pragma unroll 8
    for (int t = 0; t < SEGLEN; t++)
        hv = fmaf(a, hv, up[(size_t)t * (2 * INNER)]);
    carry[idx] = hv;
}

__global__ void combine_k(const float* __restrict__ carry, const float* __restrict__ Avec,
                          float* __restrict__ sin_)
{
    const int idx = blockIdx.x * blockDim.x + threadIdx.x;
    const int c = idx & (INNER - 1);
    const int q = idx >> 10;
    const float a = Avec[c];
    float a128 = a;
#pragma unroll
    for (int i = 0; i < 7; i++) a128 *= a128;
    float s = 0.f;
    for (int k = 0; k < NCH; k++) {
        const size_t o = (size_t)(q * NCH + k) * INNER + c;
        sin_[o] = s;
        s = fmaf(a128, s, carry[o]);
    }
}

__global__ void scan_final_gate_k(const float* __restrict__ ug, const float* __restrict__ Avec,
                                  const float* __restrict__ sin_, float* __restrict__ hout,
                                  __nv_bfloat16* __restrict__ ph, __nv_bfloat16* __restrict__ pl)
{
    const int idx = blockIdx.x * blockDim.x + threadIdx.x;
    const int c = idx & (INNER - 1);
    const int gch = idx >> 10;
    const float a = Avec[c];
    const float* up = ug + (size_t)gch * SEGLEN * (2 * INNER) + c;
    const float* gp = up + INNER;
    __nv_bfloat16* php = ph + (size_t)gch * SEGLEN * INNER + c;
    __nv_bfloat16* plp = pl + (size_t)gch * SEGLEN * INNER + c;
    float* hp = hout ? hout + (size_t)gch * SEGLEN * INNER + c : nullptr;
    float hv = sin_[idx];
#pragma unroll 4
    for (int t = 0; t < SEGLEN; t++) {
        hv = fmaf(a, hv, up[(size_t)t * (2 * INNER)]);
        if (hp) hp[(size_t)t * INNER] = hv;
        const float p = silu_f(gp[(size_t)t * (2 * INNER)]) * hv;
        const __nv_bfloat16 hi = __float2bfloat16(p);
        const __nv_bfloat16 lo = __float2bfloat16(p - __bfloat162float(hi));
        php[(size_t)t * INNER] = hi;
        plp[(size_t)t * INNER] = lo;
    }
}

// ---------------------------------------------------------------------------
// Small kernels
// ---------------------------------------------------------------------------
__global__ void compute_starts_k(const int* __restrict__ seg, int* __restrict__ starts,
                                 int* __restrict__ ends)
{
    int b = threadIdx.x;
    if (b >= Bsz) return;
    int cnt = 0;
    for (int t = 0; t < Lseq && cnt < NSEG; t++)
        if (seg[b * Lseq + t] != 0) starts[b * NSEG + cnt++] = t;
    while (cnt < NSEG) { starts[b * NSEG + cnt] = 0; cnt++; }
    for (int i = 0; i < NSEG - 1; i++) ends[b * NSEG + i] = starts[b * NSEG + i + 1];
    ends[b * NSEG + NSEG - 1] = Lseq;
}

__global__ void gather_correct_k(const int* __restrict__ ids, const float* __restrict__ E,
                                 float* __restrict__ x,
                                 __nv_bfloat16* __restrict__ xh, __nv_bfloat16* __restrict__ xl)
{
    const int row = blockIdx.x;
    const int id = ids[row];
    const float4 v = ((const float4*)(E + (size_t)id * Dm))[threadIdx.x];
    ((float4*)(x + (size_t)row * Dm))[threadIdx.x] = v;
    uint32_t h0, l0, h1, l1;
    split2(v.x, v.y, h0, l0);
    split2(v.z, v.w, h1, l1);
    ((uint2*)(xh + (size_t)row * Dm))[threadIdx.x] = make_uint2(h0, h1);
    ((uint2*)(xl + (size_t)row * Dm))[threadIdx.x] = make_uint2(l0, l1);
}

__global__ void save_state_k(const float* __restrict__ h, float* __restrict__ st,
                             const int* __restrict__ starts)
{
    const int r = blockIdx.x;
    const int c = threadIdx.x;
    const int b = r >> 3;
    const int s = starts[r];
    st[(size_t)r * INNER + c] = (s > 0) ? h[((size_t)b * Lseq + (s - 1)) * INNER + c] : 0.f;
}

__global__ void build_xs_k(const float* __restrict__ part, float* __restrict__ xs,
                           __nv_bfloat16* __restrict__ xsh, __nv_bfloat16* __restrict__ xsl,
                           const int* __restrict__ starts, const int* __restrict__ ends)
{
    const int r = blockIdx.x;
    const int q = r >> 7;
    const int t = r & (SEGLEN - 1);
    const int b = q >> 3;
    const int s = starts[q], e = ends[q];
    const int pos = s + t;
    float4 v = make_float4(0.f, 0.f, 0.f, 0.f);
    if (pos < e && pos < Lseq) {
        const size_t base = ((size_t)b * Lseq + pos) * Dm;
#pragma unroll
        for (int p = 0; p < DEC_SK; p++) {
            const float4 w = ((const float4*)(part + (size_t)p * NROWS * Dm + base))[threadIdx.x];
            v.x += w.x; v.y += w.y; v.z += w.z; v.w += w.w;
        }
    }
    ((float4*)(xs + (size_t)r * Dm))[threadIdx.x] = v;
    uint32_t h0, l0, h1, l1;
    split2(v.x, v.y, h0, l0);
    split2(v.z, v.w, h1, l1);
    ((uint2*)(xsh + (size_t)r * Dm))[threadIdx.x] = make_uint2(h0, h1);
    ((uint2*)(xsl + (size_t)r * Dm))[threadIdx.x] = make_uint2(l0, l1);
}

__global__ void extract_last_k(const float* __restrict__ xs, float* __restrict__ last,
                               const int* __restrict__ starts, const int* __restrict__ ends)
{
    const int q = blockIdx.x;
    int len = ends[q] - starts[q];
    if (len > SEGLEN) len = SEGLEN;
    if (len < 1) len = 1;
    const float4* s = (const float4*)(xs + ((size_t)q * SEGLEN + (len - 1)) * Dm);
    float4* d = (float4*)(last + (size_t)q * Dm);
    d[threadIdx.x] = s[threadIdx.x];
}

__global__ void head_k(const float* __restrict__ last,
                       const float* __restrict__ muW, const float* __restrict__ mub,
                       const float* __restrict__ lvW, const float* __restrict__ lvb,
                       float* __restrict__ out)
{
    const int o = blockIdx.x * blockDim.x + threadIdx.x;
    const int which = o >> 13;
    const int rem = o & 8191;
    const int r = rem >> 9, d = rem & 511;
    const float* W = which ? lvW : muW;
    const float* bias = which ? lvb : mub;
    const float* lr = last + (size_t)r * Dm;
    float acc = bias[d];
#pragma unroll 8
    for (int k = 0; k < Dm; k++) acc = fmaf(lr[k], W[(size_t)k * Dm + d], acc);
    out[o] = acc;
}

// ---------------------------------------------------------------------------
// Orchestration: merged base+segment passes (M=4096 mixer GEMMs).
// My launch #3 = dec GEMM (ncu window offset ~2).
// ---------------------------------------------------------------------------
extern "C" void kernel_launch(void* const* d_in, const int* in_sizes, int n_in,
                              void* d_out, int out_size)
{
    const float* decoder_output = (const float*)d_in[0];
    const int*   input_ids      = (const int*)  d_in[1];
    const int*   seg_idx        = (const int*)  d_in[2];
    const float* E              = (const float*)d_in[3];
    const float* Aparam         = (const float*)d_in[4];
    const float* Win            = (const float*)d_in[5];
    const float* Wout           = (const float*)d_in[6];
    const float* Wm1            = (const float*)d_in[7];
    const float* Wm2            = (const float*)d_in[8];
    const float* muW            = (const float*)d_in[9];
    const float* mub            = (const float*)d_in[10];
    const float* lvW            = (const float*)d_in[11];
    const float* lvb            = (const float*)d_in[12];
    float* out = (float*)d_out;

    float *x, *decpart, *ug, *h, *state, *carry, *sins, *last;
    int *starts, *ends;
    __nv_bfloat16 *decAh, *decAl, *xh, *xl, *ph, *pl, *mlph, *mlpl;
    __nv_bfloat16 *eh, *el, *winh, *winl, *wouth, *woutl, *wm1h, *wm1l, *wm2h, *wm2l;
    cudaGetSymbolAddress((void**)&x,       g_x);
    cudaGetSymbolAddress((void**)&decpart, g_decpart);
    cudaGetSymbolAddress((void**)&ug,      g_ug);
    cudaGetSymbolAddress((void**)&h,       g_h);
    cudaGetSymbolAddress((void**)&state,   g_state);
    cudaGetSymbolAddress((void**)&carry,   g_carry);
    cudaGetSymbolAddress((void**)&sins,    g_sin);
    cudaGetSymbolAddress((void**)&last,    g_last);
    cudaGetSymbolAddress((void**)&starts,  g_starts);
    cudaGetSymbolAddress((void**)&ends,    g_ends);
    cudaGetSymbolAddress((void**)&decAh,   g_decAh);
    cudaGetSymbolAddress((void**)&decAl,   g_decAl);
    cudaGetSymbolAddress((void**)&xh,      g_xh);
    cudaGetSymbolAddress((void**)&xl,      g_xl);
    cudaGetSymbolAddress((void**)&ph,      g_ph);
    cudaGetSymbolAddress((void**)&pl,      g_pl);
    cudaGetSymbolAddress((void**)&mlph,    g_mlph);
    cudaGetSymbolAddress((void**)&mlpl,    g_mlpl);
    cudaGetSymbolAddress((void**)&eh,      g_Eh);
    cudaGetSymbolAddress((void**)&el,      g_El);
    cudaGetSymbolAddress((void**)&winh,    g_WinH);
    cudaGetSymbolAddress((void**)&winl,    g_WinL);
    cudaGetSymbolAddress((void**)&wouth,   g_WoutH);
    cudaGetSymbolAddress((void**)&woutl,   g_WoutL);
    cudaGetSymbolAddress((void**)&wm1h,    g_Wm1H);
    cudaGetSymbolAddress((void**)&wm1l,    g_Wm1L);
    cudaGetSymbolAddress((void**)&wm2h,    g_Wm2H);
    cudaGetSymbolAddress((void**)&wm2l,    g_Wm2L);

    constexpr int SMEM_BIG = (2 * (128 * A_LD) + 2 * (32 * B_LDW)) * 2 * 2;
    constexpr int SMEM2 = (2 * 128 * A_LD + 2 * 32 * B_LD) * 2 * 2;
    constexpr int SMEM1 = (2 * 64  * A_LD + 2 * 32 * B_LD) * 2 * 2;
    cudaFuncSetAttribute(gemm_big, cudaFuncAttributeMaxDynamicSharedMemorySize, SMEM_BIG);
    cudaFuncSetAttribute(gemm2<2, 0>, cudaFuncAttributeMaxDynamicSharedMemorySize, SMEM2);
    cudaFuncSetAttribute(gemm2<2, 1>, cudaFuncAttributeMaxDynamicSharedMemorySize, SMEM2);
    cudaFuncSetAttribute(gemm2<1, 2>, cudaFuncAttributeMaxDynamicSharedMemorySize, SMEM1);

    auto split = [&](const float* s, __nv_bfloat16* hh, __nv_bfloat16* ll, size_t n) {
        split_k<<<(int)((n / 4 + 255) / 256), 256>>>(s, hh, ll, (int)(n / 4));
    };

    // #0..#2
    compute_starts_k<<<1, 32>>>(seg_idx, starts, ends);
    split(E, eh, el, (size_t)VOC * Dm);
    split(decoder_output, decAh, decAl, (size_t)NROWS * VOC);

    // #3: dec GEMM (split-K=8) — ncu capture target
    gemm_big<<<dim3(Dm / 256, NROWS / 128, DEC_SK), 256, SMEM_BIG>>>(
        decAh, decAl, eh, el, decpart, VOC, Dm, Dm, DEC_KSLICE, NROWS * Dm);

    // segment rows (2048..4095) from dec partials; base rows from embeddings
    build_xs_k<<<NROWS, 128>>>(decpart, x + (size_t)NROWS * Dm,
                               xh + (size_t)NROWS * Dm, xl + (size_t)NROWS * Dm,
                               starts, ends);
    gather_correct_k<<<NROWS, 128>>>(input_ids, E, x, xh, xl);
    split(Win,  winh,  winl,  (size_t)NLAY * Dm * 2 * INNER);
    split(Wout, wouth, woutl, (size_t)NLAY * INNER * Dm);
    split(Wm1,  wm1h,  wm1l,  (size_t)NLAY * Dm * MLPD);
    split(Wm2,  wm2h,  wm2l,  (size_t)NLAY * MLPD * Dm);

    // -------- Merged layer loop (base rows 0..2047, segment rows 2048..4095) --------
    for (int l = 0; l < NLAY; l++) {
        const size_t oWin  = (size_t)l * Dm * 2 * INNER;
        const size_t oWout = (size_t)l * INNER * Dm;
        const size_t oWm1  = (size_t)l * Dm * MLPD;
        const size_t oWm2  = (size_t)l * MLPD * Dm;
        const float* Al    = Aparam + (size_t)l * INNER;
        float* stl = state + (size_t)l * Bsz * NSEG * INNER;

        gemm2<2, 0><<<dim3((2 * INNER) / 128, XROWS / 128, 1), 512, SMEM2>>>(
            xh, xl, winh + oWin, winl + oWin, ug, nullptr, nullptr,
            Dm, 2 * INNER, 2 * INNER, Dm, 0);
        // base scan (rows 0..2047): carries -> combine -> final (+h for checkpoints)
        scan_carry_k<<<(Bsz * NCH * INNER) / 256, 256>>>(ug, Al, carry);
        combine_k<<<(Bsz * INNER) / 256, 256>>>(carry, Al, sins);
        scan_final_gate_k<<<(Bsz * NCH * INNER) / 256, 256>>>(ug, Al, sins, h, ph, pl);
        save_state_k<<<Bsz * NSEG, INNER>>>(h, stl, starts);
        // segment scan (rows 2048..4095) from just-saved states
        scan_final_gate_k<<<(Bsz * NSEG * INNER) / 256, 256>>>(
            ug + (size_t)NROWS * 2 * INNER, Al, stl, nullptr,
            ph + (size_t)NROWS * INNER, pl + (size_t)NROWS * INNER);
        gemm2<1, 2><<<dim3(Dm / 128, XROWS / 64, 1), 512, SMEM1>>>(
            ph, pl, wouth + oWout, woutl + oWout, x, xh, xl,
            INNER, Dm, Dm, INNER, 0);
        gemm2<2, 1><<<dim3(MLPD / 128, XROWS / 128, 1), 512, SMEM2>>>(
            xh, xl, wm1h + oWm1, wm1l + oWm1, nullptr, mlph, mlpl,
            Dm, MLPD, MLPD, Dm, 0);
        gemm2<1, 2><<<dim3(Dm / 128, XROWS / 64, 1), 512, SMEM1>>>(
            mlph, mlpl, wm2h + oWm2, wm2l + oWm2, x, xh, xl,
            MLPD, Dm, Dm, MLPD, 0);
    }

    extract_last_k<<<Bsz * NSEG, 128>>>(x + (size_t)NROWS * Dm, last, starts, ends);
    head_k<<<(2 * Bsz * NSEG * Dm) / 256, 256>>>(last, muW, mub, lvW, lvb, out);
}

// round 11
// speedup vs baseline: 2.0236x; 1.2507x over previous
#include <cuda_runtime.h>
#include <cuda_fp16.h>
#include <cstdint>

// ---------------------------------------------------------------------------
// Problem constants
// ---------------------------------------------------------------------------
#define Bsz    2
#define Lseq   1024
#define VOC    32000
#define Dm     512
#define NLAY   2
#define INNER  1024
#define MLPD   2048
#define NSEG   8
#define SEGLEN 128
#define NROWS  (Bsz*Lseq)      // 2048 base rows
#define XROWS  (2*NROWS)       // 4096 merged rows
#define DEC_SK 8
#define DEC_KSLICE (VOC/DEC_SK)
#define NCH    8

// ---------------------------------------------------------------------------
// Scratch
// ---------------------------------------------------------------------------
__device__ float g_x      [XROWS * Dm];
__device__ float g_decpart[DEC_SK * NROWS * Dm];
__device__ float g_ug     [XROWS * 2 * INNER];
__device__ float g_h      [NROWS * INNER];
__device__ float g_state  [NLAY * Bsz * NSEG * INNER];
__device__ float g_carry  [Bsz * NCH * INNER];
__device__ float g_sin    [Bsz * NCH * INNER];
__device__ float g_last   [Bsz * NSEG * Dm];
__device__ int   g_starts [Bsz * NSEG];
__device__ int   g_ends   [Bsz * NSEG];
// fp16 operands: A-side hi/lo, B-side single
__device__ __half g_decAh[NROWS * VOC];
__device__ __half g_decAl[NROWS * VOC];
__device__ __half g_xh   [XROWS * Dm];
__device__ __half g_xl   [XROWS * Dm];
__device__ __half g_ph   [XROWS * INNER];
__device__ __half g_pl   [XROWS * INNER];
__device__ __half g_mlph [XROWS * MLPD];
__device__ __half g_mlpl [XROWS * MLPD];
__device__ __half g_Ew   [VOC * Dm];
__device__ __half g_Winw [NLAY * Dm * 2 * INNER];
__device__ __half g_Woutw[NLAY * INNER * Dm];
__device__ __half g_Wm1w [NLAY * Dm * MLPD];
__device__ __half g_Wm2w [NLAY * MLPD * Dm];

__device__ __forceinline__ float silu_f(float v) { return v * (1.f / (1.f + __expf(-v))); }

// fp16 hi/lo split of two floats, packed
__device__ __forceinline__ void split2h(float a, float b, uint32_t& hp, uint32_t& lp) {
    __half ah = __float2half_rn(a), bh = __float2half_rn(b);
    float ar = a - __half2float(ah), br = b - __half2float(bh);
    __half al = __float2half_rn(ar), bl = __float2half_rn(br);
    hp = (uint32_t)__half_as_ushort(ah) | ((uint32_t)__half_as_ushort(bh) << 16);
    lp = (uint32_t)__half_as_ushort(al) | ((uint32_t)__half_as_ushort(bl) << 16);
}
__device__ __forceinline__ uint32_t cvt2h(float a, float b) {
    return (uint32_t)__half_as_ushort(__float2half_rn(a))
         | ((uint32_t)__half_as_ushort(__float2half_rn(b)) << 16);
}

// ---------------------------------------------------------------------------
// primitives
// ---------------------------------------------------------------------------
__device__ __forceinline__ uint32_t smem_u32(const void* p) {
    return (uint32_t)__cvta_generic_to_shared(p);
}
__device__ __forceinline__ void ldmA(uint32_t* r, uint32_t addr) {
    asm volatile("ldmatrix.sync.aligned.m8n8.x4.shared.b16 {%0,%1,%2,%3}, [%4];"
                 : "=r"(r[0]), "=r"(r[1]), "=r"(r[2]), "=r"(r[3]) : "r"(addr));
}
__device__ __forceinline__ void ldmT(uint32_t& r0, uint32_t& r1, uint32_t& r2, uint32_t& r3,
                                     uint32_t addr) {
    asm volatile("ldmatrix.sync.aligned.m8n8.x4.trans.shared.b16 {%0,%1,%2,%3}, [%4];"
                 : "=r"(r0), "=r"(r1), "=r"(r2), "=r"(r3) : "r"(addr));
}
__device__ __forceinline__ void mma16816(float* c, const uint32_t* a, const uint32_t* b) {
    asm volatile("mma.sync.aligned.m16n8k16.row.col.f32.f16.f16.f32 "
                 "{%0,%1,%2,%3}, {%4,%5,%6,%7}, {%8,%9}, {%0,%1,%2,%3};"
                 : "+f"(c[0]), "+f"(c[1]), "+f"(c[2]), "+f"(c[3])
                 : "r"(a[0]), "r"(a[1]), "r"(a[2]), "r"(a[3]), "r"(b[0]), "r"(b[1]));
}
__device__ __forceinline__ void cpa16(uint32_t s, const void* g) {
    asm volatile("cp.async.cg.shared.global [%0], [%1], 16;" :: "r"(s), "l"(g));
}
__device__ __forceinline__ void cpa_commit() { asm volatile("cp.async.commit_group;"); }
__device__ __forceinline__ void cpa_wait1()  { asm volatile("cp.async.wait_group 1;"); }
__device__ __forceinline__ void cpa_wait0()  { asm volatile("cp.async.wait_group 0;"); }

#define A_LD 40
#define B_LD 136
#define B_LDW 264

// ---------------------------------------------------------------------------
// gemm_big (dec): CTA 128x256x32, 8 warps (2m x 4n), warp 64x64.
// fp16 2-term: Ah*B + Al*B (B single fp16).
// ---------------------------------------------------------------------------
__global__ void __launch_bounds__(256, 1)
gemm_big(const __half* __restrict__ Ah, const __half* __restrict__ Al,
         const __half* __restrict__ Bw,
         float* __restrict__ Cf, int lda, int ldb, int ldc, int kchunk, int cslice)
{
    constexpr int A_E = 128 * A_LD;        // 5120
    constexpr int B_E = 32 * B_LDW;        // 8448
    constexpr int STAGE_B = (2 * A_E + B_E) * 2;   // 37,376
    constexpr int OFS_AL = A_E * 2;
    constexpr int OFS_B  = 2 * A_E * 2;

    extern __shared__ __align__(16) char smem[];
    const uint32_t sb = smem_u32(smem);

    const int tid  = threadIdx.x;
    const int lane = tid & 31;
    const int wid  = tid >> 5;
    const int wm = (wid & 1) * 64;
    const int wn = (wid >> 1) * 64;
    const int mbase = blockIdx.y * 128;
    const int nbase = blockIdx.x * 256;
    const int kbeg  = blockIdx.z * kchunk;
    const int niter = kchunk >> 5;

    float acc[4][8][4];
#pragma unroll
    for (int i = 0; i < 4; i++)
#pragma unroll
        for (int j = 0; j < 8; j++)
#pragma unroll
            for (int f = 0; f < 4; f++) acc[i][j][f] = 0.f;

    auto issue = [&](int st, int k0) {
        const uint32_t s0 = sb + st * STAGE_B;
#pragma unroll
        for (int i = 0; i < 2; i++) {              // A: 512 chunks, hi+lo
            const int q = tid + i * 256;
            const int row = q >> 2, c16 = q & 3;
            const size_t ga = (size_t)(mbase + row) * lda + k0 + c16 * 8;
            const uint32_t so = (uint32_t)(row * A_LD + c16 * 8) * 2;
            cpa16(s0 + so, Ah + ga);
            cpa16(s0 + OFS_AL + so, Al + ga);
        }
#pragma unroll
        for (int i = 0; i < 4; i++) {              // B: 1024 chunks, single
            const int q = tid + i * 256;
            const int kr = q >> 5, c16 = q & 31;
            const size_t gb = (size_t)(k0 + kr) * ldb + nbase + c16 * 8;
            const uint32_t so = (uint32_t)(kr * B_LDW + c16 * 8) * 2;
            cpa16(s0 + OFS_B + so, Bw + gb);
        }
    };

    issue(0, kbeg);
    cpa_commit();

    for (int c = 0; c < niter; ++c) {
        if (c + 1 < niter) {
            issue((c + 1) & 1, kbeg + (c + 1) * 32);
            cpa_commit();
            cpa_wait1();
        } else {
            cpa_wait0();
        }
        __syncthreads();

        const uint32_t s0 = sb + (c & 1) * STAGE_B;
#pragma unroll
        for (int ks = 0; ks < 32; ks += 16) {
            uint32_t Bf[8][2];
#pragma unroll
            for (int g = 0; g < 4; g++) {
                const uint32_t off = (uint32_t)((ks + (lane & 15)) * B_LDW
                                                + wn + g * 16 + (lane >> 4) * 8) * 2;
                ldmT(Bf[2*g][0], Bf[2*g][1], Bf[2*g+1][0], Bf[2*g+1][1], s0 + OFS_B + off);
            }
            uint32_t Af[4][4], Alf[4][4];
#pragma unroll
            for (int mt = 0; mt < 4; mt++) {
                const uint32_t offA = (uint32_t)((wm + mt * 16 + (lane & 15)) * A_LD
                                                 + ks + (lane >> 4) * 8) * 2;
                ldmA(Af[mt],  s0 + offA);
                ldmA(Alf[mt], s0 + OFS_AL + offA);
            }
#pragma unroll
            for (int mt = 0; mt < 4; mt++)
#pragma unroll
                for (int nt = 0; nt < 8; nt++)
                    mma16816(acc[mt][nt], Af[mt], Bf[nt]);
#pragma unroll
            for (int mt = 0; mt < 4; mt++)
#pragma unroll
                for (int nt = 0; nt < 8; nt++)
                    mma16816(acc[mt][nt], Alf[mt], Bf[nt]);
        }
        __syncthreads();
    }

    float* Cb = Cf + (size_t)blockIdx.z * cslice;
    const int tr = lane >> 2, tc = (lane & 3) * 2;
#pragma unroll
    for (int mt = 0; mt < 4; mt++) {
#pragma unroll
        for (int nt = 0; nt < 8; nt++) {
#pragma unroll
            for (int half = 0; half < 2; half++) {
                const int row = mbase + wm + mt * 16 + tr + half * 8;
                const int col = nbase + wn + nt * 8 + tc;
                float2 v = make_float2(acc[mt][nt][half * 2], acc[mt][nt][half * 2 + 1]);
                *(float2*)(Cb + (size_t)row * ldc + col) = v;
            }
        }
    }
}

// ---------------------------------------------------------------------------
// gemm2 (mixer): 512 threads, 16 warps (4m x 4n), warp 32x32, fp16 2-term.
//   EPI 0: Cf = acc ; EPI 1: (Ch,Cl)=split(silu(acc)) ; EPI 2: Cf+=acc, split.
// ---------------------------------------------------------------------------
template<int MTILES, int EPI>
__global__ void __launch_bounds__(512, 2)
gemm2(const __half* __restrict__ Ah, const __half* __restrict__ Al,
      const __half* __restrict__ Bw,
      float* __restrict__ Cf, __half* __restrict__ Ch, __half* __restrict__ Cl,
      int lda, int ldb, int ldc, int kchunk, int cslice)
{
    constexpr int BM = MTILES * 64;
    constexpr int A_E = BM * A_LD;
    constexpr int B_E = 32 * B_LD;
    constexpr int STAGE_B = (2 * A_E + B_E) * 2;
    constexpr int OFS_AL = A_E * 2;
    constexpr int OFS_B  = 2 * A_E * 2;

    extern __shared__ __align__(16) char smem[];
    const uint32_t sb = smem_u32(smem);

    const int tid  = threadIdx.x;
    const int lane = tid & 31;
    const int wid  = tid >> 5;
    const int wm = (wid >> 2) * (MTILES * 16);
    const int wn = (wid & 3) * 32;
    const int mbase = blockIdx.y * BM;
    const int nbase = blockIdx.x * 128;
    const int kbeg  = blockIdx.z * kchunk;
    const int niter = kchunk >> 5;

    float acc[MTILES][4][4];
#pragma unroll
    for (int i = 0; i < MTILES; i++)
#pragma unroll
        for (int j = 0; j < 4; j++)
#pragma unroll
            for (int f = 0; f < 4; f++) acc[i][j][f] = 0.f;

    auto issue = [&](int st, int k0) {
        const uint32_t s0 = sb + st * STAGE_B;
        if (tid < BM * 4) {
            const int row = tid >> 2, c16 = tid & 3;
            const size_t ga = (size_t)(mbase + row) * lda + k0 + c16 * 8;
            const uint32_t so = (uint32_t)(row * A_LD + c16 * 8) * 2;
            cpa16(s0 + so, Ah + ga);
            cpa16(s0 + OFS_AL + so, Al + ga);
        }
        {
            const int kr = tid >> 4, c16 = tid & 15;
            const size_t gb = (size_t)(k0 + kr) * ldb + nbase + c16 * 8;
            const uint32_t so = (uint32_t)(kr * B_LD + c16 * 8) * 2;
            cpa16(s0 + OFS_B + so, Bw + gb);
        }
    };

    issue(0, kbeg);
    cpa_commit();

    for (int c = 0; c < niter; ++c) {
        if (c + 1 < niter) {
            issue((c + 1) & 1, kbeg + (c + 1) * 32);
            cpa_commit();
            cpa_wait1();
        } else {
            cpa_wait0();
        }
        __syncthreads();

        const uint32_t s0 = sb + (c & 1) * STAGE_B;
#pragma unroll
        for (int ks = 0; ks < 32; ks += 16) {
            uint32_t Bf[4][2];
#pragma unroll
            for (int g = 0; g < 2; g++) {
                const uint32_t off = (uint32_t)((ks + (lane & 15)) * B_LD
                                                + wn + g * 16 + (lane >> 4) * 8) * 2;
                ldmT(Bf[2*g][0], Bf[2*g][1], Bf[2*g+1][0], Bf[2*g+1][1], s0 + OFS_B + off);
            }
#pragma unroll
            for (int mt = 0; mt < MTILES; mt++) {
                uint32_t Af[4], Alf[4];
                const uint32_t offA = (uint32_t)((wm + mt * 16 + (lane & 15)) * A_LD
                                                 + ks + (lane >> 4) * 8) * 2;
                ldmA(Af,  s0 + offA);
                ldmA(Alf, s0 + OFS_AL + offA);
#pragma unroll
                for (int nt = 0; nt < 4; nt++) mma16816(acc[mt][nt], Af,  Bf[nt]);
#pragma unroll
                for (int nt = 0; nt < 4; nt++) mma16816(acc[mt][nt], Alf, Bf[nt]);
            }
        }
        __syncthreads();
    }

    float* Cb = (EPI == 0) ? (Cf + (size_t)blockIdx.z * cslice) : Cf;
    const int tr = lane >> 2, tc = (lane & 3) * 2;
#pragma unroll
    for (int mt = 0; mt < MTILES; mt++) {
#pragma unroll
        for (int nt = 0; nt < 4; nt++) {
#pragma unroll
            for (int half = 0; half < 2; half++) {
                const int row = mbase + wm + mt * 16 + tr + half * 8;
                const int col = nbase + wn + nt * 8 + tc;
                float2 v = make_float2(acc[mt][nt][half * 2], acc[mt][nt][half * 2 + 1]);
                if (EPI == 0) {
                    *(float2*)(Cb + (size_t)row * ldc + col) = v;
                } else if (EPI == 1) {
                    v.x = silu_f(v.x); v.y = silu_f(v.y);
                    uint32_t hp, lp;
                    split2h(v.x, v.y, hp, lp);
                    *(uint32_t*)(Ch + (size_t)row * ldc + col) = hp;
                    *(uint32_t*)(Cl + (size_t)row * ldc + col) = lp;
                } else {
                    float* p = Cb + (size_t)row * ldc + col;
                    float2 o = *(float2*)p;
                    v.x += o.x; v.y += o.y;
                    *(float2*)p = v;
                    uint32_t hp, lp;
                    split2h(v.x, v.y, hp, lp);
                    *(uint32_t*)(Ch + (size_t)row * ldc + col) = hp;
                    *(uint32_t*)(Cl + (size_t)row * ldc + col) = lp;
                }
            }
        }
    }
}

// ---------------------------------------------------------------------------
// fp32 -> fp16 hi/lo split (A-side) and single convert (B-side)
// ---------------------------------------------------------------------------
__global__ void splith_k(const float* __restrict__ src,
                         __half* __restrict__ hi, __half* __restrict__ lo, int n4)
{
    const int i = blockIdx.x * blockDim.x + threadIdx.x;
    if (i >= n4) return;
    const float4 v = ((const float4*)src)[i];
    uint32_t h0, l0, h1, l1;
    split2h(v.x, v.y, h0, l0);
    split2h(v.z, v.w, h1, l1);
    ((uint2*)hi)[i] = make_uint2(h0, h1);
    ((uint2*)lo)[i] = make_uint2(l0, l1);
}

__global__ void convert_k(const float* __restrict__ src, __half* __restrict__ dst, int n4)
{
    const int i = blockIdx.x * blockDim.x + threadIdx.x;
    if (i >= n4) return;
    const float4 v = ((const float4*)src)[i];
    ((uint2*)dst)[i] = make_uint2(cvt2h(v.x, v.y), cvt2h(v.z, v.w));
}

// ---------------------------------------------------------------------------
// Scan kernels
// ---------------------------------------------------------------------------
__global__ void scan_carry_k(const float* __restrict__ ug, const float* __restrict__ Avec,
                             float* __restrict__ carry)
{
    const int idx = blockIdx.x * blockDim.x + threadIdx.x;
    const int c = idx & (INNER - 1);
    const int gch = idx >> 10;
    const float a = Avec[c];
    const float* up = ug + (size_t)gch * SEGLEN * (2 * INNER) + c;
    float hv = 0.f;
#pragma unroll 8
    for (int t = 0; t < SEGLEN; t++)
        hv = fmaf(a, hv, up[(size_t)t * (2 * INNER)]);
    carry[idx] = hv;
}

__global__ void combine_k(const float* __restrict__ carry, const float* __restrict__ Avec,
                          float* __restrict__ sin_)
{
    const int idx = blockIdx.x * blockDim.x + threadIdx.x;
    const int c = idx & (INNER - 1);
    const int q = idx >> 10;
    const float a = Avec[c];
    float a128 = a;
#pragma unroll
    for (int i = 0; i < 7; i++) a128 *= a128;
    float s = 0.f;
    for (int k = 0; k < NCH; k++) {
        const size_t o = (size_t)(q * NCH + k) * INNER + c;
        sin_[o] = s;
        s = fmaf(a128, s, carry[o]);
    }
}

__global__ void scan_final_gate_k(const float* __restrict__ ug, const float* __restrict__ Avec,
                                  const float* __restrict__ sin_, float* __restrict__ hout,
                                  __half* __restrict__ ph, __half* __restrict__ pl)
{
    const int idx = blockIdx.x * blockDim.x + threadIdx.x;
    const int c = idx & (INNER - 1);
    const int gch = idx >> 10;
    const float a = Avec[c];
    const float* up = ug + (size_t)gch * SEGLEN * (2 * INNER) + c;
    const float* gp = up + INNER;
    __half* php = ph + (size_t)gch * SEGLEN * INNER + c;
    __half* plp = pl + (size_t)gch * SEGLEN * INNER + c;
    float* hp = hout ? hout + (size_t)gch * SEGLEN * INNER + c : nullptr;
    float hv = sin_[idx];
#pragma unroll 4
    for (int t = 0; t < SEGLEN; t++) {
        hv = fmaf(a, hv, up[(size_t)t * (2 * INNER)]);
        if (hp) hp[(size_t)t * INNER] = hv;
        const float p = silu_f(gp[(size_t)t * (2 * INNER)]) * hv;
        const __half hi = __float2half_rn(p);
        const __half lo = __float2half_rn(p - __half2float(hi));
        php[(size_t)t * INNER] = hi;
        plp[(size_t)t * INNER] = lo;
    }
}

// ---------------------------------------------------------------------------
// Small kernels
// ---------------------------------------------------------------------------
__global__ void compute_starts_k(const int* __restrict__ seg, int* __restrict__ starts,
                                 int* __restrict__ ends)
{
    int b = threadIdx.x;
    if (b >= Bsz) return;
    int cnt = 0;
    for (int t = 0; t < Lseq && cnt < NSEG; t++)
        if (seg[b * Lseq + t] != 0) starts[b * NSEG + cnt++] = t;
    while (cnt < NSEG) { starts[b * NSEG + cnt] = 0; cnt++; }
    for (int i = 0; i < NSEG - 1; i++) ends[b * NSEG + i] = starts[b * NSEG + i + 1];
    ends[b * NSEG + NSEG - 1] = Lseq;
}

__global__ void gather_correct_k(const int* __restrict__ ids, const float* __restrict__ E,
                                 float* __restrict__ x,
                                 __half* __restrict__ xh, __half* __restrict__ xl)
{
    const int row = blockIdx.x;
    const int id = ids[row];
    const float4 v = ((const float4*)(E + (size_t)id * Dm))[threadIdx.x];
    ((float4*)(x + (size_t)row * Dm))[threadIdx.x] = v;
    uint32_t h0, l0, h1, l1;
    split2h(v.x, v.y, h0, l0);
    split2h(v.z, v.w, h1, l1);
    ((uint2*)(xh + (size_t)row * Dm))[threadIdx.x] = make_uint2(h0, h1);
    ((uint2*)(xl + (size_t)row * Dm))[threadIdx.x] = make_uint2(l0, l1);
}

__global__ void save_state_k(const float* __restrict__ h, float* __restrict__ st,
                             const int* __restrict__ starts)
{
    const int r = blockIdx.x;
    const int c = threadIdx.x;
    const int b = r >> 3;
    const int s = starts[r];
    st[(size_t)r * INNER + c] = (s > 0) ? h[((size_t)b * Lseq + (s - 1)) * INNER + c] : 0.f;
}

__global__ void build_xs_k(const float* __restrict__ part, float* __restrict__ xs,
                           __half* __restrict__ xsh, __half* __restrict__ xsl,
                           const int* __restrict__ starts, const int* __restrict__ ends)
{
    const int r = blockIdx.x;
    const int q = r >> 7;
    const int t = r & (SEGLEN - 1);
    const int b = q >> 3;
    const int s = starts[q], e = ends[q];
    const int pos = s + t;
    float4 v = make_float4(0.f, 0.f, 0.f, 0.f);
    if (pos < e && pos < Lseq) {
        const size_t base = ((size_t)b * Lseq + pos) * Dm;
#pragma unroll
        for (int p = 0; p < DEC_SK; p++) {
            const float4 w = ((const float4*)(part + (size_t)p * NROWS * Dm + base))[threadIdx.x];
            v.x += w.x; v.y += w.y; v.z += w.z; v.w += w.w;
        }
    }
    ((float4*)(xs + (size_t)r * Dm))[threadIdx.x] = v;
    uint32_t h0, l0, h1, l1;
    split2h(v.x, v.y, h0, l0);
    split2h(v.z, v.w, h1, l1);
    ((uint2*)(xsh + (size_t)r * Dm))[threadIdx.x] = make_uint2(h0, h1);
    ((uint2*)(xsl + (size_t)r * Dm))[threadIdx.x] = make_uint2(l0, l1);
}

__global__ void extract_last_k(const float* __restrict__ xs, float* __restrict__ last,
                               const int* __restrict__ starts, const int* __restrict__ ends)
{
    const int q = blockIdx.x;
    int len = ends[q] - starts[q];
    if (len > SEGLEN) len = SEGLEN;
    if (len < 1) len = 1;
    const float4* s = (const float4*)(xs + ((size_t)q * SEGLEN + (len - 1)) * Dm);
    float4* d = (float4*)(last + (size_t)q * Dm);
    d[threadIdx.x] = s[threadIdx.x];
}

__global__ void head_k(const float* __restrict__ last,
                       const float* __restrict__ muW, const float* __restrict__ mub,
                       const float* __restrict__ lvW, const float* __restrict__ lvb,
                       float* __restrict__ out)
{
    const int o = blockIdx.x * blockDim.x + threadIdx.x;
    const int which = o >> 13;
    const int rem = o & 8191;
    const int r = rem >> 9, d = rem & 511;
    const float* W = which ? lvW : muW;
    const float* bias = which ? lvb : mub;
    const float* lr = last + (size_t)r * Dm;
    float acc = bias[d];
#pragma unroll 8
    for (int k = 0; k < Dm; k++) acc = fmaf(lr[k], W[(size_t)k * Dm + d], acc);
    out[o] = acc;
}

// ---------------------------------------------------------------------------
// Orchestration (merged passes; my launch #3 = dec GEMM for ncu window)
// ---------------------------------------------------------------------------
extern "C" void kernel_launch(void* const* d_in, const int* in_sizes, int n_in,
                              void* d_out, int out_size)
{
    const float* decoder_output = (const float*)d_in[0];
    const int*   input_ids      = (const int*)  d_in[1];
    const int*   seg_idx        = (const int*)  d_in[2];
    const float* E              = (const float*)d_in[3];
    const float* Aparam         = (const float*)d_in[4];
    const float* Win            = (const float*)d_in[5];
    const float* Wout           = (const float*)d_in[6];
    const float* Wm1            = (const float*)d_in[7];
    const float* Wm2            = (const float*)d_in[8];
    const float* muW            = (const float*)d_in[9];
    const float* mub            = (const float*)d_in[10];
    const float* lvW            = (const float*)d_in[11];
    const float* lvb            = (const float*)d_in[12];
    float* out = (float*)d_out;

    float *x, *decpart, *ug, *h, *state, *carry, *sins, *last;
    int *starts, *ends;
    __half *decAh, *decAl, *xh, *xl, *ph, *pl, *mlph, *mlpl;
    __half *ew, *winw, *woutw, *wm1w, *wm2w;
    cudaGetSymbolAddress((void**)&x,       g_x);
    cudaGetSymbolAddress((void**)&decpart, g_decpart);
    cudaGetSymbolAddress((void**)&ug,      g_ug);
    cudaGetSymbolAddress((void**)&h,       g_h);
    cudaGetSymbolAddress((void**)&state,   g_state);
    cudaGetSymbolAddress((void**)&carry,   g_carry);
    cudaGetSymbolAddress((void**)&sins,    g_sin);
    cudaGetSymbolAddress((void**)&last,    g_last);
    cudaGetSymbolAddress((void**)&starts,  g_starts);
    cudaGetSymbolAddress((void**)&ends,    g_ends);
    cudaGetSymbolAddress((void**)&decAh,   g_decAh);
    cudaGetSymbolAddress((void**)&decAl,   g_decAl);
    cudaGetSymbolAddress((void**)&xh,      g_xh);
    cudaGetSymbolAddress((void**)&xl,      g_xl);
    cudaGetSymbolAddress((void**)&ph,      g_ph);
    cudaGetSymbolAddress((void**)&pl,      g_pl);
    cudaGetSymbolAddress((void**)&mlph,    g_mlph);
    cudaGetSymbolAddress((void**)&mlpl,    g_mlpl);
    cudaGetSymbolAddress((void**)&ew,      g_Ew);
    cudaGetSymbolAddress((void**)&winw,    g_Winw);
    cudaGetSymbolAddress((void**)&woutw,   g_Woutw);
    cudaGetSymbolAddress((void**)&wm1w,    g_Wm1w);
    cudaGetSymbolAddress((void**)&wm2w,    g_Wm2w);

    constexpr int SMEM_BIG = (2 * (128 * A_LD) + 32 * B_LDW) * 2 * 2;  // 74,752 B
    constexpr int SMEM2 = (2 * 128 * A_LD + 32 * B_LD) * 2 * 2;        // 58,368 B
    constexpr int SMEM1 = (2 * 64  * A_LD + 32 * B_LD) * 2 * 2;        // 37,888 B
    cudaFuncSetAttribute(gemm_big, cudaFuncAttributeMaxDynamicSharedMemorySize, SMEM_BIG);
    cudaFuncSetAttribute(gemm2<2, 0>, cudaFuncAttributeMaxDynamicSharedMemorySize, SMEM2);
    cudaFuncSetAttribute(gemm2<2, 1>, cudaFuncAttributeMaxDynamicSharedMemorySize, SMEM2);
    cudaFuncSetAttribute(gemm2<1, 2>, cudaFuncAttributeMaxDynamicSharedMemorySize, SMEM1);

    auto splitA = [&](const float* s, __half* hh, __half* ll, size_t n) {
        splith_k<<<(int)((n / 4 + 255) / 256), 256>>>(s, hh, ll, (int)(n / 4));
    };
    auto convB = [&](const float* s, __half* d, size_t n) {
        convert_k<<<(int)((n / 4 + 255) / 256), 256>>>(s, d, (int)(n / 4));
    };

    // #0..#2
    compute_starts_k<<<1, 32>>>(seg_idx, starts, ends);
    convB(E, ew, (size_t)VOC * Dm);
    splitA(decoder_output, decAh, decAl, (size_t)NROWS * VOC);

    // #3: dec GEMM (split-K=8) — ncu capture target
    gemm_big<<<dim3(Dm / 256, NROWS / 128, DEC_SK), 256, SMEM_BIG>>>(
        decAh, decAl, ew, decpart, VOC, Dm, Dm, DEC_KSLICE, NROWS * Dm);

    build_xs_k<<<NROWS, 128>>>(decpart, x + (size_t)NROWS * Dm,
                               xh + (size_t)NROWS * Dm, xl + (size_t)NROWS * Dm,
                               starts, ends);
    gather_correct_k<<<NROWS, 128>>>(input_ids, E, x, xh, xl);
    convB(Win,  winw,  (size_t)NLAY * Dm * 2 * INNER);
    convB(Wout, woutw, (size_t)NLAY * INNER * Dm);
    convB(Wm1,  wm1w,  (size_t)NLAY * Dm * MLPD);
    convB(Wm2,  wm2w,  (size_t)NLAY * MLPD * Dm);

    // -------- Merged layer loop (base rows 0..2047, segment rows 2048..4095) --------
    for (int l = 0; l < NLAY; l++) {
        const size_t oWin  = (size_t)l * Dm * 2 * INNER;
        const size_t oWout = (size_t)l * INNER * Dm;
        const size_t oWm1  = (size_t)l * Dm * MLPD;
        const size_t oWm2  = (size_t)l * MLPD * Dm;
        const float* Al    = Aparam + (size_t)l * INNER;
        float* stl = state + (size_t)l * Bsz * NSEG * INNER;

        gemm2<2, 0><<<dim3((2 * INNER) / 128, XROWS / 128, 1), 512, SMEM2>>>(
            xh, xl, winw + oWin, ug, nullptr, nullptr,
            Dm, 2 * INNER, 2 * INNER, Dm, 0);
        scan_carry_k<<<(Bsz * NCH * INNER) / 256, 256>>>(ug, Al, carry);
        combine_k<<<(Bsz * INNER) / 256, 256>>>(carry, Al, sins);
        scan_final_gate_k<<<(Bsz * NCH * INNER) / 256, 256>>>(ug, Al, sins, h, ph, pl);
        save_state_k<<<Bsz * NSEG, INNER>>>(h, stl, starts);
        scan_final_gate_k<<<(Bsz * NSEG * INNER) / 256, 256>>>(
            ug + (size_t)NROWS * 2 * INNER, Al, stl, nullptr,
            ph + (size_t)NROWS * INNER, pl + (size_t)NROWS * INNER);
        gemm2<1, 2><<<dim3(Dm / 128, XROWS / 64, 1), 512, SMEM1>>>(
            ph, pl, woutw + oWout, x, xh, xl,
            INNER, Dm, Dm, INNER, 0);
        gemm2<2, 1><<<dim3(MLPD / 128, XROWS / 128, 1), 512, SMEM2>>>(
            xh, xl, wm1w + oWm1, nullptr, mlph, mlpl,
            Dm, MLPD, MLPD, Dm, 0);
        gemm2<1, 2><<<dim3(Dm / 128, XROWS / 64, 1), 512, SMEM1>>>(
            mlph, mlpl, wm2w + oWm2, x, xh, xl,
            MLPD, Dm, Dm, MLPD, 0);
    }

    extract_last_k<<<Bsz * NSEG, 128>>>(x + (size_t)NROWS * Dm, last, starts, ends);
    head_k<<<(2 * Bsz * NSEG * Dm) / 256, 256>>>(last, muW, mub, lvW, lvb, out);
}

// round 12
// speedup vs baseline: 2.1679x; 1.0713x over previous
#include <cuda_runtime.h>
#include <cuda_fp16.h>
#include <cstdint>

// ---------------------------------------------------------------------------
// Problem constants
// ---------------------------------------------------------------------------
#define Bsz    2
#define Lseq   1024
#define VOC    32000
#define Dm     512
#define NLAY   2
#define INNER  1024
#define MLPD   2048
#define NSEG   8
#define SEGLEN 128
#define NROWS  (Bsz*Lseq)      // 2048 base rows
#define XROWS  (2*NROWS)       // 4096 merged rows
#define DEC_SK 8
#define DEC_KSLICE (VOC/DEC_SK)
#define NCH    8

// ---------------------------------------------------------------------------
// Scratch
// ---------------------------------------------------------------------------
__device__ float g_x      [XROWS * Dm];
__device__ float g_decpart[DEC_SK * NROWS * Dm];
__device__ float g_ug     [XROWS * 2 * INNER];
__device__ float g_h      [NROWS * INNER];
__device__ float g_state  [NLAY * Bsz * NSEG * INNER];
__device__ float g_carry  [Bsz * NCH * INNER];
__device__ float g_sin    [Bsz * NCH * INNER];
__device__ float g_last   [Bsz * NSEG * Dm];
__device__ int   g_starts [Bsz * NSEG];
__device__ int   g_ends   [Bsz * NSEG];
// single-fp16 operands (mixer 1-term); dec A split happens inline in gemm_big
__device__ __half g_xw   [XROWS * Dm];
__device__ __half g_pw   [XROWS * INNER];
__device__ __half g_mlpw [XROWS * MLPD];
__device__ __half g_Ew   [VOC * Dm];
__device__ __half g_Winw [NLAY * Dm * 2 * INNER];
__device__ __half g_Woutw[NLAY * INNER * Dm];
__device__ __half g_Wm1w [NLAY * Dm * MLPD];
__device__ __half g_Wm2w [NLAY * MLPD * Dm];

__device__ __forceinline__ float silu_f(float v) { return v * (1.f / (1.f + __expf(-v))); }

__device__ __forceinline__ void split2h(float a, float b, uint32_t& hp, uint32_t& lp) {
    __half ah = __float2half_rn(a), bh = __float2half_rn(b);
    float ar = a - __half2float(ah), br = b - __half2float(bh);
    __half al = __float2half_rn(ar), bl = __float2half_rn(br);
    hp = (uint32_t)__half_as_ushort(ah) | ((uint32_t)__half_as_ushort(bh) << 16);
    lp = (uint32_t)__half_as_ushort(al) | ((uint32_t)__half_as_ushort(bl) << 16);
}
__device__ __forceinline__ uint32_t cvt2h(float a, float b) {
    return (uint32_t)__half_as_ushort(__float2half_rn(a))
         | ((uint32_t)__half_as_ushort(__float2half_rn(b)) << 16);
}

// ---------------------------------------------------------------------------
// primitives
// ---------------------------------------------------------------------------
__device__ __forceinline__ uint32_t smem_u32(const void* p) {
    return (uint32_t)__cvta_generic_to_shared(p);
}
__device__ __forceinline__ void ldmA(uint32_t* r, uint32_t addr) {
    asm volatile("ldmatrix.sync.aligned.m8n8.x4.shared.b16 {%0,%1,%2,%3}, [%4];"
                 : "=r"(r[0]), "=r"(r[1]), "=r"(r[2]), "=r"(r[3]) : "r"(addr));
}
__device__ __forceinline__ void ldmT(uint32_t& r0, uint32_t& r1, uint32_t& r2, uint32_t& r3,
                                     uint32_t addr) {
    asm volatile("ldmatrix.sync.aligned.m8n8.x4.trans.shared.b16 {%0,%1,%2,%3}, [%4];"
                 : "=r"(r0), "=r"(r1), "=r"(r2), "=r"(r3) : "r"(addr));
}
__device__ __forceinline__ void mma16816(float* c, const uint32_t* a, const uint32_t* b) {
    asm volatile("mma.sync.aligned.m16n8k16.row.col.f32.f16.f16.f32 "
                 "{%0,%1,%2,%3}, {%4,%5,%6,%7}, {%8,%9}, {%0,%1,%2,%3};"
                 : "+f"(c[0]), "+f"(c[1]), "+f"(c[2]), "+f"(c[3])
                 : "r"(a[0]), "r"(a[1]), "r"(a[2]), "r"(a[3]), "r"(b[0]), "r"(b[1]));
}
__device__ __forceinline__ void cpa16(uint32_t s, const void* g) {
    asm volatile("cp.async.cg.shared.global [%0], [%1], 16;" :: "r"(s), "l"(g));
}
__device__ __forceinline__ void cpa_commit() { asm volatile("cp.async.commit_group;"); }
__device__ __forceinline__ void cpa_wait1()  { asm volatile("cp.async.wait_group 1;"); }
__device__ __forceinline__ void cpa_wait0()  { asm volatile("cp.async.wait_group 0;"); }

#define A_LD 40
#define B_LD 136
#define B_LDW 264

// ---------------------------------------------------------------------------
// gemm_big (dec): CTA 128x256x32, 8 warps (2m x 4n), warp 64x64.
// A fp32 in global, split inline to fp16 hi/lo in smem (2-term); B single fp16.
// Single-buffer (r7-style); pipelining shown to move tensor% by <1pt.
// ---------------------------------------------------------------------------
__global__ void __launch_bounds__(256, 1)
gemm_big(const float* __restrict__ A, const __half* __restrict__ Bw,
         float* __restrict__ Cf, int lda, int ldb, int ldc, int kchunk, int cslice)
{
    __shared__ __align__(16) __half sAh[128 * A_LD];
    __shared__ __align__(16) __half sAl[128 * A_LD];
    __shared__ __align__(16) __half sB [32 * B_LDW];

    const int tid  = threadIdx.x;
    const int lane = tid & 31;
    const int wid  = tid >> 5;
    const int wm = (wid & 1) * 64;
    const int wn = (wid >> 1) * 64;
    const int mbase = blockIdx.y * 128;
    const int nbase = blockIdx.x * 256;
    const int kbeg  = blockIdx.z * kchunk;

    float acc[4][8][4];
#pragma unroll
    for (int i = 0; i < 4; i++)
#pragma unroll
        for (int j = 0; j < 8; j++)
#pragma unroll
            for (int f = 0; f < 4; f++) acc[i][j][f] = 0.f;

    // A: 128 rows x 32 fp32 = 1024 float4 chunks (4/thread)
    const int arow = tid >> 1, ac4 = (tid & 1) << 2;   // covers 2 float4 per row pair
    // B: 32 k-rows x 256 halves = 1024 uint4 chunks (4/thread)
    const int bkr = tid >> 5, bc16 = tid & 31;

    for (int k0 = kbeg; k0 < kbeg + kchunk; k0 += 32) {
        float4 av[4];
        uint4 bv[4];
#pragma unroll
        for (int i = 0; i < 4; i++) {
            // slot q = tid + i*256: row = q>>3 (8 float4 per 32-float row)
            const int q = tid + i * 256;
            const int row = q >> 3, c4 = q & 7;
            av[i] = *(const float4*)(A + (size_t)(mbase + row) * lda + k0 + c4 * 4);
        }
#pragma unroll
        for (int i = 0; i < 4; i++) {
            const int q = tid + i * 256;
            const int kr = q >> 5, c16 = q & 31;
            bv[i] = *(const uint4*)(Bw + (size_t)(k0 + kr) * ldb + nbase + c16 * 8);
        }
        __syncthreads();
#pragma unroll
        for (int i = 0; i < 4; i++) {
            const int q = tid + i * 256;
            const int row = q >> 3, c4 = q & 7;
            uint32_t h0, l0, h1, l1;
            split2h(av[i].x, av[i].y, h0, l0);
            split2h(av[i].z, av[i].w, h1, l1);
            *(uint2*)(sAh + row * A_LD + c4 * 4) = make_uint2(h0, h1);
            *(uint2*)(sAl + row * A_LD + c4 * 4) = make_uint2(l0, l1);
        }
#pragma unroll
        for (int i = 0; i < 4; i++) {
            const int q = tid + i * 256;
            const int kr = q >> 5, c16 = q & 31;
            *(uint4*)(sB + kr * B_LDW + c16 * 8) = bv[i];
        }
        __syncthreads();

#pragma unroll
        for (int ks = 0; ks < 32; ks += 16) {
            uint32_t Bf[8][2];
#pragma unroll
            for (int g = 0; g < 4; g++) {
                const uint32_t off = smem_u32(sB) +
                    (uint32_t)((ks + (lane & 15)) * B_LDW + wn + g * 16 + (lane >> 4) * 8) * 2;
                ldmT(Bf[2*g][0], Bf[2*g][1], Bf[2*g+1][0], Bf[2*g+1][1], off);
            }
            uint32_t Af[4][4], Alf[4][4];
#pragma unroll
            for (int mt = 0; mt < 4; mt++) {
                const uint32_t o = (uint32_t)((wm + mt * 16 + (lane & 15)) * A_LD
                                              + ks + (lane >> 4) * 8) * 2;
                ldmA(Af[mt],  smem_u32(sAh) + o);
                ldmA(Alf[mt], smem_u32(sAl) + o);
            }
#pragma unroll
            for (int mt = 0; mt < 4; mt++)
#pragma unroll
                for (int nt = 0; nt < 8; nt++)
                    mma16816(acc[mt][nt], Af[mt], Bf[nt]);
#pragma unroll
            for (int mt = 0; mt < 4; mt++)
#pragma unroll
                for (int nt = 0; nt < 8; nt++)
                    mma16816(acc[mt][nt], Alf[mt], Bf[nt]);
        }
    }

    float* Cb = Cf + (size_t)blockIdx.z * cslice;
    const int tr = lane >> 2, tc = (lane & 3) * 2;
#pragma unroll
    for (int mt = 0; mt < 4; mt++) {
#pragma unroll
        for (int nt = 0; nt < 8; nt++) {
#pragma unroll
            for (int half = 0; half < 2; half++) {
                const int row = mbase + wm + mt * 16 + tr + half * 8;
                const int col = nbase + wn + nt * 8 + tc;
                float2 v = make_float2(acc[mt][nt][half * 2], acc[mt][nt][half * 2 + 1]);
                *(float2*)(Cb + (size_t)row * ldc + col) = v;
            }
        }
    }
}

// ---------------------------------------------------------------------------
// gemm2 (mixer): 512 threads, 16 warps (4m x 4n), warp 32x32, fp16 1-term.
//   EPI 0: Cf = acc ; EPI 1: Cw = fp16(silu(acc)) ; EPI 2: Cf += acc, Cw = fp16(Cf)
// ---------------------------------------------------------------------------
template<int MTILES, int EPI>
__global__ void __launch_bounds__(512, 2)
gemm2(const __half* __restrict__ Aw, const __half* __restrict__ Bw,
      float* __restrict__ Cf, __half* __restrict__ Cw,
      int lda, int ldb, int ldc, int kchunk, int cslice)
{
    constexpr int BM = MTILES * 64;
    constexpr int A_E = BM * A_LD;
    constexpr int B_E = 32 * B_LD;
    constexpr int STAGE_B = (A_E + B_E) * 2;
    constexpr int OFS_B = A_E * 2;

    extern __shared__ __align__(16) char smem[];
    const uint32_t sb = smem_u32(smem);

    const int tid  = threadIdx.x;
    const int lane = tid & 31;
    const int wid  = tid >> 5;
    const int wm = (wid >> 2) * (MTILES * 16);
    const int wn = (wid & 3) * 32;
    const int mbase = blockIdx.y * BM;
    const int nbase = blockIdx.x * 128;
    const int kbeg  = blockIdx.z * kchunk;
    const int niter = kchunk >> 5;

    float acc[MTILES][4][4];
#pragma unroll
    for (int i = 0; i < MTILES; i++)
#pragma unroll
        for (int j = 0; j < 4; j++)
#pragma unroll
            for (int f = 0; f < 4; f++) acc[i][j][f] = 0.f;

    auto issue = [&](int st, int k0) {
        const uint32_t s0 = sb + st * STAGE_B;
        if (tid < BM * 4) {                         // A: BM rows x 4 chunks
            const int row = tid >> 2, c16 = tid & 3;
            const size_t ga = (size_t)(mbase + row) * lda + k0 + c16 * 8;
            cpa16(s0 + (uint32_t)(row * A_LD + c16 * 8) * 2, Aw + ga);
        }
        {                                           // B: 32 k x 16 chunks = 512
            const int kr = tid >> 4, c16 = tid & 15;
            const size_t gb = (size_t)(k0 + kr) * ldb + nbase + c16 * 8;
            cpa16(s0 + OFS_B + (uint32_t)(kr * B_LD + c16 * 8) * 2, Bw + gb);
        }
    };

    issue(0, kbeg);
    cpa_commit();

    for (int c = 0; c < niter; ++c) {
        if (c + 1 < niter) {
            issue((c + 1) & 1, kbeg + (c + 1) * 32);
            cpa_commit();
            cpa_wait1();
        } else {
            cpa_wait0();
        }
        __syncthreads();

        const uint32_t s0 = sb + (c & 1) * STAGE_B;
#pragma unroll
        for (int ks = 0; ks < 32; ks += 16) {
            uint32_t Bf[4][2];
#pragma unroll
            for (int g = 0; g < 2; g++) {
                const uint32_t off = (uint32_t)((ks + (lane & 15)) * B_LD
                                                + wn + g * 16 + (lane >> 4) * 8) * 2;
                ldmT(Bf[2*g][0], Bf[2*g][1], Bf[2*g+1][0], Bf[2*g+1][1], s0 + OFS_B + off);
            }
#pragma unroll
            for (int mt = 0; mt < MTILES; mt++) {
                uint32_t Af[4];
                const uint32_t offA = (uint32_t)((wm + mt * 16 + (lane & 15)) * A_LD
                                                 + ks + (lane >> 4) * 8) * 2;
                ldmA(Af, s0 + offA);
#pragma unroll
                for (int nt = 0; nt < 4; nt++) mma16816(acc[mt][nt], Af, Bf[nt]);
            }
        }
        __syncthreads();
    }

    float* Cb = (EPI == 0) ? (Cf + (size_t)blockIdx.z * cslice) : Cf;
    const int tr = lane >> 2, tc = (lane & 3) * 2;
#pragma unroll
    for (int mt = 0; mt < MTILES; mt++) {
#pragma unroll
        for (int nt = 0; nt < 4; nt++) {
#pragma unroll
            for (int half = 0; half < 2; half++) {
                const int row = mbase + wm + mt * 16 + tr + half * 8;
                const int col = nbase + wn + nt * 8 + tc;
                float2 v = make_float2(acc[mt][nt][half * 2], acc[mt][nt][half * 2 + 1]);
                if (EPI == 0) {
                    *(float2*)(Cb + (size_t)row * ldc + col) = v;
                } else if (EPI == 1) {
                    v.x = silu_f(v.x); v.y = silu_f(v.y);
                    *(uint32_t*)(Cw + (size_t)row * ldc + col) = cvt2h(v.x, v.y);
                } else {
                    float* p = Cb + (size_t)row * ldc + col;
                    float2 o = *(float2*)p;
                    v.x += o.x; v.y += o.y;
                    *(float2*)p = v;
                    *(uint32_t*)(Cw + (size_t)row * ldc + col) = cvt2h(v.x, v.y);
                }
            }
        }
    }
}

// ---------------------------------------------------------------------------
// fp32 -> fp16 convert
// ---------------------------------------------------------------------------
__global__ void convert_k(const float* __restrict__ src, __half* __restrict__ dst, int n4)
{
    const int i = blockIdx.x * blockDim.x + threadIdx.x;
    if (i >= n4) return;
    const float4 v = ((const float4*)src)[i];
    ((uint2*)dst)[i] = make_uint2(cvt2h(v.x, v.y), cvt2h(v.z, v.w));
}

// ---------------------------------------------------------------------------
// Scan kernels
// ---------------------------------------------------------------------------
__global__ void scan_carry_k(const float* __restrict__ ug, const float* __restrict__ Avec,
                             float* __restrict__ carry)
{
    const int idx = blockIdx.x * blockDim.x + threadIdx.x;
    const int c = idx & (INNER - 1);
    const int gch = idx >> 10;
    const float a = Avec[c];
    const float* up = ug + (size_t)gch * SEGLEN * (2 * INNER) + c;
    float hv = 0.f;
#pragma unroll 8
    for (int t = 0; t < SEGLEN; t++)
        hv = fmaf(a, hv, up[(size_t)t * (2 * INNER)]);
    carry[idx] = hv;
}

__global__ void combine_k(const float* __restrict__ carry, const float* __restrict__ Avec,
                          float* __restrict__ sin_)
{
    const int idx = blockIdx.x * blockDim.x + threadIdx.x;
    const int c = idx & (INNER - 1);
    const int q = idx >> 10;
    const float a = Avec[c];
    float a128 = a;
#pragma unroll
    for (int i = 0; i < 7; i++) a128 *= a128;
    float s = 0.f;
    for (int k = 0; k < NCH; k++) {
        const size_t o = (size_t)(q * NCH + k) * INNER + c;
        sin_[o] = s;
        s = fmaf(a128, s, carry[o]);
    }
}

__global__ void scan_final_gate_k(const float* __restrict__ ug, const float* __restrict__ Avec,
                                  const float* __restrict__ sin_, float* __restrict__ hout,
                                  __half* __restrict__ pw)
{
    const int idx = blockIdx.x * blockDim.x + threadIdx.x;
    const int c = idx & (INNER - 1);
    const int gch = idx >> 10;
    const float a = Avec[c];
    const float* up = ug + (size_t)gch * SEGLEN * (2 * INNER) + c;
    const float* gp = up + INNER;
    __half* pp = pw + (size_t)gch * SEGLEN * INNER + c;
    float* hp = hout ? hout + (size_t)gch * SEGLEN * INNER + c : nullptr;
    float hv = sin_[idx];
#pragma unroll 4
    for (int t = 0; t < SEGLEN; t++) {
        hv = fmaf(a, hv, up[(size_t)t * (2 * INNER)]);
        if (hp) hp[(size_t)t * INNER] = hv;
        const float p = silu_f(gp[(size_t)t * (2 * INNER)]) * hv;
        pp[(size_t)t * INNER] = __float2half_rn(p);
    }
}

// ---------------------------------------------------------------------------
// Small kernels
// ---------------------------------------------------------------------------
__global__ void compute_starts_k(const int* __restrict__ seg, int* __restrict__ starts,
                                 int* __restrict__ ends)
{
    int b = threadIdx.x;
    if (b >= Bsz) return;
    int cnt = 0;
    for (int t = 0; t < Lseq && cnt < NSEG; t++)
        if (seg[b * Lseq + t] != 0) starts[b * NSEG + cnt++] = t;
    while (cnt < NSEG) { starts[b * NSEG + cnt] = 0; cnt++; }
    for (int i = 0; i < NSEG - 1; i++) ends[b * NSEG + i] = starts[b * NSEG + i + 1];
    ends[b * NSEG + NSEG - 1] = Lseq;
}

__global__ void gather_correct_k(const int* __restrict__ ids, const float* __restrict__ E,
                                 float* __restrict__ x, __half* __restrict__ xw)
{
    const int row = blockIdx.x;
    const int id = ids[row];
    const float4 v = ((const float4*)(E + (size_t)id * Dm))[threadIdx.x];
    ((float4*)(x + (size_t)row * Dm))[threadIdx.x] = v;
    ((uint2*)(xw + (size_t)row * Dm))[threadIdx.x] =
        make_uint2(cvt2h(v.x, v.y), cvt2h(v.z, v.w));
}

__global__ void save_state_k(const float* __restrict__ h, float* __restrict__ st,
                             const int* __restrict__ starts)
{
    const int r = blockIdx.x;
    const int c = threadIdx.x;
    const int b = r >> 3;
    const int s = starts[r];
    st[(size_t)r * INNER + c] = (s > 0) ? h[((size_t)b * Lseq + (s - 1)) * INNER + c] : 0.f;
}

__global__ void build_xs_k(const float* __restrict__ part, float* __restrict__ xs,
                           __half* __restrict__ xsw,
                           const int* __restrict__ starts, const int* __restrict__ ends)
{
    const int r = blockIdx.x;
    const int q = r >> 7;
    const int t = r & (SEGLEN - 1);
    const int b = q >> 3;
    const int s = starts[q], e = ends[q];
    const int pos = s + t;
    float4 v = make_float4(0.f, 0.f, 0.f, 0.f);
    if (pos < e && pos < Lseq) {
        const size_t base = ((size_t)b * Lseq + pos) * Dm;
#pragma unroll
        for (int p = 0; p < DEC_SK; p++) {
            const float4 w = ((const float4*)(part + (size_t)p * NROWS * Dm + base))[threadIdx.x];
            v.x += w.x; v.y += w.y; v.z += w.z; v.w += w.w;
        }
    }
    ((float4*)(xs + (size_t)r * Dm))[threadIdx.x] = v;
    ((uint2*)(xsw + (size_t)r * Dm))[threadIdx.x] =
        make_uint2(cvt2h(v.x, v.y), cvt2h(v.z, v.w));
}

__global__ void extract_last_k(const float* __restrict__ xs, float* __restrict__ last,
                               const int* __restrict__ starts, const int* __restrict__ ends)
{
    const int q = blockIdx.x;
    int len = ends[q] - starts[q];
    if (len > SEGLEN) len = SEGLEN;
    if (len < 1) len = 1;
    const float4* s = (const float4*)(xs + ((size_t)q * SEGLEN + (len - 1)) * Dm);
    float4* d = (float4*)(last + (size_t)q * Dm);
    d[threadIdx.x] = s[threadIdx.x];
}

__global__ void head_k(const float* __restrict__ last,
                       const float* __restrict__ muW, const float* __restrict__ mub,
                       const float* __restrict__ lvW, const float* __restrict__ lvb,
                       float* __restrict__ out)
{
    const int o = blockIdx.x * blockDim.x + threadIdx.x;
    const int which = o >> 13;
    const int rem = o & 8191;
    const int r = rem >> 9, d = rem & 511;
    const float* W = which ? lvW : muW;
    const float* bias = which ? lvb : mub;
    const float* lr = last + (size_t)r * Dm;
    float acc = bias[d];
#pragma unroll 8
    for (int k = 0; k < Dm; k++) acc = fmaf(lr[k], W[(size_t)k * Dm + d], acc);
    out[o] = acc;
}

// ---------------------------------------------------------------------------
// Orchestration (merged passes; my launch #3 = dec GEMM for ncu window)
// ---------------------------------------------------------------------------
extern "C" void kernel_launch(void* const* d_in, const int* in_sizes, int n_in,
                              void* d_out, int out_size)
{
    const float* decoder_output = (const float*)d_in[0];
    const int*   input_ids      = (const int*)  d_in[1];
    const int*   seg_idx        = (const int*)  d_in[2];
    const float* E              = (const float*)d_in[3];
    const float* Aparam         = (const float*)d_in[4];
    const float* Win            = (const float*)d_in[5];
    const float* Wout           = (const float*)d_in[6];
    const float* Wm1            = (const float*)d_in[7];
    const float* Wm2            = (const float*)d_in[8];
    const float* muW            = (const float*)d_in[9];
    const float* mub            = (const float*)d_in[10];
    const float* lvW            = (const float*)d_in[11];
    const float* lvb            = (const float*)d_in[12];
    float* out = (float*)d_out;

    float *x, *decpart, *ug, *h, *state, *carry, *sins, *last;
    int *starts, *ends;
    __half *xw, *pw, *mlpw, *ew, *winw, *woutw, *wm1w, *wm2w;
    cudaGetSymbolAddress((void**)&x,       g_x);
    cudaGetSymbolAddress((void**)&decpart, g_decpart);
    cudaGetSymbolAddress((void**)&ug,      g_ug);
    cudaGetSymbolAddress((void**)&h,       g_h);
    cudaGetSymbolAddress((void**)&state,   g_state);
    cudaGetSymbolAddress((void**)&carry,   g_carry);
    cudaGetSymbolAddress((void**)&sins,    g_sin);
    cudaGetSymbolAddress((void**)&last,    g_last);
    cudaGetSymbolAddress((void**)&starts,  g_starts);
    cudaGetSymbolAddress((void**)&ends,    g_ends);
    cudaGetSymbolAddress((void**)&xw,      g_xw);
    cudaGetSymbolAddress((void**)&pw,      g_pw);
    cudaGetSymbolAddress((void**)&mlpw,    g_mlpw);
    cudaGetSymbolAddress((void**)&ew,      g_Ew);
    cudaGetSymbolAddress((void**)&winw,    g_Winw);
    cudaGetSymbolAddress((void**)&woutw,   g_Woutw);
    cudaGetSymbolAddress((void**)&wm1w,    g_Wm1w);
    cudaGetSymbolAddress((void**)&wm2w,    g_Wm2w);

    constexpr int SMEM2 = (128 * A_LD + 32 * B_LD) * 2 * 2;   // 37,888 B
    constexpr int SMEM1 = (64  * A_LD + 32 * B_LD) * 2 * 2;   // 27,648 B
    cudaFuncSetAttribute(gemm2<2, 0>, cudaFuncAttributeMaxDynamicSharedMemorySize, SMEM2);
    cudaFuncSetAttribute(gemm2<2, 1>, cudaFuncAttributeMaxDynamicSharedMemorySize, SMEM2);
    cudaFuncSetAttribute(gemm2<1, 2>, cudaFuncAttributeMaxDynamicSharedMemorySize, SMEM1);

    auto convB = [&](const float* s, __half* d, size_t n) {
        convert_k<<<(int)((n / 4 + 255) / 256), 256>>>(s, d, (int)(n / 4));
    };

    // #0..#2
    compute_starts_k<<<1, 32>>>(seg_idx, starts, ends);
    convB(E, ew, (size_t)VOC * Dm);
    gather_correct_k<<<NROWS, 128>>>(input_ids, E, x, xw);

    // #3: dec GEMM (split-K=8, inline fp32->fp16 hi/lo split) — ncu capture target
    gemm_big<<<dim3(Dm / 256, NROWS / 128, DEC_SK), 256>>>(
        decoder_output, ew, decpart, VOC, Dm, Dm, DEC_KSLICE, NROWS * Dm);

    build_xs_k<<<NROWS, 128>>>(decpart, x + (size_t)NROWS * Dm,
                               xw + (size_t)NROWS * Dm, starts, ends);
    convB(Win,  winw,  (size_t)NLAY * Dm * 2 * INNER);
    convB(Wout, woutw, (size_t)NLAY * INNER * Dm);
    convB(Wm1,  wm1w,  (size_t)NLAY * Dm * MLPD);
    convB(Wm2,  wm2w,  (size_t)NLAY * MLPD * Dm);

    // -------- Merged layer loop (base rows 0..2047, segment rows 2048..4095) --------
    for (int l = 0; l < NLAY; l++) {
        const size_t oWin  = (size_t)l * Dm * 2 * INNER;
        const size_t oWout = (size_t)l * INNER * Dm;
        const size_t oWm1  = (size_t)l * Dm * MLPD;
        const size_t oWm2  = (size_t)l * MLPD * Dm;
        const float* Al    = Aparam + (size_t)l * INNER;
        float* stl = state + (size_t)l * Bsz * NSEG * INNER;

        gemm2<2, 0><<<dim3((2 * INNER) / 128, XROWS / 128, 1), 512, SMEM2>>>(
            xw, winw + oWin, ug, nullptr, Dm, 2 * INNER, 2 * INNER, Dm, 0);
        scan_carry_k<<<(Bsz * NCH * INNER) / 256, 256>>>(ug, Al, carry);
        combine_k<<<(Bsz * INNER) / 256, 256>>>(carry, Al, sins);
        scan_final_gate_k<<<(Bsz * NCH * INNER) / 256, 256>>>(ug, Al, sins, h, pw);
        save_state_k<<<Bsz * NSEG, INNER>>>(h, stl, starts);
        scan_final_gate_k<<<(Bsz * NSEG * INNER) / 256, 256>>>(
            ug + (size_t)NROWS * 2 * INNER, Al, stl, nullptr,
            pw + (size_t)NROWS * INNER);
        gemm2<1, 2><<<dim3(Dm / 128, XROWS / 64, 1), 512, SMEM1>>>(
            pw, woutw + oWout, x, xw, INNER, Dm, Dm, INNER, 0);
        gemm2<2, 1><<<dim3(MLPD / 128, XROWS / 128, 1), 512, SMEM2>>>(
            xw, wm1w + oWm1, nullptr, mlpw, Dm, MLPD, MLPD, Dm, 0);
        gemm2<1, 2><<<dim3(Dm / 128, XROWS / 64, 1), 512, SMEM1>>>(
            mlpw, wm2w + oWm2, x, xw, MLPD, Dm, Dm, MLPD, 0);
    }

    extract_last_k<<<Bsz * NSEG, 128>>>(x + (size_t)NROWS * Dm, last, starts, ends);
    head_k<<<(2 * Bsz * NSEG * Dm) / 256, 256>>>(last, muW, mub, lvW, lvb, out);
}

// round 13
// speedup vs baseline: 2.6704x; 1.2318x over previous
#include <cuda_runtime.h>
#include <cuda_fp16.h>
#include <cstdint>

// ---------------------------------------------------------------------------
// Problem constants
// ---------------------------------------------------------------------------
#define Bsz    2
#define Lseq   1024
#define VOC    32000
#define Dm     512
#define NLAY   2
#define INNER  1024
#define MLPD   2048
#define NSEG   8
#define SEGLEN 128
#define NROWS  (Bsz*Lseq)      // 2048 base rows
#define XROWS  (2*NROWS)       // 4096 merged rows
#define DEC_SK 8
#define DEC_KSLICE (VOC/DEC_SK)
#define NCH    8

// ---------------------------------------------------------------------------
// Scratch
// ---------------------------------------------------------------------------
__device__ float g_x      [XROWS * Dm];
__device__ float g_decpart[DEC_SK * NROWS * Dm];
__device__ float g_ug     [XROWS * 2 * INNER];
__device__ float g_h      [NROWS * INNER];
__device__ float g_state  [NLAY * Bsz * NSEG * INNER];
__device__ float g_carry  [Bsz * NCH * INNER];
__device__ float g_sin    [Bsz * NCH * INNER];
__device__ float g_last   [Bsz * NSEG * Dm];
__device__ int   g_starts [Bsz * NSEG];
__device__ int   g_ends   [Bsz * NSEG];
// single-fp16 operands everywhere (1-term GEMMs)
__device__ __half g_decAw[NROWS * VOC];
__device__ __half g_xw   [XROWS * Dm];
__device__ __half g_pw   [XROWS * INNER];
__device__ __half g_mlpw [XROWS * MLPD];
__device__ __half g_Ew   [VOC * Dm];
__device__ __half g_Winw [NLAY * Dm * 2 * INNER];
__device__ __half g_Woutw[NLAY * INNER * Dm];
__device__ __half g_Wm1w [NLAY * Dm * MLPD];
__device__ __half g_Wm2w [NLAY * MLPD * Dm];

__device__ __forceinline__ float silu_f(float v) { return v * (1.f / (1.f + __expf(-v))); }

__device__ __forceinline__ uint32_t cvt2h(float a, float b) {
    return (uint32_t)__half_as_ushort(__float2half_rn(a))
         | ((uint32_t)__half_as_ushort(__float2half_rn(b)) << 16);
}

// ---------------------------------------------------------------------------
// primitives
// ---------------------------------------------------------------------------
__device__ __forceinline__ uint32_t smem_u32(const void* p) {
    return (uint32_t)__cvta_generic_to_shared(p);
}
__device__ __forceinline__ void ldmA(uint32_t* r, uint32_t addr) {
    asm volatile("ldmatrix.sync.aligned.m8n8.x4.shared.b16 {%0,%1,%2,%3}, [%4];"
                 : "=r"(r[0]), "=r"(r[1]), "=r"(r[2]), "=r"(r[3]) : "r"(addr));
}
__device__ __forceinline__ void ldmT(uint32_t& r0, uint32_t& r1, uint32_t& r2, uint32_t& r3,
                                     uint32_t addr) {
    asm volatile("ldmatrix.sync.aligned.m8n8.x4.trans.shared.b16 {%0,%1,%2,%3}, [%4];"
                 : "=r"(r0), "=r"(r1), "=r"(r2), "=r"(r3) : "r"(addr));
}
__device__ __forceinline__ void mma16816(float* c, const uint32_t* a, const uint32_t* b) {
    asm volatile("mma.sync.aligned.m16n8k16.row.col.f32.f16.f16.f32 "
                 "{%0,%1,%2,%3}, {%4,%5,%6,%7}, {%8,%9}, {%0,%1,%2,%3};"
                 : "+f"(c[0]), "+f"(c[1]), "+f"(c[2]), "+f"(c[3])
                 : "r"(a[0]), "r"(a[1]), "r"(a[2]), "r"(a[3]), "r"(b[0]), "r"(b[1]));
}
__device__ __forceinline__ void cpa16(uint32_t s, const void* g) {
    asm volatile("cp.async.cg.shared.global [%0], [%1], 16;" :: "r"(s), "l"(g));
}
__device__ __forceinline__ void cpa_commit() { asm volatile("cp.async.commit_group;"); }
__device__ __forceinline__ void cpa_wait1()  { asm volatile("cp.async.wait_group 1;"); }
__device__ __forceinline__ void cpa_wait0()  { asm volatile("cp.async.wait_group 0;"); }

#define A_LD 40
#define B_LD 136
#define B_LDW 264

// ---------------------------------------------------------------------------
// gemm_big (dec): CTA 128x256x32, 8 warps (2m x 4n), warp 64x64.
// Single fp16 term, 2-stage cp.async pipeline (r11 structure minus Al).
// ---------------------------------------------------------------------------
__global__ void __launch_bounds__(256, 1)
gemm_big(const __half* __restrict__ Aw, const __half* __restrict__ Bw,
         float* __restrict__ Cf, int lda, int ldb, int ldc, int kchunk, int cslice)
{
    constexpr int A_E = 128 * A_LD;        // 5120
    constexpr int B_E = 32 * B_LDW;        // 8448
    constexpr int STAGE_B = (A_E + B_E) * 2;   // 27,136 B
    constexpr int OFS_B = A_E * 2;

    extern __shared__ __align__(16) char smem[];
    const uint32_t sb = smem_u32(smem);

    const int tid  = threadIdx.x;
    const int lane = tid & 31;
    const int wid  = tid >> 5;
    const int wm = (wid & 1) * 64;
    const int wn = (wid >> 1) * 64;
    const int mbase = blockIdx.y * 128;
    const int nbase = blockIdx.x * 256;
    const int kbeg  = blockIdx.z * kchunk;
    const int niter = kchunk >> 5;

    float acc[4][8][4];
#pragma unroll
    for (int i = 0; i < 4; i++)
#pragma unroll
        for (int j = 0; j < 8; j++)
#pragma unroll
            for (int f = 0; f < 4; f++) acc[i][j][f] = 0.f;

    auto issue = [&](int st, int k0) {
        const uint32_t s0 = sb + st * STAGE_B;
#pragma unroll
        for (int i = 0; i < 2; i++) {              // A: 512 chunks
            const int q = tid + i * 256;
            const int row = q >> 2, c16 = q & 3;
            const size_t ga = (size_t)(mbase + row) * lda + k0 + c16 * 8;
            cpa16(s0 + (uint32_t)(row * A_LD + c16 * 8) * 2, Aw + ga);
        }
#pragma unroll
        for (int i = 0; i < 4; i++) {              // B: 1024 chunks
            const int q = tid + i * 256;
            const int kr = q >> 5, c16 = q & 31;
            const size_t gb = (size_t)(k0 + kr) * ldb + nbase + c16 * 8;
            cpa16(s0 + OFS_B + (uint32_t)(kr * B_LDW + c16 * 8) * 2, Bw + gb);
        }
    };

    issue(0, kbeg);
    cpa_commit();

    for (int c = 0; c < niter; ++c) {
        if (c + 1 < niter) {
            issue((c + 1) & 1, kbeg + (c + 1) * 32);
            cpa_commit();
            cpa_wait1();
        } else {
            cpa_wait0();
        }
        __syncthreads();

        const uint32_t s0 = sb + (c & 1) * STAGE_B;
#pragma unroll
        for (int ks = 0; ks < 32; ks += 16) {
            uint32_t Bf[8][2];
#pragma unroll
            for (int g = 0; g < 4; g++) {
                const uint32_t off = (uint32_t)((ks + (lane & 15)) * B_LDW
                                                + wn + g * 16 + (lane >> 4) * 8) * 2;
                ldmT(Bf[2*g][0], Bf[2*g][1], Bf[2*g+1][0], Bf[2*g+1][1], s0 + OFS_B + off);
            }
            uint32_t Af[4][4];
#pragma unroll
            for (int mt = 0; mt < 4; mt++) {
                const uint32_t o = (uint32_t)((wm + mt * 16 + (lane & 15)) * A_LD
                                              + ks + (lane >> 4) * 8) * 2;
                ldmA(Af[mt], s0 + o);
            }
#pragma unroll
            for (int mt = 0; mt < 4; mt++)
#pragma unroll
                for (int nt = 0; nt < 8; nt++)
                    mma16816(acc[mt][nt], Af[mt], Bf[nt]);
        }
        __syncthreads();
    }

    float* Cb = Cf + (size_t)blockIdx.z * cslice;
    const int tr = lane >> 2, tc = (lane & 3) * 2;
#pragma unroll
    for (int mt = 0; mt < 4; mt++) {
#pragma unroll
        for (int nt = 0; nt < 8; nt++) {
#pragma unroll
            for (int half = 0; half < 2; half++) {
                const int row = mbase + wm + mt * 16 + tr + half * 8;
                const int col = nbase + wn + nt * 8 + tc;
                float2 v = make_float2(acc[mt][nt][half * 2], acc[mt][nt][half * 2 + 1]);
                *(float2*)(Cb + (size_t)row * ldc + col) = v;
            }
        }
    }
}

// ---------------------------------------------------------------------------
// gemm2 (mixer): 512 threads, 16 warps (4m x 4n), warp 32x32, fp16 1-term.
//   EPI 0: Cf = acc ; EPI 1: Cw = fp16(silu(acc)) ; EPI 2: Cf += acc, Cw = fp16(Cf)
// ---------------------------------------------------------------------------
template<int MTILES, int EPI>
__global__ void __launch_bounds__(512, 2)
gemm2(const __half* __restrict__ Aw, const __half* __restrict__ Bw,
      float* __restrict__ Cf, __half* __restrict__ Cw,
      int lda, int ldb, int ldc, int kchunk, int cslice)
{
    constexpr int BM = MTILES * 64;
    constexpr int A_E = BM * A_LD;
    constexpr int B_E = 32 * B_LD;
    constexpr int STAGE_B = (A_E + B_E) * 2;
    constexpr int OFS_B = A_E * 2;

    extern __shared__ __align__(16) char smem[];
    const uint32_t sb = smem_u32(smem);

    const int tid  = threadIdx.x;
    const int lane = tid & 31;
    const int wid  = tid >> 5;
    const int wm = (wid >> 2) * (MTILES * 16);
    const int wn = (wid & 3) * 32;
    const int mbase = blockIdx.y * BM;
    const int nbase = blockIdx.x * 128;
    const int kbeg  = blockIdx.z * kchunk;
    const int niter = kchunk >> 5;

    float acc[MTILES][4][4];
#pragma unroll
    for (int i = 0; i < MTILES; i++)
#pragma unroll
        for (int j = 0; j < 4; j++)
#pragma unroll
            for (int f = 0; f < 4; f++) acc[i][j][f] = 0.f;

    auto issue = [&](int st, int k0) {
        const uint32_t s0 = sb + st * STAGE_B;
        if (tid < BM * 4) {
            const int row = tid >> 2, c16 = tid & 3;
            const size_t ga = (size_t)(mbase + row) * lda + k0 + c16 * 8;
            cpa16(s0 + (uint32_t)(row * A_LD + c16 * 8) * 2, Aw + ga);
        }
        {
            const int kr = tid >> 4, c16 = tid & 15;
            const size_t gb = (size_t)(k0 + kr) * ldb + nbase + c16 * 8;
            cpa16(s0 + OFS_B + (uint32_t)(kr * B_LD + c16 * 8) * 2, Bw + gb);
        }
    };

    issue(0, kbeg);
    cpa_commit();

    for (int c = 0; c < niter; ++c) {
        if (c + 1 < niter) {
            issue((c + 1) & 1, kbeg + (c + 1) * 32);
            cpa_commit();
            cpa_wait1();
        } else {
            cpa_wait0();
        }
        __syncthreads();

        const uint32_t s0 = sb + (c & 1) * STAGE_B;
#pragma unroll
        for (int ks = 0; ks < 32; ks += 16) {
            uint32_t Bf[4][2];
#pragma unroll
            for (int g = 0; g < 2; g++) {
                const uint32_t off = (uint32_t)((ks + (lane & 15)) * B_LD
                                                + wn + g * 16 + (lane >> 4) * 8) * 2;
                ldmT(Bf[2*g][0], Bf[2*g][1], Bf[2*g+1][0], Bf[2*g+1][1], s0 + OFS_B + off);
            }
#pragma unroll
            for (int mt = 0; mt < MTILES; mt++) {
                uint32_t Af[4];
                const uint32_t offA = (uint32_t)((wm + mt * 16 + (lane & 15)) * A_LD
                                                 + ks + (lane >> 4) * 8) * 2;
                ldmA(Af, s0 + offA);
#pragma unroll
                for (int nt = 0; nt < 4; nt++) mma16816(acc[mt][nt], Af, Bf[nt]);
            }
        }
        __syncthreads();
    }

    float* Cb = (EPI == 0) ? (Cf + (size_t)blockIdx.z * cslice) : Cf;
    const int tr = lane >> 2, tc = (lane & 3) * 2;
#pragma unroll
    for (int mt = 0; mt < MTILES; mt++) {
#pragma unroll
        for (int nt = 0; nt < 4; nt++) {
#pragma unroll
            for (int half = 0; half < 2; half++) {
                const int row = mbase + wm + mt * 16 + tr + half * 8;
                const int col = nbase + wn + nt * 8 + tc;
                float2 v = make_float2(acc[mt][nt][half * 2], acc[mt][nt][half * 2 + 1]);
                if (EPI == 0) {
                    *(float2*)(Cb + (size_t)row * ldc + col) = v;
                } else if (EPI == 1) {
                    v.x = silu_f(v.x); v.y = silu_f(v.y);
                    *(uint32_t*)(Cw + (size_t)row * ldc + col) = cvt2h(v.x, v.y);
                } else {
                    float* p = Cb + (size_t)row * ldc + col;
                    float2 o = *(float2*)p;
                    v.x += o.x; v.y += o.y;
                    *(float2*)p = v;
                    *(uint32_t*)(Cw + (size_t)row * ldc + col) = cvt2h(v.x, v.y);
                }
            }
        }
    }
}

// ---------------------------------------------------------------------------
// fp32 -> fp16 convert
// ---------------------------------------------------------------------------
__global__ void convert_k(const float* __restrict__ src, __half* __restrict__ dst, int n4)
{
    const int i = blockIdx.x * blockDim.x + threadIdx.x;
    if (i >= n4) return;
    const float4 v = ((const float4*)src)[i];
    ((uint2*)dst)[i] = make_uint2(cvt2h(v.x, v.y), cvt2h(v.z, v.w));
}

// ---------------------------------------------------------------------------
// Scan kernels
// ---------------------------------------------------------------------------
__global__ void scan_carry_k(const float* __restrict__ ug, const float* __restrict__ Avec,
                             float* __restrict__ carry)
{
    const int idx = blockIdx.x * blockDim.x + threadIdx.x;
    const int c = idx & (INNER - 1);
    const int gch = idx >> 10;
    const float a = Avec[c];
    const float* up = ug + (size_t)gch * SEGLEN * (2 * INNER) + c;
    float hv = 0.f;
#pragma unroll 8
    for (int t = 0; t < SEGLEN; t++)
        hv = fmaf(a, hv, up[(size_t)t * (2 * INNER)]);
    carry[idx] = hv;
}

__global__ void combine_k(const float* __restrict__ carry, const float* __restrict__ Avec,
                          float* __restrict__ sin_)
{
    const int idx = blockIdx.x * blockDim.x + threadIdx.x;
    const int c = idx & (INNER - 1);
    const int q = idx >> 10;
    const float a = Avec[c];
    float a128 = a;
#pragma unroll
    for (int i = 0; i < 7; i++) a128 *= a128;
    float s = 0.f;
    for (int k = 0; k < NCH; k++) {
        const size_t o = (size_t)(q * NCH + k) * INNER + c;
        sin_[o] = s;
        s = fmaf(a128, s, carry[o]);
    }
}

__global__ void scan_final_gate_k(const float* __restrict__ ug, const float* __restrict__ Avec,
                                  const float* __restrict__ sin_, float* __restrict__ hout,
                                  __half* __restrict__ pw)
{
    const int idx = blockIdx.x * blockDim.x + threadIdx.x;
    const int c = idx & (INNER - 1);
    const int gch = idx >> 10;
    const float a = Avec[c];
    const float* up = ug + (size_t)gch * SEGLEN * (2 * INNER) + c;
    const float* gp = up + INNER;
    __half* pp = pw + (size_t)gch * SEGLEN * INNER + c;
    float* hp = hout ? hout + (size_t)gch * SEGLEN * INNER + c : nullptr;
    float hv = sin_[idx];
#pragma unroll 4
    for (int t = 0; t < SEGLEN; t++) {
        hv = fmaf(a, hv, up[(size_t)t * (2 * INNER)]);
        if (hp) hp[(size_t)t * INNER] = hv;
        const float p = silu_f(gp[(size_t)t * (2 * INNER)]) * hv;
        pp[(size_t)t * INNER] = __float2half_rn(p);
    }
}

// ---------------------------------------------------------------------------
// Small kernels
// ---------------------------------------------------------------------------
__global__ void compute_starts_k(const int* __restrict__ seg, int* __restrict__ starts,
                                 int* __restrict__ ends)
{
    int b = threadIdx.x;
    if (b >= Bsz) return;
    int cnt = 0;
    for (int t = 0; t < Lseq && cnt < NSEG; t++)
        if (seg[b * Lseq + t] != 0) starts[b * NSEG + cnt++] = t;
    while (cnt < NSEG) { starts[b * NSEG + cnt] = 0; cnt++; }
    for (int i = 0; i < NSEG - 1; i++) ends[b * NSEG + i] = starts[b * NSEG + i + 1];
    ends[b * NSEG + NSEG - 1] = Lseq;
}

__global__ void gather_correct_k(const int* __restrict__ ids, const float* __restrict__ E,
                                 float* __restrict__ x, __half* __restrict__ xw)
{
    const int row = blockIdx.x;
    const int id = ids[row];
    const float4 v = ((const float4*)(E + (size_t)id * Dm))[threadIdx.x];
    ((float4*)(x + (size_t)row * Dm))[threadIdx.x] = v;
    ((uint2*)(xw + (size_t)row * Dm))[threadIdx.x] =
        make_uint2(cvt2h(v.x, v.y), cvt2h(v.z, v.w));
}

__global__ void save_state_k(const float* __restrict__ h, float* __restrict__ st,
                             const int* __restrict__ starts)
{
    const int r = blockIdx.x;
    const int c = threadIdx.x;
    const int b = r >> 3;
    const int s = starts[r];
    st[(size_t)r * INNER + c] = (s > 0) ? h[((size_t)b * Lseq + (s - 1)) * INNER + c] : 0.f;
}

__global__ void build_xs_k(const float* __restrict__ part, float* __restrict__ xs,
                           __half* __restrict__ xsw,
                           const int* __restrict__ starts, const int* __restrict__ ends)
{
    const int r = blockIdx.x;
    const int q = r >> 7;
    const int t = r & (SEGLEN - 1);
    const int b = q >> 3;
    const int s = starts[q], e = ends[q];
    const int pos = s + t;
    float4 v = make_float4(0.f, 0.f, 0.f, 0.f);
    if (pos < e && pos < Lseq) {
        const size_t base = ((size_t)b * Lseq + pos) * Dm;
#pragma unroll
        for (int p = 0; p < DEC_SK; p++) {
            const float4 w = ((const float4*)(part + (size_t)p * NROWS * Dm + base))[threadIdx.x];
            v.x += w.x; v.y += w.y; v.z += w.z; v.w += w.w;
        }
    }
    ((float4*)(xs + (size_t)r * Dm))[threadIdx.x] = v;
    ((uint2*)(xsw + (size_t)r * Dm))[threadIdx.x] =
        make_uint2(cvt2h(v.x, v.y), cvt2h(v.z, v.w));
}

__global__ void extract_last_k(const float* __restrict__ xs, float* __restrict__ last,
                               const int* __restrict__ starts, const int* __restrict__ ends)
{
    const int q = blockIdx.x;
    int len = ends[q] - starts[q];
    if (len > SEGLEN) len = SEGLEN;
    if (len < 1) len = 1;
    const float4* s = (const float4*)(xs + ((size_t)q * SEGLEN + (len - 1)) * Dm);
    float4* d = (float4*)(last + (size_t)q * Dm);
    d[threadIdx.x] = s[threadIdx.x];
}

__global__ void head_k(const float* __restrict__ last,
                       const float* __restrict__ muW, const float* __restrict__ mub,
                       const float* __restrict__ lvW, const float* __restrict__ lvb,
                       float* __restrict__ out)
{
    const int o = blockIdx.x * blockDim.x + threadIdx.x;
    const int which = o >> 13;
    const int rem = o & 8191;
    const int r = rem >> 9, d = rem & 511;
    const float* W = which ? lvW : muW;
    const float* bias = which ? lvb : mub;
    const float* lr = last + (size_t)r * Dm;
    float acc = bias[d];
#pragma unroll 8
    for (int k = 0; k < Dm; k++) acc = fmaf(lr[k], W[(size_t)k * Dm + d], acc);
    out[o] = acc;
}

// ---------------------------------------------------------------------------
// Orchestration (merged passes; my launch #3 = dec GEMM for ncu window)
// ---------------------------------------------------------------------------
extern "C" void kernel_launch(void* const* d_in, const int* in_sizes, int n_in,
                              void* d_out, int out_size)
{
    const float* decoder_output = (const float*)d_in[0];
    const int*   input_ids      = (const int*)  d_in[1];
    const int*   seg_idx        = (const int*)  d_in[2];
    const float* E              = (const float*)d_in[3];
    const float* Aparam         = (const float*)d_in[4];
    const float* Win            = (const float*)d_in[5];
    const float* Wout           = (const float*)d_in[6];
    const float* Wm1            = (const float*)d_in[7];
    const float* Wm2            = (const float*)d_in[8];
    const float* muW            = (const float*)d_in[9];
    const float* mub            = (const float*)d_in[10];
    const float* lvW            = (const float*)d_in[11];
    const float* lvb            = (const float*)d_in[12];
    float* out = (float*)d_out;

    float *x, *decpart, *ug, *h, *state, *carry, *sins, *last;
    int *starts, *ends;
    __half *decAw, *xw, *pw, *mlpw, *ew, *winw, *woutw, *wm1w, *wm2w;
    cudaGetSymbolAddress((void**)&x,       g_x);
    cudaGetSymbolAddress((void**)&decpart, g_decpart);
    cudaGetSymbolAddress((void**)&ug,      g_ug);
    cudaGetSymbolAddress((void**)&h,       g_h);
    cudaGetSymbolAddress((void**)&state,   g_state);
    cudaGetSymbolAddress((void**)&carry,   g_carry);
    cudaGetSymbolAddress((void**)&sins,    g_sin);
    cudaGetSymbolAddress((void**)&last,    g_last);
    cudaGetSymbolAddress((void**)&starts,  g_starts);
    cudaGetSymbolAddress((void**)&ends,    g_ends);
    cudaGetSymbolAddress((void**)&decAw,   g_decAw);
    cudaGetSymbolAddress((void**)&xw,      g_xw);
    cudaGetSymbolAddress((void**)&pw,      g_pw);
    cudaGetSymbolAddress((void**)&mlpw,    g_mlpw);
    cudaGetSymbolAddress((void**)&ew,      g_Ew);
    cudaGetSymbolAddress((void**)&winw,    g_Winw);
    cudaGetSymbolAddress((void**)&woutw,   g_Woutw);
    cudaGetSymbolAddress((void**)&wm1w,    g_Wm1w);
    cudaGetSymbolAddress((void**)&wm2w,    g_Wm2w);

    constexpr int SMEM_BIG = (128 * A_LD + 32 * B_LDW) * 2 * 2;  // 54,272 B
    constexpr int SMEM2 = (128 * A_LD + 32 * B_LD) * 2 * 2;      // 37,888 B
    constexpr int SMEM1 = (64  * A_LD + 32 * B_LD) * 2 * 2;      // 27,648 B
    cudaFuncSetAttribute(gemm_big, cudaFuncAttributeMaxDynamicSharedMemorySize, SMEM_BIG);
    cudaFuncSetAttribute(gemm2<2, 0>, cudaFuncAttributeMaxDynamicSharedMemorySize, SMEM2);
    cudaFuncSetAttribute(gemm2<2, 1>, cudaFuncAttributeMaxDynamicSharedMemorySize, SMEM2);
    cudaFuncSetAttribute(gemm2<1, 2>, cudaFuncAttributeMaxDynamicSharedMemorySize, SMEM1);

    auto convB = [&](const float* s, __half* d, size_t n) {
        convert_k<<<(int)((n / 4 + 255) / 256), 256>>>(s, d, (int)(n / 4));
    };

    // #0..#2
    compute_starts_k<<<1, 32>>>(seg_idx, starts, ends);
    convB(E, ew, (size_t)VOC * Dm);
    convB(decoder_output, decAw, (size_t)NROWS * VOC);

    // #3: dec GEMM (split-K=8, 1-term fp16, pipelined) — ncu capture target
    gemm_big<<<dim3(Dm / 256, NROWS / 128, DEC_SK), 256, SMEM_BIG>>>(
        decAw, ew, decpart, VOC, Dm, Dm, DEC_KSLICE, NROWS * Dm);

    gather_correct_k<<<NROWS, 128>>>(input_ids, E, x, xw);
    build_xs_k<<<NROWS, 128>>>(decpart, x + (size_t)NROWS * Dm,
                               xw + (size_t)NROWS * Dm, starts, ends);
    convB(Win,  winw,  (size_t)NLAY * Dm * 2 * INNER);
    convB(Wout, woutw, (size_t)NLAY * INNER * Dm);
    convB(Wm1,  wm1w,  (size_t)NLAY * Dm * MLPD);
    convB(Wm2,  wm2w,  (size_t)NLAY * MLPD * Dm);

    // -------- Merged layer loop (base rows 0..2047, segment rows 2048..4095) --------
    for (int l = 0; l < NLAY; l++) {
        const size_t oWin  = (size_t)l * Dm * 2 * INNER;
        const size_t oWout = (size_t)l * INNER * Dm;
        const size_t oWm1  = (size_t)l * Dm * MLPD;
        const size_t oWm2  = (size_t)l * MLPD * Dm;
        const float* Al    = Aparam + (size_t)l * INNER;
        float* stl = state + (size_t)l * Bsz * NSEG * INNER;

        gemm2<2, 0><<<dim3((2 * INNER) / 128, XROWS / 128, 1), 512, SMEM2>>>(
            xw, winw + oWin, ug, nullptr, Dm, 2 * INNER, 2 * INNER, Dm, 0);
        scan_carry_k<<<(Bsz * NCH * INNER) / 256, 256>>>(ug, Al, carry);
        combine_k<<<(Bsz * INNER) / 256, 256>>>(carry, Al, sins);
        scan_final_gate_k<<<(Bsz * NCH * INNER) / 256, 256>>>(ug, Al, sins, h, pw);
        save_state_k<<<Bsz * NSEG, INNER>>>(h, stl, starts);
        scan_final_gate_k<<<(Bsz * NSEG * INNER) / 256, 256>>>(
            ug + (size_t)NROWS * 2 * INNER, Al, stl, nullptr,
            pw + (size_t)NROWS * INNER);
        gemm2<1, 2><<<dim3(Dm / 128, XROWS / 64, 1), 512, SMEM1>>>(
            pw, woutw + oWout, x, xw, INNER, Dm, Dm, INNER, 0);
        gemm2<2, 1><<<dim3(MLPD / 128, XROWS / 128, 1), 512, SMEM2>>>(
            xw, wm1w + oWm1, nullptr, mlpw, Dm, MLPD, MLPD, Dm, 0);
        gemm2<1, 2><<<dim3(Dm / 128, XROWS / 64, 1), 512, SMEM1>>>(
            mlpw, wm2w + oWm2, x, xw, MLPD, Dm, Dm, MLPD, 0);
    }

    extract_last_k<<<Bsz * NSEG, 128>>>(x + (size_t)NROWS * Dm, last, starts, ends);
    head_k<<<(2 * Bsz * NSEG * Dm) / 256, 256>>>(last, muW, mub, lvW, lvb, out);
}

// round 14
// speedup vs baseline: 2.7710x; 1.0377x over previous
#include <cuda_runtime.h>
#include <cuda_fp16.h>
#include <cstdint>

// ---------------------------------------------------------------------------
// Problem constants
// ---------------------------------------------------------------------------
#define Bsz    2
#define Lseq   1024
#define VOC    32000
#define Dm     512
#define NLAY   2
#define INNER  1024
#define MLPD   2048
#define NSEG   8
#define SEGLEN 128
#define NROWS  (Bsz*Lseq)      // 2048 base rows
#define XROWS  (2*NROWS)       // 4096 merged rows
#define DEC_SK 8
#define DEC_KSLICE (VOC/DEC_SK)
#define NCH    16              // base-scan chunks per sequence
#define CHLEN  (Lseq/NCH)      // 64

// ---------------------------------------------------------------------------
// Scratch
// ---------------------------------------------------------------------------
__device__ float g_x      [XROWS * Dm];
__device__ float g_decpart[DEC_SK * NROWS * Dm];
__device__ float g_ug     [XROWS * 2 * INNER];
__device__ float g_h      [NROWS * INNER];
__device__ float g_state  [NLAY * Bsz * NSEG * INNER];
__device__ float g_carry  [Bsz * NCH * INNER];
__device__ float g_sin    [Bsz * NCH * INNER];
__device__ float g_last   [Bsz * NSEG * Dm];
__device__ int   g_starts [Bsz * NSEG];
__device__ int   g_ends   [Bsz * NSEG];
// single-fp16 operands (1-term GEMMs)
__device__ __half g_decAw[NROWS * VOC];
__device__ __half g_xw   [XROWS * Dm];
__device__ __half g_pw   [XROWS * INNER];
__device__ __half g_mlpw [XROWS * MLPD];
__device__ __half g_Ew   [VOC * Dm];
__device__ __half g_Winw [NLAY * Dm * 2 * INNER];
__device__ __half g_Woutw[NLAY * INNER * Dm];
__device__ __half g_Wm1w [NLAY * Dm * MLPD];
__device__ __half g_Wm2w [NLAY * MLPD * Dm];

__device__ __forceinline__ float silu_f(float v) { return v * (1.f / (1.f + __expf(-v))); }

__device__ __forceinline__ uint32_t cvt2h(float a, float b) {
    return (uint32_t)__half_as_ushort(__float2half_rn(a))
         | ((uint32_t)__half_as_ushort(__float2half_rn(b)) << 16);
}

// ---------------------------------------------------------------------------
// primitives
// ---------------------------------------------------------------------------
__device__ __forceinline__ uint32_t smem_u32(const void* p) {
    return (uint32_t)__cvta_generic_to_shared(p);
}
__device__ __forceinline__ void ldmA(uint32_t* r, uint32_t addr) {
    asm volatile("ldmatrix.sync.aligned.m8n8.x4.shared.b16 {%0,%1,%2,%3}, [%4];"
                 : "=r"(r[0]), "=r"(r[1]), "=r"(r[2]), "=r"(r[3]) : "r"(addr));
}
__device__ __forceinline__ void ldmT(uint32_t& r0, uint32_t& r1, uint32_t& r2, uint32_t& r3,
                                     uint32_t addr) {
    asm volatile("ldmatrix.sync.aligned.m8n8.x4.trans.shared.b16 {%0,%1,%2,%3}, [%4];"
                 : "=r"(r0), "=r"(r1), "=r"(r2), "=r"(r3) : "r"(addr));
}
__device__ __forceinline__ void mma16816(float* c, const uint32_t* a, const uint32_t* b) {
    asm volatile("mma.sync.aligned.m16n8k16.row.col.f32.f16.f16.f32 "
                 "{%0,%1,%2,%3}, {%4,%5,%6,%7}, {%8,%9}, {%0,%1,%2,%3};"
                 : "+f"(c[0]), "+f"(c[1]), "+f"(c[2]), "+f"(c[3])
                 : "r"(a[0]), "r"(a[1]), "r"(a[2]), "r"(a[3]), "r"(b[0]), "r"(b[1]));
}
__device__ __forceinline__ void cpa16(uint32_t s, const void* g) {
    asm volatile("cp.async.cg.shared.global [%0], [%1], 16;" :: "r"(s), "l"(g));
}
__device__ __forceinline__ void cpa_commit() { asm volatile("cp.async.commit_group;"); }
__device__ __forceinline__ void cpa_wait1()  { asm volatile("cp.async.wait_group 1;"); }
__device__ __forceinline__ void cpa_wait0()  { asm volatile("cp.async.wait_group 0;"); }

#define A_LD 40
#define B_LD 136

// ---------------------------------------------------------------------------
// gemm2: 512 threads, 16 warps (4m x 4n), warp 32x32, fp16 1-term,
// 2-stage cp.async, occ 2. Used for dec (EPI 0 + split-K) and all mixer GEMMs.
//   EPI 0: Cf[bz slice] = acc
//   EPI 1: Cw = fp16(silu(acc))
//   EPI 2: Cf += acc ; Cw = fp16(Cf)
// ---------------------------------------------------------------------------
template<int MTILES, int EPI>
__global__ void __launch_bounds__(512, 2)
gemm2(const __half* __restrict__ Aw, const __half* __restrict__ Bw,
      float* __restrict__ Cf, __half* __restrict__ Cw,
      int lda, int ldb, int ldc, int kchunk, int cslice)
{
    constexpr int BM = MTILES * 64;
    constexpr int A_E = BM * A_LD;
    constexpr int B_E = 32 * B_LD;
    constexpr int STAGE_B = (A_E + B_E) * 2;
    constexpr int OFS_B = A_E * 2;

    extern __shared__ __align__(16) char smem[];
    const uint32_t sb = smem_u32(smem);

    const int tid  = threadIdx.x;
    const int lane = tid & 31;
    const int wid  = tid >> 5;
    const int wm = (wid >> 2) * (MTILES * 16);
    const int wn = (wid & 3) * 32;
    const int mbase = blockIdx.y * BM;
    const int nbase = blockIdx.x * 128;
    const int kbeg  = blockIdx.z * kchunk;
    const int niter = kchunk >> 5;

    float acc[MTILES][4][4];
#pragma unroll
    for (int i = 0; i < MTILES; i++)
#pragma unroll
        for (int j = 0; j < 4; j++)
#pragma unroll
            for (int f = 0; f < 4; f++) acc[i][j][f] = 0.f;

    auto issue = [&](int st, int k0) {
        const uint32_t s0 = sb + st * STAGE_B;
        if (tid < BM * 4) {
            const int row = tid >> 2, c16 = tid & 3;
            const size_t ga = (size_t)(mbase + row) * lda + k0 + c16 * 8;
            cpa16(s0 + (uint32_t)(row * A_LD + c16 * 8) * 2, Aw + ga);
        }
        {
            const int kr = tid >> 4, c16 = tid & 15;
            const size_t gb = (size_t)(k0 + kr) * ldb + nbase + c16 * 8;
            cpa16(s0 + OFS_B + (uint32_t)(kr * B_LD + c16 * 8) * 2, Bw + gb);
        }
    };

    issue(0, kbeg);
    cpa_commit();

    for (int c = 0; c < niter; ++c) {
        if (c + 1 < niter) {
            issue((c + 1) & 1, kbeg + (c + 1) * 32);
            cpa_commit();
            cpa_wait1();
        } else {
            cpa_wait0();
        }
        __syncthreads();

        const uint32_t s0 = sb + (c & 1) * STAGE_B;
#pragma unroll
        for (int ks = 0; ks < 32; ks += 16) {
            uint32_t Bf[4][2];
#pragma unroll
            for (int g = 0; g < 2; g++) {
                const uint32_t off = (uint32_t)((ks + (lane & 15)) * B_LD
                                                + wn + g * 16 + (lane >> 4) * 8) * 2;
                ldmT(Bf[2*g][0], Bf[2*g][1], Bf[2*g+1][0], Bf[2*g+1][1], s0 + OFS_B + off);
            }
#pragma unroll
            for (int mt = 0; mt < MTILES; mt++) {
                uint32_t Af[4];
                const uint32_t offA = (uint32_t)((wm + mt * 16 + (lane & 15)) * A_LD
                                                 + ks + (lane >> 4) * 8) * 2;
                ldmA(Af, s0 + offA);
#pragma unroll
                for (int nt = 0; nt < 4; nt++) mma16816(acc[mt][nt], Af, Bf[nt]);
            }
        }
        __syncthreads();
    }

    float* Cb = (EPI == 0) ? (Cf + (size_t)blockIdx.z * cslice) : Cf;
    const int tr = lane >> 2, tc = (lane & 3) * 2;
#pragma unroll
    for (int mt = 0; mt < MTILES; mt++) {
#pragma unroll
        for (int nt = 0; nt < 4; nt++) {
#pragma unroll
            for (int half = 0; half < 2; half++) {
                const int row = mbase + wm + mt * 16 + tr + half * 8;
                const int col = nbase + wn + nt * 8 + tc;
                float2 v = make_float2(acc[mt][nt][half * 2], acc[mt][nt][half * 2 + 1]);
                if (EPI == 0) {
                    *(float2*)(Cb + (size_t)row * ldc + col) = v;
                } else if (EPI == 1) {
                    v.x = silu_f(v.x); v.y = silu_f(v.y);
                    *(uint32_t*)(Cw + (size_t)row * ldc + col) = cvt2h(v.x, v.y);
                } else {
                    float* p = Cb + (size_t)row * ldc + col;
                    float2 o = *(float2*)p;
                    v.x += o.x; v.y += o.y;
                    *(float2*)p = v;
                    *(uint32_t*)(Cw + (size_t)row * ldc + col) = cvt2h(v.x, v.y);
                }
            }
        }
    }
}

// ---------------------------------------------------------------------------
// fp32 -> fp16 convert
// ---------------------------------------------------------------------------
__global__ void convert_k(const float* __restrict__ src, __half* __restrict__ dst, int n4)
{
    const int i = blockIdx.x * blockDim.x + threadIdx.x;
    if (i >= n4) return;
    const float4 v = ((const float4*)src)[i];
    ((uint2*)dst)[i] = make_uint2(cvt2h(v.x, v.y), cvt2h(v.z, v.w));
}

// ---------------------------------------------------------------------------
// Scan kernels (base: NCH chunks of CHLEN; segments: 1 chunk of SEGLEN)
// ---------------------------------------------------------------------------
__global__ void scan_carry_k(const float* __restrict__ ug, const float* __restrict__ Avec,
                             float* __restrict__ carry)
{
    const int idx = blockIdx.x * blockDim.x + threadIdx.x;
    const int c = idx & (INNER - 1);
    const int gch = idx >> 10;
    const float a = Avec[c];
    const float* up = ug + (size_t)gch * CHLEN * (2 * INNER) + c;
    float hv = 0.f;
#pragma unroll 8
    for (int t = 0; t < CHLEN; t++)
        hv = fmaf(a, hv, up[(size_t)t * (2 * INNER)]);
    carry[idx] = hv;
}

__global__ void combine_k(const float* __restrict__ carry, const float* __restrict__ Avec,
                          float* __restrict__ sin_)
{
    const int idx = blockIdx.x * blockDim.x + threadIdx.x;
    const int c = idx & (INNER - 1);
    const int q = idx >> 10;
    const float a = Avec[c];
    float achunk = a;
#pragma unroll
    for (int i = 0; i < 6; i++) achunk *= achunk;   // a^64 = a^CHLEN
    float s = 0.f;
    for (int k = 0; k < NCH; k++) {
        const size_t o = (size_t)(q * NCH + k) * INNER + c;
        sin_[o] = s;
        s = fmaf(achunk, s, carry[o]);
    }
}

// len-parametrized final scan + gate
__global__ void scan_final_gate_k(const float* __restrict__ ug, const float* __restrict__ Avec,
                                  const float* __restrict__ sin_, float* __restrict__ hout,
                                  __half* __restrict__ pw, int len)
{
    const int idx = blockIdx.x * blockDim.x + threadIdx.x;
    const int c = idx & (INNER - 1);
    const int gch = idx >> 10;
    const float a = Avec[c];
    const float* up = ug + (size_t)gch * len * (2 * INNER) + c;
    const float* gp = up + INNER;
    __half* pp = pw + (size_t)gch * len * INNER + c;
    float* hp = hout ? hout + (size_t)gch * len * INNER + c : nullptr;
    float hv = sin_[idx];
#pragma unroll 4
    for (int t = 0; t < len; t++) {
        hv = fmaf(a, hv, up[(size_t)t * (2 * INNER)]);
        if (hp) hp[(size_t)t * INNER] = hv;
        const float p = silu_f(gp[(size_t)t * (2 * INNER)]) * hv;
        pp[(size_t)t * INNER] = __float2half_rn(p);
    }
}

// ---------------------------------------------------------------------------
// Small kernels
// ---------------------------------------------------------------------------
__global__ void compute_starts_k(const int* __restrict__ seg, int* __restrict__ starts,
                                 int* __restrict__ ends)
{
    int b = threadIdx.x;
    if (b >= Bsz) return;
    int cnt = 0;
    for (int t = 0; t < Lseq && cnt < NSEG; t++)
        if (seg[b * Lseq + t] != 0) starts[b * NSEG + cnt++] = t;
    while (cnt < NSEG) { starts[b * NSEG + cnt] = 0; cnt++; }
    for (int i = 0; i < NSEG - 1; i++) ends[b * NSEG + i] = starts[b * NSEG + i + 1];
    ends[b * NSEG + NSEG - 1] = Lseq;
}

__global__ void gather_correct_k(const int* __restrict__ ids, const float* __restrict__ E,
                                 float* __restrict__ x, __half* __restrict__ xw)
{
    const int row = blockIdx.x;
    const int id = ids[row];
    const float4 v = ((const float4*)(E + (size_t)id * Dm))[threadIdx.x];
    ((float4*)(x + (size_t)row * Dm))[threadIdx.x] = v;
    ((uint2*)(xw + (size_t)row * Dm))[threadIdx.x] =
        make_uint2(cvt2h(v.x, v.y), cvt2h(v.z, v.w));
}

__global__ void save_state_k(const float* __restrict__ h, float* __restrict__ st,
                             const int* __restrict__ starts)
{
    const int r = blockIdx.x;
    const int c = threadIdx.x;
    const int b = r >> 3;
    const int s = starts[r];
    st[(size_t)r * INNER + c] = (s > 0) ? h[((size_t)b * Lseq + (s - 1)) * INNER + c] : 0.f;
}

__global__ void build_xs_k(const float* __restrict__ part, float* __restrict__ xs,
                           __half* __restrict__ xsw,
                           const int* __restrict__ starts, const int* __restrict__ ends)
{
    const int r = blockIdx.x;
    const int q = r >> 7;
    const int t = r & (SEGLEN - 1);
    const int b = q >> 3;
    const int s = starts[q], e = ends[q];
    const int pos = s + t;
    float4 v = make_float4(0.f, 0.f, 0.f, 0.f);
    if (pos < e && pos < Lseq) {
        const size_t base = ((size_t)b * Lseq + pos) * Dm;
#pragma unroll
        for (int p = 0; p < DEC_SK; p++) {
            const float4 w = ((const float4*)(part + (size_t)p * NROWS * Dm + base))[threadIdx.x];
            v.x += w.x; v.y += w.y; v.z += w.z; v.w += w.w;
        }
    }
    ((float4*)(xs + (size_t)r * Dm))[threadIdx.x] = v;
    ((uint2*)(xsw + (size_t)r * Dm))[threadIdx.x] =
        make_uint2(cvt2h(v.x, v.y), cvt2h(v.z, v.w));
}

__global__ void extract_last_k(const float* __restrict__ xs, float* __restrict__ last,
                               const int* __restrict__ starts, const int* __restrict__ ends)
{
    const int q = blockIdx.x;
    int len = ends[q] - starts[q];
    if (len > SEGLEN) len = SEGLEN;
    if (len < 1) len = 1;
    const float4* s = (const float4*)(xs + ((size_t)q * SEGLEN + (len - 1)) * Dm);
    float4* d = (float4*)(last + (size_t)q * Dm);
    d[threadIdx.x] = s[threadIdx.x];
}

__global__ void head_k(const float* __restrict__ last,
                       const float* __restrict__ muW, const float* __restrict__ mub,
                       const float* __restrict__ lvW, const float* __restrict__ lvb,
                       float* __restrict__ out)
{
    const int o = blockIdx.x * blockDim.x + threadIdx.x;
    const int which = o >> 13;
    const int rem = o & 8191;
    const int r = rem >> 9, d = rem & 511;
    const float* W = which ? lvW : muW;
    const float* bias = which ? lvb : mub;
    const float* lr = last + (size_t)r * Dm;
    float acc = bias[d];
#pragma unroll 8
    for (int k = 0; k < Dm; k++) acc = fmaf(lr[k], W[(size_t)k * Dm + d], acc);
    out[o] = acc;
}

// ---------------------------------------------------------------------------
// Orchestration (merged passes; my launch #3 = dec GEMM for ncu window)
// ---------------------------------------------------------------------------
extern "C" void kernel_launch(void* const* d_in, const int* in_sizes, int n_in,
                              void* d_out, int out_size)
{
    const float* decoder_output = (const float*)d_in[0];
    const int*   input_ids      = (const int*)  d_in[1];
    const int*   seg_idx        = (const int*)  d_in[2];
    const float* E              = (const float*)d_in[3];
    const float* Aparam         = (const float*)d_in[4];
    const float* Win            = (const float*)d_in[5];
    const float* Wout           = (const float*)d_in[6];
    const float* Wm1            = (const float*)d_in[7];
    const float* Wm2            = (const float*)d_in[8];
    const float* muW            = (const float*)d_in[9];
    const float* mub            = (const float*)d_in[10];
    const float* lvW            = (const float*)d_in[11];
    const float* lvb            = (const float*)d_in[12];
    float* out = (float*)d_out;

    float *x, *decpart, *ug, *h, *state, *carry, *sins, *last;
    int *starts, *ends;
    __half *decAw, *xw, *pw, *mlpw, *ew, *winw, *woutw, *wm1w, *wm2w;
    cudaGetSymbolAddress((void**)&x,       g_x);
    cudaGetSymbolAddress((void**)&decpart, g_decpart);
    cudaGetSymbolAddress((void**)&ug,      g_ug);
    cudaGetSymbolAddress((void**)&h,       g_h);
    cudaGetSymbolAddress((void**)&state,   g_state);
    cudaGetSymbolAddress((void**)&carry,   g_carry);
    cudaGetSymbolAddress((void**)&sins,    g_sin);
    cudaGetSymbolAddress((void**)&last,    g_last);
    cudaGetSymbolAddress((void**)&starts,  g_starts);
    cudaGetSymbolAddress((void**)&ends,    g_ends);
    cudaGetSymbolAddress((void**)&decAw,   g_decAw);
    cudaGetSymbolAddress((void**)&xw,      g_xw);
    cudaGetSymbolAddress((void**)&pw,      g_pw);
    cudaGetSymbolAddress((void**)&mlpw,    g_mlpw);
    cudaGetSymbolAddress((void**)&ew,      g_Ew);
    cudaGetSymbolAddress((void**)&winw,    g_Winw);
    cudaGetSymbolAddress((void**)&woutw,   g_Woutw);
    cudaGetSymbolAddress((void**)&wm1w,    g_Wm1w);
    cudaGetSymbolAddress((void**)&wm2w,    g_Wm2w);

    constexpr int SMEM2 = (128 * A_LD + 32 * B_LD) * 2 * 2;   // 37,888 B
    constexpr int SMEM1 = (64  * A_LD + 32 * B_LD) * 2 * 2;   // 27,648 B
    cudaFuncSetAttribute(gemm2<2, 0>, cudaFuncAttributeMaxDynamicSharedMemorySize, SMEM2);
    cudaFuncSetAttribute(gemm2<2, 1>, cudaFuncAttributeMaxDynamicSharedMemorySize, SMEM2);
    cudaFuncSetAttribute(gemm2<1, 2>, cudaFuncAttributeMaxDynamicSharedMemorySize, SMEM1);

    auto convB = [&](const float* s, __half* d, size_t n) {
        convert_k<<<(int)((n / 4 + 255) / 256), 256>>>(s, d, (int)(n / 4));
    };

    // #0..#2
    compute_starts_k<<<1, 32>>>(seg_idx, starts, ends);
    convB(E, ew, (size_t)VOC * Dm);
    convB(decoder_output, decAw, (size_t)NROWS * VOC);

    // #3: dec GEMM (split-K=8, 1-term fp16, occ-2 geometry) — ncu capture target
    gemm2<2, 0><<<dim3(Dm / 128, NROWS / 128, DEC_SK), 512, SMEM2>>>(
        decAw, ew, decpart, nullptr, VOC, Dm, Dm, DEC_KSLICE, NROWS * Dm);

    gather_correct_k<<<NROWS, 128>>>(input_ids, E, x, xw);
    build_xs_k<<<NROWS, 128>>>(decpart, x + (size_t)NROWS * Dm,
                               xw + (size_t)NROWS * Dm, starts, ends);
    convB(Win,  winw,  (size_t)NLAY * Dm * 2 * INNER);
    convB(Wout, woutw, (size_t)NLAY * INNER * Dm);
    convB(Wm1,  wm1w,  (size_t)NLAY * Dm * MLPD);
    convB(Wm2,  wm2w,  (size_t)NLAY * MLPD * Dm);

    // -------- Merged layer loop (base rows 0..2047, segment rows 2048..4095) --------
    for (int l = 0; l < NLAY; l++) {
        const size_t oWin  = (size_t)l * Dm * 2 * INNER;
        const size_t oWout = (size_t)l * INNER * Dm;
        const size_t oWm1  = (size_t)l * Dm * MLPD;
        const size_t oWm2  = (size_t)l * MLPD * Dm;
        const float* Al    = Aparam + (size_t)l * INNER;
        float* stl = state + (size_t)l * Bsz * NSEG * INNER;

        gemm2<2, 0><<<dim3((2 * INNER) / 128, XROWS / 128, 1), 512, SMEM2>>>(
            xw, winw + oWin, ug, nullptr, Dm, 2 * INNER, 2 * INNER, Dm, 0);
        // base scan (rows 0..2047): NCH=16 chunks of 64
        scan_carry_k<<<(Bsz * NCH * INNER) / 256, 256>>>(ug, Al, carry);
        combine_k<<<(Bsz * INNER) / 256, 256>>>(carry, Al, sins);
        scan_final_gate_k<<<(Bsz * NCH * INNER) / 256, 256>>>(ug, Al, sins, h, pw, CHLEN);
        save_state_k<<<Bsz * NSEG, INNER>>>(h, stl, starts);
        // segment scan (rows 2048..4095): 16 chunks of 128 from saved states
        scan_final_gate_k<<<(Bsz * NSEG * INNER) / 256, 256>>>(
            ug + (size_t)NROWS * 2 * INNER, Al, stl, nullptr,
            pw + (size_t)NROWS * INNER, SEGLEN);
        gemm2<1, 2><<<dim3(Dm / 128, XROWS / 64, 1), 512, SMEM1>>>(
            pw, woutw + oWout, x, xw, INNER, Dm, Dm, INNER, 0);
        gemm2<2, 1><<<dim3(MLPD / 128, XROWS / 128, 1), 512, SMEM2>>>(
            xw, wm1w + oWm1, nullptr, mlpw, Dm, MLPD, MLPD, Dm, 0);
        gemm2<1, 2><<<dim3(Dm / 128, XROWS / 64, 1), 512, SMEM1>>>(
            mlpw, wm2w + oWm2, x, xw, MLPD, Dm, Dm, MLPD, 0);
    }

    extract_last_k<<<Bsz * NSEG, 128>>>(x + (size_t)NROWS * Dm, last, starts, ends);
    head_k<<<(2 * Bsz * NSEG * Dm) / 256, 256>>>(last, muW, mub, lvW, lvb, out);
}

// round 15
// speedup vs baseline: 2.7851x; 1.0051x over previous
#include <cuda_runtime.h>
#include <cuda_fp16.h>
#include <cstdint>

// ---------------------------------------------------------------------------
// Problem constants
// ---------------------------------------------------------------------------
#define Bsz    2
#define Lseq   1024
#define VOC    32000
#define Dm     512
#define NLAY   2
#define INNER  1024
#define MLPD   2048
#define NSEG   8
#define SEGLEN 128
#define NROWS  (Bsz*Lseq)      // 2048 base rows
#define XROWS  (2*NROWS)       // 4096 merged rows
#define DEC_SK 4
#define DEC_KSLICE (VOC/DEC_SK)   // 8000
#define NCH    16
#define CHLEN  (Lseq/NCH)         // 64

// ---------------------------------------------------------------------------
// Scratch
// ---------------------------------------------------------------------------
__device__ float g_x      [XROWS * Dm];
__device__ float g_decpart[DEC_SK * NROWS * Dm];
__device__ float g_ug     [XROWS * 2 * INNER];
__device__ float g_h      [NROWS * INNER];
__device__ float g_state  [NLAY * Bsz * NSEG * INNER];
__device__ float g_carry  [Bsz * NCH * INNER];
__device__ float g_sin    [Bsz * NCH * INNER];
__device__ float g_last   [Bsz * NSEG * Dm];
__device__ int   g_starts [Bsz * NSEG];
__device__ int   g_ends   [Bsz * NSEG];
__device__ __half g_decAw[NROWS * VOC];
__device__ __half g_xw   [XROWS * Dm];
__device__ __half g_pw   [XROWS * INNER];
__device__ __half g_mlpw [XROWS * MLPD];
__device__ __half g_Ew   [VOC * Dm];
__device__ __half g_Winw [NLAY * Dm * 2 * INNER];
__device__ __half g_Woutw[NLAY * INNER * Dm];
__device__ __half g_Wm1w [NLAY * Dm * MLPD];
__device__ __half g_Wm2w [NLAY * MLPD * Dm];

__device__ __forceinline__ float silu_f(float v) { return v * (1.f / (1.f + __expf(-v))); }

__device__ __forceinline__ uint32_t cvt2h(float a, float b) {
    return (uint32_t)__half_as_ushort(__float2half_rn(a))
         | ((uint32_t)__half_as_ushort(__float2half_rn(b)) << 16);
}

// ---------------------------------------------------------------------------
// primitives
// ---------------------------------------------------------------------------
__device__ __forceinline__ uint32_t smem_u32(const void* p) {
    return (uint32_t)__cvta_generic_to_shared(p);
}
__device__ __forceinline__ void ldmA(uint32_t* r, uint32_t addr) {
    asm volatile("ldmatrix.sync.aligned.m8n8.x4.shared.b16 {%0,%1,%2,%3}, [%4];"
                 : "=r"(r[0]), "=r"(r[1]), "=r"(r[2]), "=r"(r[3]) : "r"(addr));
}
__device__ __forceinline__ void ldmT(uint32_t& r0, uint32_t& r1, uint32_t& r2, uint32_t& r3,
                                     uint32_t addr) {
    asm volatile("ldmatrix.sync.aligned.m8n8.x4.trans.shared.b16 {%0,%1,%2,%3}, [%4];"
                 : "=r"(r0), "=r"(r1), "=r"(r2), "=r"(r3) : "r"(addr));
}
__device__ __forceinline__ void mma16816(float* c, const uint32_t* a, const uint32_t* b) {
    asm volatile("mma.sync.aligned.m16n8k16.row.col.f32.f16.f16.f32 "
                 "{%0,%1,%2,%3}, {%4,%5,%6,%7}, {%8,%9}, {%0,%1,%2,%3};"
                 : "+f"(c[0]), "+f"(c[1]), "+f"(c[2]), "+f"(c[3])
                 : "r"(a[0]), "r"(a[1]), "r"(a[2]), "r"(a[3]), "r"(b[0]), "r"(b[1]));
}
__device__ __forceinline__ void cpa16(uint32_t s, const void* g) {
    asm volatile("cp.async.cg.shared.global [%0], [%1], 16;" :: "r"(s), "l"(g));
}
__device__ __forceinline__ void cpa_commit() { asm volatile("cp.async.commit_group;"); }
__device__ __forceinline__ void cpa_wait1()  { asm volatile("cp.async.wait_group 1;"); }
__device__ __forceinline__ void cpa_wait0()  { asm volatile("cp.async.wait_group 0;"); }

#define A_LD 40
#define B_LD 136

// ---------------------------------------------------------------------------
// gemm2: 512 threads, 16 warps (4m x 4n), warp 32x32, fp16 1-term, 2-stage
// cp.async. ALL fragments for a stage are prefetched into registers before
// any mma issues (breaks the per-group ldm->mma dependency exposure).
//   EPI 0: Cf[bz slice] = acc
//   EPI 1: Cw = fp16(silu(acc))
//   EPI 2: Cf += acc ; Cw = fp16(Cf)
// ---------------------------------------------------------------------------
template<int MTILES, int EPI>
__global__ void __launch_bounds__(512)
gemm2(const __half* __restrict__ Aw, const __half* __restrict__ Bw,
      float* __restrict__ Cf, __half* __restrict__ Cw,
      int lda, int ldb, int ldc, int kchunk, int cslice)
{
    constexpr int BM = MTILES * 64;
    constexpr int A_E = BM * A_LD;
    constexpr int B_E = 32 * B_LD;
    constexpr int STAGE_B = (A_E + B_E) * 2;
    constexpr int OFS_B = A_E * 2;

    extern __shared__ __align__(16) char smem[];
    const uint32_t sb = smem_u32(smem);

    const int tid  = threadIdx.x;
    const int lane = tid & 31;
    const int wid  = tid >> 5;
    const int wm = (wid >> 2) * (MTILES * 16);
    const int wn = (wid & 3) * 32;
    const int mbase = blockIdx.y * BM;
    const int nbase = blockIdx.x * 128;
    const int kbeg  = blockIdx.z * kchunk;
    const int niter = kchunk >> 5;

    float acc[MTILES][4][4];
#pragma unroll
    for (int i = 0; i < MTILES; i++)
#pragma unroll
        for (int j = 0; j < 4; j++)
#pragma unroll
            for (int f = 0; f < 4; f++) acc[i][j][f] = 0.f;

    auto issue = [&](int st, int k0) {
        const uint32_t s0 = sb + st * STAGE_B;
        if (tid < BM * 4) {
            const int row = tid >> 2, c16 = tid & 3;
            const size_t ga = (size_t)(mbase + row) * lda + k0 + c16 * 8;
            cpa16(s0 + (uint32_t)(row * A_LD + c16 * 8) * 2, Aw + ga);
        }
        {
            const int kr = tid >> 4, c16 = tid & 15;
            const size_t gb = (size_t)(k0 + kr) * ldb + nbase + c16 * 8;
            cpa16(s0 + OFS_B + (uint32_t)(kr * B_LD + c16 * 8) * 2, Bw + gb);
        }
    };

    issue(0, kbeg);
    cpa_commit();

    for (int c = 0; c < niter; ++c) {
        if (c + 1 < niter) {
            issue((c + 1) & 1, kbeg + (c + 1) * 32);
            cpa_commit();
            cpa_wait1();
        } else {
            cpa_wait0();
        }
        __syncthreads();

        const uint32_t s0 = sb + (c & 1) * STAGE_B;
        // prefetch ALL fragments for this stage (both ks halves)
        uint32_t Bf[2][4][2];
        uint32_t Af[2][MTILES][4];
#pragma unroll
        for (int h = 0; h < 2; h++) {
            const int ks = h * 16;
#pragma unroll
            for (int g = 0; g < 2; g++) {
                const uint32_t off = (uint32_t)((ks + (lane & 15)) * B_LD
                                                + wn + g * 16 + (lane >> 4) * 8) * 2;
                ldmT(Bf[h][2*g][0], Bf[h][2*g][1], Bf[h][2*g+1][0], Bf[h][2*g+1][1],
                     s0 + OFS_B + off);
            }
#pragma unroll
            for (int mt = 0; mt < MTILES; mt++) {
                const uint32_t offA = (uint32_t)((wm + mt * 16 + (lane & 15)) * A_LD
                                                 + ks + (lane >> 4) * 8) * 2;
                ldmA(Af[h][mt], s0 + offA);
            }
        }
        // pure mma burst
#pragma unroll
        for (int h = 0; h < 2; h++)
#pragma unroll
            for (int mt = 0; mt < MTILES; mt++)
#pragma unroll
                for (int nt = 0; nt < 4; nt++)
                    mma16816(acc[mt][nt], Af[h][mt], Bf[h][nt]);
        __syncthreads();
    }

    float* Cb = (EPI == 0) ? (Cf + (size_t)blockIdx.z * cslice) : Cf;
    const int tr = lane >> 2, tc = (lane & 3) * 2;
#pragma unroll
    for (int mt = 0; mt < MTILES; mt++) {
#pragma unroll
        for (int nt = 0; nt < 4; nt++) {
#pragma unroll
            for (int half = 0; half < 2; half++) {
                const int row = mbase + wm + mt * 16 + tr + half * 8;
                const int col = nbase + wn + nt * 8 + tc;
                float2 v = make_float2(acc[mt][nt][half * 2], acc[mt][nt][half * 2 + 1]);
                if (EPI == 0) {
                    *(float2*)(Cb + (size_t)row * ldc + col) = v;
                } else if (EPI == 1) {
                    v.x = silu_f(v.x); v.y = silu_f(v.y);
                    *(uint32_t*)(Cw + (size_t)row * ldc + col) = cvt2h(v.x, v.y);
                } else {
                    float* p = Cb + (size_t)row * ldc + col;
                    float2 o = *(float2*)p;
                    v.x += o.x; v.y += o.y;
                    *(float2*)p = v;
                    *(uint32_t*)(Cw + (size_t)row * ldc + col) = cvt2h(v.x, v.y);
                }
            }
        }
    }
}

// ---------------------------------------------------------------------------
// fp32 -> fp16 converts
// ---------------------------------------------------------------------------
__global__ void convert_k(const float* __restrict__ src, __half* __restrict__ dst, int n4)
{
    const int i = blockIdx.x * blockDim.x + threadIdx.x;
    if (i >= n4) return;
    const float4 v = ((const float4*)src)[i];
    ((uint2*)dst)[i] = make_uint2(cvt2h(v.x, v.y), cvt2h(v.z, v.w));
}

// all 4 weight tensors in one launch
#define N4_WIN  (NLAY * Dm * 2 * INNER / 4)   // 524288
#define N4_WOUT (NLAY * INNER * Dm / 4)       // 262144
#define N4_WM1  (NLAY * Dm * MLPD / 4)        // 524288
#define N4_WM2  (NLAY * MLPD * Dm / 4)        // 262144
#define N4_TOT  (N4_WIN + N4_WOUT + N4_WM1 + N4_WM2)

__global__ void convert_weights_k(const float* __restrict__ win, const float* __restrict__ wout,
                                  const float* __restrict__ wm1, const float* __restrict__ wm2,
                                  __half* __restrict__ dwin, __half* __restrict__ dwout,
                                  __half* __restrict__ dwm1, __half* __restrict__ dwm2)
{
    int i = blockIdx.x * blockDim.x + threadIdx.x;
    if (i >= N4_TOT) return;
    const float* s;
    __half* d;
    if (i < N4_WIN)                       { s = win;  d = dwin; }
    else if ((i -= N4_WIN) < N4_WOUT)     { s = wout; d = dwout; }
    else if ((i -= N4_WOUT) < N4_WM1)     { s = wm1;  d = dwm1; }
    else { i -= N4_WM1;                     s = wm2;  d = dwm2; }
    const float4 v = ((const float4*)s)[i];
    ((uint2*)d)[i] = make_uint2(cvt2h(v.x, v.y), cvt2h(v.z, v.w));
}

// ---------------------------------------------------------------------------
// Scan kernels
// ---------------------------------------------------------------------------
__global__ void scan_carry_k(const float* __restrict__ ug, const float* __restrict__ Avec,
                             float* __restrict__ carry)
{
    const int idx = blockIdx.x * blockDim.x + threadIdx.x;
    const int c = idx & (INNER - 1);
    const int gch = idx >> 10;
    const float a = Avec[c];
    const float* up = ug + (size_t)gch * CHLEN * (2 * INNER) + c;
    float hv = 0.f;
#pragma unroll 8
    for (int t = 0; t < CHLEN; t++)
        hv = fmaf(a, hv, up[(size_t)t * (2 * INNER)]);
    carry[idx] = hv;
}

__global__ void combine_k(const float* __restrict__ carry, const float* __restrict__ Avec,
                          float* __restrict__ sin_)
{
    const int idx = blockIdx.x * blockDim.x + threadIdx.x;
    const int c = idx & (INNER - 1);
    const int q = idx >> 10;
    const float a = Avec[c];
    float achunk = a;
#pragma unroll
    for (int i = 0; i < 6; i++) achunk *= achunk;   // a^64
    float s = 0.f;
    for (int k = 0; k < NCH; k++) {
        const size_t o = (size_t)(q * NCH + k) * INNER + c;
        sin_[o] = s;
        s = fmaf(achunk, s, carry[o]);
    }
}

__global__ void scan_final_gate_k(const float* __restrict__ ug, const float* __restrict__ Avec,
                                  const float* __restrict__ sin_, float* __restrict__ hout,
                                  __half* __restrict__ pw, int len)
{
    const int idx = blockIdx.x * blockDim.x + threadIdx.x;
    const int c = idx & (INNER - 1);
    const int gch = idx >> 10;
    const float a = Avec[c];
    const float* up = ug + (size_t)gch * len * (2 * INNER) + c;
    const float* gp = up + INNER;
    __half* pp = pw + (size_t)gch * len * INNER + c;
    float* hp = hout ? hout + (size_t)gch * len * INNER + c : nullptr;
    float hv = sin_[idx];
#pragma unroll 4
    for (int t = 0; t < len; t++) {
        hv = fmaf(a, hv, up[(size_t)t * (2 * INNER)]);
        if (hp) hp[(size_t)t * INNER] = hv;
        const float p = silu_f(gp[(size_t)t * (2 * INNER)]) * hv;
        pp[(size_t)t * INNER] = __float2half_rn(p);
    }
}

// ---------------------------------------------------------------------------
// Small kernels
// ---------------------------------------------------------------------------
__global__ void compute_starts_k(const int* __restrict__ seg, int* __restrict__ starts,
                                 int* __restrict__ ends)
{
    int b = threadIdx.x;
    if (b >= Bsz) return;
    int cnt = 0;
    for (int t = 0; t < Lseq && cnt < NSEG; t++)
        if (seg[b * Lseq + t] != 0) starts[b * NSEG + cnt++] = t;
    while (cnt < NSEG) { starts[b * NSEG + cnt] = 0; cnt++; }
    for (int i = 0; i < NSEG - 1; i++) ends[b * NSEG + i] = starts[b * NSEG + i + 1];
    ends[b * NSEG + NSEG - 1] = Lseq;
}

// Fused: blocks [0, NROWS) gather embeddings into base rows;
//        blocks [NROWS, 2*NROWS) build segment rows from dec partials.
__global__ void build_inputs_k(const int* __restrict__ ids, const float* __restrict__ E,
                               const float* __restrict__ part,
                               float* __restrict__ x, __half* __restrict__ xw,
                               const int* __restrict__ starts, const int* __restrict__ ends)
{
    const int bid = blockIdx.x;
    if (bid < NROWS) {
        const int id = ids[bid];
        const float4 v = ((const float4*)(E + (size_t)id * Dm))[threadIdx.x];
        ((float4*)(x + (size_t)bid * Dm))[threadIdx.x] = v;
        ((uint2*)(xw + (size_t)bid * Dm))[threadIdx.x] =
            make_uint2(cvt2h(v.x, v.y), cvt2h(v.z, v.w));
    } else {
        const int r = bid - NROWS;
        const int q = r >> 7;
        const int t = r & (SEGLEN - 1);
        const int b = q >> 3;
        const int s = starts[q], e = ends[q];
        const int pos = s + t;
        float4 v = make_float4(0.f, 0.f, 0.f, 0.f);
        if (pos < e && pos < Lseq) {
            const size_t base = ((size_t)b * Lseq + pos) * Dm;
#pragma unroll
            for (int p = 0; p < DEC_SK; p++) {
                const float4 w =
                    ((const float4*)(part + (size_t)p * NROWS * Dm + base))[threadIdx.x];
                v.x += w.x; v.y += w.y; v.z += w.z; v.w += w.w;
            }
        }
        ((float4*)(x + (size_t)bid * Dm))[threadIdx.x] = v;
        ((uint2*)(xw + (size_t)bid * Dm))[threadIdx.x] =
            make_uint2(cvt2h(v.x, v.y), cvt2h(v.z, v.w));
    }
}

__global__ void save_state_k(const float* __restrict__ h, float* __restrict__ st,
                             const int* __restrict__ starts)
{
    const int r = blockIdx.x;
    const int c = threadIdx.x;
    const int b = r >> 3;
    const int s = starts[r];
    st[(size_t)r * INNER + c] = (s > 0) ? h[((size_t)b * Lseq + (s - 1)) * INNER + c] : 0.f;
}

__global__ void extract_last_k(const float* __restrict__ xs, float* __restrict__ last,
                               const int* __restrict__ starts, const int* __restrict__ ends)
{
    const int q = blockIdx.x;
    int len = ends[q] - starts[q];
    if (len > SEGLEN) len = SEGLEN;
    if (len < 1) len = 1;
    const float4* s = (const float4*)(xs + ((size_t)q * SEGLEN + (len - 1)) * Dm);
    float4* d = (float4*)(last + (size_t)q * Dm);
    d[threadIdx.x] = s[threadIdx.x];
}

__global__ void head_k(const float* __restrict__ last,
                       const float* __restrict__ muW, const float* __restrict__ mub,
                       const float* __restrict__ lvW, const float* __restrict__ lvb,
                       float* __restrict__ out)
{
    const int o = blockIdx.x * blockDim.x + threadIdx.x;
    const int which = o >> 13;
    const int rem = o & 8191;
    const int r = rem >> 9, d = rem & 511;
    const float* W = which ? lvW : muW;
    const float* bias = which ? lvb : mub;
    const float* lr = last + (size_t)r * Dm;
    float acc = bias[d];
#pragma unroll 8
    for (int k = 0; k < Dm; k++) acc = fmaf(lr[k], W[(size_t)k * Dm + d], acc);
    out[o] = acc;
}

// ---------------------------------------------------------------------------
// Orchestration (merged passes; my launch #3 = dec GEMM for ncu window)
// ---------------------------------------------------------------------------
extern "C" void kernel_launch(void* const* d_in, const int* in_sizes, int n_in,
                              void* d_out, int out_size)
{
    const float* decoder_output = (const float*)d_in[0];
    const int*   input_ids      = (const int*)  d_in[1];
    const int*   seg_idx        = (const int*)  d_in[2];
    const float* E              = (const float*)d_in[3];
    const float* Aparam         = (const float*)d_in[4];
    const float* Win            = (const float*)d_in[5];
    const float* Wout           = (const float*)d_in[6];
    const float* Wm1            = (const float*)d_in[7];
    const float* Wm2            = (const float*)d_in[8];
    const float* muW            = (const float*)d_in[9];
    const float* mub            = (const float*)d_in[10];
    const float* lvW            = (const float*)d_in[11];
    const float* lvb            = (const float*)d_in[12];
    float* out = (float*)d_out;

    float *x, *decpart, *ug, *h, *state, *carry, *sins, *last;
    int *starts, *ends;
    __half *decAw, *xw, *pw, *mlpw, *ew, *winw, *woutw, *wm1w, *wm2w;
    cudaGetSymbolAddress((void**)&x,       g_x);
    cudaGetSymbolAddress((void**)&decpart, g_decpart);
    cudaGetSymbolAddress((void**)&ug,      g_ug);
    cudaGetSymbolAddress((void**)&h,       g_h);
    cudaGetSymbolAddress((void**)&state,   g_state);
    cudaGetSymbolAddress((void**)&carry,   g_carry);
    cudaGetSymbolAddress((void**)&sins,    g_sin);
    cudaGetSymbolAddress((void**)&last,    g_last);
    cudaGetSymbolAddress((void**)&starts,  g_starts);
    cudaGetSymbolAddress((void**)&ends,    g_ends);
    cudaGetSymbolAddress((void**)&decAw,   g_decAw);
    cudaGetSymbolAddress((void**)&xw,      g_xw);
    cudaGetSymbolAddress((void**)&pw,      g_pw);
    cudaGetSymbolAddress((void**)&mlpw,    g_mlpw);
    cudaGetSymbolAddress((void**)&ew,      g_Ew);
    cudaGetSymbolAddress((void**)&winw,    g_Winw);
    cudaGetSymbolAddress((void**)&woutw,   g_Woutw);
    cudaGetSymbolAddress((void**)&wm1w,    g_Wm1w);
    cudaGetSymbolAddress((void**)&wm2w,    g_Wm2w);

    constexpr int SMEM2 = (128 * A_LD + 32 * B_LD) * 2 * 2;   // 37,888 B
    constexpr int SMEM1 = (64  * A_LD + 32 * B_LD) * 2 * 2;   // 27,648 B
    cudaFuncSetAttribute(gemm2<2, 0>, cudaFuncAttributeMaxDynamicSharedMemorySize, SMEM2);
    cudaFuncSetAttribute(gemm2<2, 1>, cudaFuncAttributeMaxDynamicSharedMemorySize, SMEM2);
    cudaFuncSetAttribute(gemm2<1, 2>, cudaFuncAttributeMaxDynamicSharedMemorySize, SMEM1);

    // #0..#2
    compute_starts_k<<<1, 32>>>(seg_idx, starts, ends);
    convert_k<<<(VOC * Dm / 4 + 255) / 256, 256>>>(E, ew, VOC * Dm / 4);
    convert_k<<<(NROWS * VOC / 4 + 255) / 256, 256>>>(decoder_output, decAw, NROWS * VOC / 4);

    // #3: dec GEMM (split-K=4, 1-term fp16, frag-prefetch) — ncu capture target
    gemm2<2, 0><<<dim3(Dm / 128, NROWS / 128, DEC_SK), 512, SMEM2>>>(
        decAw, ew, decpart, nullptr, VOC, Dm, Dm, DEC_KSLICE, NROWS * Dm);

    build_inputs_k<<<XROWS, 128>>>(input_ids, E, decpart, x, xw, starts, ends);
    convert_weights_k<<<(N4_TOT + 255) / 256, 256>>>(Win, Wout, Wm1, Wm2,
                                                     winw, woutw, wm1w, wm2w);

    // -------- Merged layer loop (base rows 0..2047, segment rows 2048..4095) --------
    for (int l = 0; l < NLAY; l++) {
        const size_t oWin  = (size_t)l * Dm * 2 * INNER;
        const size_t oWout = (size_t)l * INNER * Dm;
        const size_t oWm1  = (size_t)l * Dm * MLPD;
        const size_t oWm2  = (size_t)l * MLPD * Dm;
        const float* Al    = Aparam + (size_t)l * INNER;
        float* stl = state + (size_t)l * Bsz * NSEG * INNER;

        gemm2<2, 0><<<dim3((2 * INNER) / 128, XROWS / 128, 1), 512, SMEM2>>>(
            xw, winw + oWin, ug, nullptr, Dm, 2 * INNER, 2 * INNER, Dm, 0);
        scan_carry_k<<<(Bsz * NCH * INNER) / 256, 256>>>(ug, Al, carry);
        combine_k<<<(Bsz * INNER) / 256, 256>>>(carry, Al, sins);
        scan_final_gate_k<<<(Bsz * NCH * INNER) / 256, 256>>>(ug, Al, sins, h, pw, CHLEN);
        save_state_k<<<Bsz * NSEG, INNER>>>(h, stl, starts);
        scan_final_gate_k<<<(Bsz * NSEG * INNER) / 256, 256>>>(
            ug + (size_t)NROWS * 2 * INNER, Al, stl, nullptr,
            pw + (size_t)NROWS * INNER, SEGLEN);
        gemm2<1, 2><<<dim3(Dm / 128, XROWS / 64, 1), 512, SMEM1>>>(
            pw, woutw + oWout, x, xw, INNER, Dm, Dm, INNER, 0);
        gemm2<2, 1><<<dim3(MLPD / 128, XROWS / 128, 1), 512, SMEM2>>>(
            xw, wm1w + oWm1, nullptr, mlpw, Dm, MLPD, MLPD, Dm, 0);
        gemm2<1, 2><<<dim3(Dm / 128, XROWS / 64, 1), 512, SMEM1>>>(
            mlpw, wm2w + oWm2, x, xw, MLPD, Dm, Dm, MLPD, 0);
    }

    extract_last_k<<<Bsz * NSEG, 128>>>(x + (size_t)NROWS * Dm, last, starts, ends);
    head_k<<<(2 * Bsz * NSEG * Dm) / 256, 256>>>(last, muW, mub, lvW, lvb, out);
}

// round 16
// speedup vs baseline: 2.9806x; 1.0702x over previous
#include <cuda_runtime.h>
#include <cuda_fp16.h>
#include <cstdint>

// ---------------------------------------------------------------------------
// Problem constants
// ---------------------------------------------------------------------------
#define Bsz    2
#define Lseq   1024
#define VOC    32000
#define Dm     512
#define NLAY   2
#define INNER  1024
#define MLPD   2048
#define NSEG   8
#define SEGLEN 128
#define NROWS  (Bsz*Lseq)      // 2048 base rows
#define XROWS  (2*NROWS)       // 4096 merged rows
#define DEC_SK 4
#define DEC_KSLICE (VOC/DEC_SK)   // 8000
#define NCH    16
#define CHLEN  (Lseq/NCH)         // 64

// ---------------------------------------------------------------------------
// Scratch
// ---------------------------------------------------------------------------
__device__ float g_x      [XROWS * Dm];
__device__ float g_decpart[DEC_SK * NROWS * Dm];
__device__ float g_ug     [XROWS * 2 * INNER];
__device__ float g_h      [NROWS * INNER];
__device__ float g_state  [NLAY * Bsz * NSEG * INNER];
__device__ float g_carry  [Bsz * NCH * INNER];
__device__ float g_sin    [Bsz * NCH * INNER];
__device__ float g_last   [Bsz * NSEG * Dm];
__device__ int   g_starts [Bsz * NSEG];
__device__ int   g_ends   [Bsz * NSEG];
__device__ __half g_decAw[NROWS * VOC];
__device__ __half g_xw   [XROWS * Dm];
__device__ __half g_pw   [XROWS * INNER];
__device__ __half g_mlpw [XROWS * MLPD];
__device__ __half g_Ew   [VOC * Dm];
__device__ __half g_Winw [NLAY * Dm * 2 * INNER];
__device__ __half g_Woutw[NLAY * INNER * Dm];
__device__ __half g_Wm1w [NLAY * Dm * MLPD];
__device__ __half g_Wm2w [NLAY * MLPD * Dm];

__device__ __forceinline__ float silu_f(float v) { return v * (1.f / (1.f + __expf(-v))); }

__device__ __forceinline__ uint32_t cvt2h(float a, float b) {
    return (uint32_t)__half_as_ushort(__float2half_rn(a))
         | ((uint32_t)__half_as_ushort(__float2half_rn(b)) << 16);
}

// ---------------------------------------------------------------------------
// primitives
// ---------------------------------------------------------------------------
__device__ __forceinline__ uint32_t smem_u32(const void* p) {
    return (uint32_t)__cvta_generic_to_shared(p);
}
__device__ __forceinline__ void ldmA(uint32_t* r, uint32_t addr) {
    asm volatile("ldmatrix.sync.aligned.m8n8.x4.shared.b16 {%0,%1,%2,%3}, [%4];"
                 : "=r"(r[0]), "=r"(r[1]), "=r"(r[2]), "=r"(r[3]) : "r"(addr));
}
__device__ __forceinline__ void ldmT(uint32_t& r0, uint32_t& r1, uint32_t& r2, uint32_t& r3,
                                     uint32_t addr) {
    asm volatile("ldmatrix.sync.aligned.m8n8.x4.trans.shared.b16 {%0,%1,%2,%3}, [%4];"
                 : "=r"(r0), "=r"(r1), "=r"(r2), "=r"(r3) : "r"(addr));
}
__device__ __forceinline__ void mma16816(float* c, const uint32_t* a, const uint32_t* b) {
    asm volatile("mma.sync.aligned.m16n8k16.row.col.f32.f16.f16.f32 "
                 "{%0,%1,%2,%3}, {%4,%5,%6,%7}, {%8,%9}, {%0,%1,%2,%3};"
                 : "+f"(c[0]), "+f"(c[1]), "+f"(c[2]), "+f"(c[3])
                 : "r"(a[0]), "r"(a[1]), "r"(a[2]), "r"(a[3]), "r"(b[0]), "r"(b[1]));
}
__device__ __forceinline__ void cpa16(uint32_t s, const void* g) {
    asm volatile("cp.async.cg.shared.global [%0], [%1], 16;" :: "r"(s), "l"(g));
}
__device__ __forceinline__ void cpa_commit() { asm volatile("cp.async.commit_group;"); }
__device__ __forceinline__ void cpa_wait1()  { asm volatile("cp.async.wait_group 1;"); }
__device__ __forceinline__ void cpa_wait0()  { asm volatile("cp.async.wait_group 0;"); }

#define A_LD 72     // 64 K + 8 pad (halves)
#define B_LD 136    // 128 N + 8 pad

// ---------------------------------------------------------------------------
// gemm2: 512 threads, 16 warps (4m x 4n), warp 32x32, fp16 1-term.
// BK = 64 per stage (halves per-stage sync/issue overhead per mma),
// 2-stage cp.async pipeline.
//   EPI 0: Cf[bz slice] = acc
//   EPI 1: Cw = fp16(silu(acc))
//   EPI 2: Cf += acc ; Cw = fp16(Cf)
// ---------------------------------------------------------------------------
template<int MTILES, int EPI>
__global__ void __launch_bounds__(512)
gemm2(const __half* __restrict__ Aw, const __half* __restrict__ Bw,
      float* __restrict__ Cf, __half* __restrict__ Cw,
      int lda, int ldb, int ldc, int kchunk, int cslice)
{
    constexpr int BM = MTILES * 64;
    constexpr int A_E = BM * A_LD;         // halves per A stage
    constexpr int B_E = 64 * B_LD;         // halves per B stage
    constexpr int STAGE_B = (A_E + B_E) * 2;
    constexpr int OFS_B = A_E * 2;

    extern __shared__ __align__(16) char smem[];
    const uint32_t sb = smem_u32(smem);

    const int tid  = threadIdx.x;
    const int lane = tid & 31;
    const int wid  = tid >> 5;
    const int wm = (wid >> 2) * (MTILES * 16);
    const int wn = (wid & 3) * 32;
    const int mbase = blockIdx.y * BM;
    const int nbase = blockIdx.x * 128;
    const int kbeg  = blockIdx.z * kchunk;
    const int niter = kchunk >> 6;

    float acc[MTILES][4][4];
#pragma unroll
    for (int i = 0; i < MTILES; i++)
#pragma unroll
        for (int j = 0; j < 4; j++)
#pragma unroll
            for (int f = 0; f < 4; f++) acc[i][j][f] = 0.f;

    auto issue = [&](int st, int k0) {
        const uint32_t s0 = sb + st * STAGE_B;
        // A: BM rows x 8 16B-chunks (BM*8 chunks total)
#pragma unroll
        for (int i = 0; i < MTILES; i++) {
            const int q = tid + i * 512;
            const int row = q >> 3, c16 = q & 7;
            const size_t ga = (size_t)(mbase + row) * lda + k0 + c16 * 8;
            cpa16(s0 + (uint32_t)(row * A_LD + c16 * 8) * 2, Aw + ga);
        }
        // B: 64 k-rows x 16 chunks = 1024 chunks
#pragma unroll
        for (int i = 0; i < 2; i++) {
            const int q = tid + i * 512;
            const int kr = q >> 4, c16 = q & 15;
            const size_t gb = (size_t)(k0 + kr) * ldb + nbase + c16 * 8;
            cpa16(s0 + OFS_B + (uint32_t)(kr * B_LD + c16 * 8) * 2, Bw + gb);
        }
    };

    issue(0, kbeg);
    cpa_commit();

    for (int c = 0; c < niter; ++c) {
        if (c + 1 < niter) {
            issue((c + 1) & 1, kbeg + (c + 1) * 64);
            cpa_commit();
            cpa_wait1();
        } else {
            cpa_wait0();
        }
        __syncthreads();

        const uint32_t s0 = sb + (c & 1) * STAGE_B;
#pragma unroll
        for (int ks = 0; ks < 64; ks += 16) {
            uint32_t Bf[4][2];
#pragma unroll
            for (int g = 0; g < 2; g++) {
                const uint32_t off = (uint32_t)((ks + (lane & 15)) * B_LD
                                                + wn + g * 16 + (lane >> 4) * 8) * 2;
                ldmT(Bf[2*g][0], Bf[2*g][1], Bf[2*g+1][0], Bf[2*g+1][1], s0 + OFS_B + off);
            }
#pragma unroll
            for (int mt = 0; mt < MTILES; mt++) {
                uint32_t Af[4];
                const uint32_t offA = (uint32_t)((wm + mt * 16 + (lane & 15)) * A_LD
                                                 + ks + (lane >> 4) * 8) * 2;
                ldmA(Af, s0 + offA);
#pragma unroll
                for (int nt = 0; nt < 4; nt++) mma16816(acc[mt][nt], Af, Bf[nt]);
            }
        }
        __syncthreads();
    }

    float* Cb = (EPI == 0) ? (Cf + (size_t)blockIdx.z * cslice) : Cf;
    const int tr = lane >> 2, tc = (lane & 3) * 2;
#pragma unroll
    for (int mt = 0; mt < MTILES; mt++) {
#pragma unroll
        for (int nt = 0; nt < 4; nt++) {
#pragma unroll
            for (int half = 0; half < 2; half++) {
                const int row = mbase + wm + mt * 16 + tr + half * 8;
                const int col = nbase + wn + nt * 8 + tc;
                float2 v = make_float2(acc[mt][nt][half * 2], acc[mt][nt][half * 2 + 1]);
                if (EPI == 0) {
                    *(float2*)(Cb + (size_t)row * ldc + col) = v;
                } else if (EPI == 1) {
                    v.x = silu_f(v.x); v.y = silu_f(v.y);
                    *(uint32_t*)(Cw + (size_t)row * ldc + col) = cvt2h(v.x, v.y);
                } else {
                    float* p = Cb + (size_t)row * ldc + col;
                    float2 o = *(float2*)p;
                    v.x += o.x; v.y += o.y;
                    *(float2*)p = v;
                    *(uint32_t*)(Cw + (size_t)row * ldc + col) = cvt2h(v.x, v.y);
                }
            }
        }
    }
}

// ---------------------------------------------------------------------------
// fp32 -> fp16 converts
// ---------------------------------------------------------------------------
__global__ void convert_k(const float* __restrict__ src, __half* __restrict__ dst, int n4)
{
    const int i = blockIdx.x * blockDim.x + threadIdx.x;
    if (i >= n4) return;
    const float4 v = ((const float4*)src)[i];
    ((uint2*)dst)[i] = make_uint2(cvt2h(v.x, v.y), cvt2h(v.z, v.w));
}

#define N4_WIN  (NLAY * Dm * 2 * INNER / 4)
#define N4_WOUT (NLAY * INNER * Dm / 4)
#define N4_WM1  (NLAY * Dm * MLPD / 4)
#define N4_WM2  (NLAY * MLPD * Dm / 4)
#define N4_TOT  (N4_WIN + N4_WOUT + N4_WM1 + N4_WM2)

__global__ void convert_weights_k(const float* __restrict__ win, const float* __restrict__ wout,
                                  const float* __restrict__ wm1, const float* __restrict__ wm2,
                                  __half* __restrict__ dwin, __half* __restrict__ dwout,
                                  __half* __restrict__ dwm1, __half* __restrict__ dwm2)
{
    int i = blockIdx.x * blockDim.x + threadIdx.x;
    if (i >= N4_TOT) return;
    const float* s;
    __half* d;
    if (i < N4_WIN)                       { s = win;  d = dwin; }
    else if ((i -= N4_WIN) < N4_WOUT)     { s = wout; d = dwout; }
    else if ((i -= N4_WOUT) < N4_WM1)     { s = wm1;  d = dwm1; }
    else { i -= N4_WM1;                     s = wm2;  d = dwm2; }
    const float4 v = ((const float4*)s)[i];
    ((uint2*)d)[i] = make_uint2(cvt2h(v.x, v.y), cvt2h(v.z, v.w));
}

// ---------------------------------------------------------------------------
// Scan kernels
// ---------------------------------------------------------------------------
__global__ void scan_carry_k(const float* __restrict__ ug, const float* __restrict__ Avec,
                             float* __restrict__ carry)
{
    const int idx = blockIdx.x * blockDim.x + threadIdx.x;
    const int c = idx & (INNER - 1);
    const int gch = idx >> 10;
    const float a = Avec[c];
    const float* up = ug + (size_t)gch * CHLEN * (2 * INNER) + c;
    float hv = 0.f;
#pragma unroll 8
    for (int t = 0; t < CHLEN; t++)
        hv = fmaf(a, hv, up[(size_t)t * (2 * INNER)]);
    carry[idx] = hv;
}

__global__ void combine_k(const float* __restrict__ carry, const float* __restrict__ Avec,
                          float* __restrict__ sin_)
{
    const int idx = blockIdx.x * blockDim.x + threadIdx.x;
    const int c = idx & (INNER - 1);
    const int q = idx >> 10;
    const float a = Avec[c];
    float achunk = a;
#pragma unroll
    for (int i = 0; i < 6; i++) achunk *= achunk;   // a^64
    float s = 0.f;
    for (int k = 0; k < NCH; k++) {
        const size_t o = (size_t)(q * NCH + k) * INNER + c;
        sin_[o] = s;
        s = fmaf(achunk, s, carry[o]);
    }
}

__global__ void scan_final_gate_k(const float* __restrict__ ug, const float* __restrict__ Avec,
                                  const float* __restrict__ sin_, float* __restrict__ hout,
                                  __half* __restrict__ pw, int len)
{
    const int idx = blockIdx.x * blockDim.x + threadIdx.x;
    const int c = idx & (INNER - 1);
    const int gch = idx >> 10;
    const float a = Avec[c];
    const float* up = ug + (size_t)gch * len * (2 * INNER) + c;
    const float* gp = up + INNER;
    __half* pp = pw + (size_t)gch * len * INNER + c;
    float* hp = hout ? hout + (size_t)gch * len * INNER + c : nullptr;
    float hv = sin_[idx];
#pragma unroll 4
    for (int t = 0; t < len; t++) {
        hv = fmaf(a, hv, up[(size_t)t * (2 * INNER)]);
        if (hp) hp[(size_t)t * INNER] = hv;
        const float p = silu_f(gp[(size_t)t * (2 * INNER)]) * hv;
        pp[(size_t)t * INNER] = __float2half_rn(p);
    }
}

// ---------------------------------------------------------------------------
// Small kernels
// ---------------------------------------------------------------------------
__global__ void compute_starts_k(const int* __restrict__ seg, int* __restrict__ starts,
                                 int* __restrict__ ends)
{
    int b = threadIdx.x;
    if (b >= Bsz) return;
    int cnt = 0;
    for (int t = 0; t < Lseq && cnt < NSEG; t++)
        if (seg[b * Lseq + t] != 0) starts[b * NSEG + cnt++] = t;
    while (cnt < NSEG) { starts[b * NSEG + cnt] = 0; cnt++; }
    for (int i = 0; i < NSEG - 1; i++) ends[b * NSEG + i] = starts[b * NSEG + i + 1];
    ends[b * NSEG + NSEG - 1] = Lseq;
}

__global__ void build_inputs_k(const int* __restrict__ ids, const float* __restrict__ E,
                               const float* __restrict__ part,
                               float* __restrict__ x, __half* __restrict__ xw,
                               const int* __restrict__ starts, const int* __restrict__ ends)
{
    const int bid = blockIdx.x;
    if (bid < NROWS) {
        const int id = ids[bid];
        const float4 v = ((const float4*)(E + (size_t)id * Dm))[threadIdx.x];
        ((float4*)(x + (size_t)bid * Dm))[threadIdx.x] = v;
        ((uint2*)(xw + (size_t)bid * Dm))[threadIdx.x] =
            make_uint2(cvt2h(v.x, v.y), cvt2h(v.z, v.w));
    } else {
        const int r = bid - NROWS;
        const int q = r >> 7;
        const int t = r & (SEGLEN - 1);
        const int b = q >> 3;
        const int s = starts[q], e = ends[q];
        const int pos = s + t;
        float4 v = make_float4(0.f, 0.f, 0.f, 0.f);
        if (pos < e && pos < Lseq) {
            const size_t base = ((size_t)b * Lseq + pos) * Dm;
#pragma unroll
            for (int p = 0; p < DEC_SK; p++) {
                const float4 w =
                    ((const float4*)(part + (size_t)p * NROWS * Dm + base))[threadIdx.x];
                v.x += w.x; v.y += w.y; v.z += w.z; v.w += w.w;
            }
        }
        ((float4*)(x + (size_t)bid * Dm))[threadIdx.x] = v;
        ((uint2*)(xw + (size_t)bid * Dm))[threadIdx.x] =
            make_uint2(cvt2h(v.x, v.y), cvt2h(v.z, v.w));
    }
}

__global__ void save_state_k(const float* __restrict__ h, float* __restrict__ st,
                             const int* __restrict__ starts)
{
    const int r = blockIdx.x;
    const int c = threadIdx.x;
    const int b = r >> 3;
    const int s = starts[r];
    st[(size_t)r * INNER + c] = (s > 0) ? h[((size_t)b * Lseq + (s - 1)) * INNER + c] : 0.f;
}

__global__ void extract_last_k(const float* __restrict__ xs, float* __restrict__ last,
                               const int* __restrict__ starts, const int* __restrict__ ends)
{
    const int q = blockIdx.x;
    int len = ends[q] - starts[q];
    if (len > SEGLEN) len = SEGLEN;
    if (len < 1) len = 1;
    const float4* s = (const float4*)(xs + ((size_t)q * SEGLEN + (len - 1)) * Dm);
    float4* d = (float4*)(last + (size_t)q * Dm);
    d[threadIdx.x] = s[threadIdx.x];
}

__global__ void head_k(const float* __restrict__ last,
                       const float* __restrict__ muW, const float* __restrict__ mub,
                       const float* __restrict__ lvW, const float* __restrict__ lvb,
                       float* __restrict__ out)
{
    const int o = blockIdx.x * blockDim.x + threadIdx.x;
    const int which = o >> 13;
    const int rem = o & 8191;
    const int r = rem >> 9, d = rem & 511;
    const float* W = which ? lvW : muW;
    const float* bias = which ? lvb : mub;
    const float* lr = last + (size_t)r * Dm;
    float acc = bias[d];
#pragma unroll 8
    for (int k = 0; k < Dm; k++) acc = fmaf(lr[k], W[(size_t)k * Dm + d], acc);
    out[o] = acc;
}

// ---------------------------------------------------------------------------
// Orchestration (my launch #3 = dec GEMM for ncu window)
// ---------------------------------------------------------------------------
extern "C" void kernel_launch(void* const* d_in, const int* in_sizes, int n_in,
                              void* d_out, int out_size)
{
    const float* decoder_output = (const float*)d_in[0];
    const int*   input_ids      = (const int*)  d_in[1];
    const int*   seg_idx        = (const int*)  d_in[2];
    const float* E              = (const float*)d_in[3];
    const float* Aparam         = (const float*)d_in[4];
    const float* Win            = (const float*)d_in[5];
    const float* Wout           = (const float*)d_in[6];
    const float* Wm1            = (const float*)d_in[7];
    const float* Wm2            = (const float*)d_in[8];
    const float* muW            = (const float*)d_in[9];
    const float* mub            = (const float*)d_in[10];
    const float* lvW            = (const float*)d_in[11];
    const float* lvb            = (const float*)d_in[12];
    float* out = (float*)d_out;

    float *x, *decpart, *ug, *h, *state, *carry, *sins, *last;
    int *starts, *ends;
    __half *decAw, *xw, *pw, *mlpw, *ew, *winw, *woutw, *wm1w, *wm2w;
    cudaGetSymbolAddress((void**)&x,       g_x);
    cudaGetSymbolAddress((void**)&decpart, g_decpart);
    cudaGetSymbolAddress((void**)&ug,      g_ug);
    cudaGetSymbolAddress((void**)&h,       g_h);
    cudaGetSymbolAddress((void**)&state,   g_state);
    cudaGetSymbolAddress((void**)&carry,   g_carry);
    cudaGetSymbolAddress((void**)&sins,    g_sin);
    cudaGetSymbolAddress((void**)&last,    g_last);
    cudaGetSymbolAddress((void**)&starts,  g_starts);
    cudaGetSymbolAddress((void**)&ends,    g_ends);
    cudaGetSymbolAddress((void**)&decAw,   g_decAw);
    cudaGetSymbolAddress((void**)&xw,      g_xw);
    cudaGetSymbolAddress((void**)&pw,      g_pw);
    cudaGetSymbolAddress((void**)&mlpw,    g_mlpw);
    cudaGetSymbolAddress((void**)&ew,      g_Ew);
    cudaGetSymbolAddress((void**)&winw,    g_Winw);
    cudaGetSymbolAddress((void**)&woutw,   g_Woutw);
    cudaGetSymbolAddress((void**)&wm1w,    g_Wm1w);
    cudaGetSymbolAddress((void**)&wm2w,    g_Wm2w);

    constexpr int SMEM2 = (128 * A_LD + 64 * B_LD) * 2 * 2;   // 71,680 B
    constexpr int SMEM1 = (64  * A_LD + 64 * B_LD) * 2 * 2;   // 53,248 B
    cudaFuncSetAttribute(gemm2<2, 0>, cudaFuncAttributeMaxDynamicSharedMemorySize, SMEM2);
    cudaFuncSetAttribute(gemm2<2, 1>, cudaFuncAttributeMaxDynamicSharedMemorySize, SMEM2);
    cudaFuncSetAttribute(gemm2<1, 2>, cudaFuncAttributeMaxDynamicSharedMemorySize, SMEM1);

    // #0..#2
    compute_starts_k<<<1, 32>>>(seg_idx, starts, ends);
    convert_k<<<(VOC * Dm / 4 + 255) / 256, 256>>>(E, ew, VOC * Dm / 4);
    convert_k<<<(NROWS * VOC / 4 + 255) / 256, 256>>>(decoder_output, decAw, NROWS * VOC / 4);

    // #3: dec GEMM (split-K=4, 1-term fp16, BK=64) — ncu capture target
    gemm2<2, 0><<<dim3(Dm / 128, NROWS / 128, DEC_SK), 512, SMEM2>>>(
        decAw, ew, decpart, nullptr, VOC, Dm, Dm, DEC_KSLICE, NROWS * Dm);

    build_inputs_k<<<XROWS, 128>>>(input_ids, E, decpart, x, xw, starts, ends);
    convert_weights_k<<<(N4_TOT + 255) / 256, 256>>>(Win, Wout, Wm1, Wm2,
                                                     winw, woutw, wm1w, wm2w);

    // -------- Merged layer loop (base rows 0..2047, segment rows 2048..4095) --------
    for (int l = 0; l < NLAY; l++) {
        const size_t oWin  = (size_t)l * Dm * 2 * INNER;
        const size_t oWout = (size_t)l * INNER * Dm;
        const size_t oWm1  = (size_t)l * Dm * MLPD;
        const size_t oWm2  = (size_t)l * MLPD * Dm;
        const float* Al    = Aparam + (size_t)l * INNER;
        float* stl = state + (size_t)l * Bsz * NSEG * INNER;

        gemm2<2, 0><<<dim3((2 * INNER) / 128, XROWS / 128, 1), 512, SMEM2>>>(
            xw, winw + oWin, ug, nullptr, Dm, 2 * INNER, 2 * INNER, Dm, 0);
        scan_carry_k<<<(Bsz * NCH * INNER) / 256, 256>>>(ug, Al, carry);
        combine_k<<<(Bsz * INNER) / 256, 256>>>(carry, Al, sins);
        scan_final_gate_k<<<(Bsz * NCH * INNER) / 256, 256>>>(ug, Al, sins, h, pw, CHLEN);
        save_state_k<<<Bsz * NSEG, INNER>>>(h, stl, starts);
        scan_final_gate_k<<<(Bsz * NSEG * INNER) / 256, 256>>>(
            ug + (size_t)NROWS * 2 * INNER, Al, stl, nullptr,
            pw + (size_t)NROWS * INNER, SEGLEN);
        gemm2<1, 2><<<dim3(Dm / 128, XROWS / 64, 1), 512, SMEM1>>>(
            pw, woutw + oWout, x, xw, INNER, Dm, Dm, INNER, 0);
        gemm2<2, 1><<<dim3(MLPD / 128, XROWS / 128, 1), 512, SMEM2>>>(
            xw, wm1w + oWm1, nullptr, mlpw, Dm, MLPD, MLPD, Dm, 0);
        gemm2<1, 2><<<dim3(Dm / 128, XROWS / 64, 1), 512, SMEM1>>>(
            mlpw, wm2w + oWm2, x, xw, MLPD, Dm, Dm, MLPD, 0);
    }

    extract_last_k<<<Bsz * NSEG, 128>>>(x + (size_t)NROWS * Dm, last, starts, ends);
    head_k<<<(2 * Bsz * NSEG * Dm) / 256, 256>>>(last, muW, mub, lvW, lvb, out);
}